// round 1
// baseline (speedup 1.0000x reference)
#include <cuda_runtime.h>
#include <cstdint>
#include <math.h>

#define BB 4
#define TT 2048
#define DD 2048
#define HH 16
#define HDIM 128
#define MROWS (BB*TT)

// ---------------- scratch (device globals: no allocation allowed) ----------------
__device__ float g_q[BB*HH*TT*HDIM];     // 64 MiB, layout (B,H,T,hd)
__device__ float g_k[BB*HH*TT*HDIM];     // 64 MiB
__device__ float g_v[BB*HH*TT*HDIM];     // 64 MiB
__device__ float g_ctx[BB*TT*DD];        // 64 MiB, layout (B,T,D) for proj GEMM
__device__ int   g_len[BB];

// ---------------- per-batch valid lengths (mask is a contiguous prefix) ----------
__global__ void lengths_kernel(const int* __restrict__ mask) {
    __shared__ int sd[256];
    int b = blockIdx.x;
    int s = 0;
    for (int i = threadIdx.x; i < TT; i += 256) s += mask[b * TT + i];
    sd[threadIdx.x] = s;
    __syncthreads();
    for (int st = 128; st > 0; st >>= 1) {
        if (threadIdx.x < st) sd[threadIdx.x] += sd[threadIdx.x + st];
        __syncthreads();
    }
    if (threadIdx.x == 0) g_len[b] = sd[0];
}

// ---------------- fp32 GEMM: C[M,N] = A[M,K] @ W[N,K]^T ----------------
// 128x128 tile, BK=16, 256 threads, 8x8 micro-tile per thread.
// MODE 0: QKV — scatter epilogue into g_q/g_k/g_v (B,H,T,hd), no transpose pass needed.
// MODE 1: proj — A is g_ctx (device symbol), plain write to Cout.
template <int MODE>
__global__ __launch_bounds__(256) void gemm_kernel(
    const float* __restrict__ Ain, const float* __restrict__ W,
    float* __restrict__ Cout, int N, int K)
{
    __shared__ float As[16][128];
    __shared__ float Ws[16][128];
    const float* A = (MODE == 0) ? Ain : (const float*)g_ctx;

    const int bm = blockIdx.y * 128;
    const int bn = blockIdx.x * 128;
    const int tid = threadIdx.x;
    const int tx = tid & 15, ty = tid >> 4;

    float acc[8][8];
#pragma unroll
    for (int i = 0; i < 8; i++)
#pragma unroll
        for (int j = 0; j < 8; j++) acc[i][j] = 0.f;

    for (int k0 = 0; k0 < K; k0 += 16) {
#pragma unroll
        for (int l = 0; l < 2; l++) {
            int f = tid + l * 256;          // float4 idx in [0,512)
            int row = f >> 2, c4 = f & 3;
            float4 av = *(const float4*)(A + (size_t)(bm + row) * K + k0 + c4 * 4);
            As[c4 * 4 + 0][row] = av.x; As[c4 * 4 + 1][row] = av.y;
            As[c4 * 4 + 2][row] = av.z; As[c4 * 4 + 3][row] = av.w;
            float4 wv = *(const float4*)(W + (size_t)(bn + row) * K + k0 + c4 * 4);
            Ws[c4 * 4 + 0][row] = wv.x; Ws[c4 * 4 + 1][row] = wv.y;
            Ws[c4 * 4 + 2][row] = wv.z; Ws[c4 * 4 + 3][row] = wv.w;
        }
        __syncthreads();
#pragma unroll
        for (int kk = 0; kk < 16; kk++) {
            float a[8], bb[8];
            *(float4*)&a[0]  = *(const float4*)&As[kk][ty * 8];
            *(float4*)&a[4]  = *(const float4*)&As[kk][ty * 8 + 4];
            *(float4*)&bb[0] = *(const float4*)&Ws[kk][tx * 8];
            *(float4*)&bb[4] = *(const float4*)&Ws[kk][tx * 8 + 4];
#pragma unroll
            for (int i = 0; i < 8; i++)
#pragma unroll
                for (int j = 0; j < 8; j++)
                    acc[i][j] += a[i] * bb[j];
        }
        __syncthreads();
    }

    if (MODE == 0) {
        // bn spans exactly one head (128 cols): which/h constant per block
        const int which = bn >> 11;          // 0=q 1=k 2=v
        const int h = (bn >> 7) & 15;
        float* dst = (which == 0) ? g_q : (which == 1) ? g_k : g_v;
#pragma unroll
        for (int i = 0; i < 8; i++) {
            int m = bm + ty * 8 + i;
            int b_ = m >> 11, t_ = m & (TT - 1);
            float* p = dst + (((size_t)b_ * HH + h) * TT + t_) * HDIM + tx * 8;
            *(float4*)p       = *(float4*)&acc[i][0];
            *(float4*)(p + 4) = *(float4*)&acc[i][4];
        }
    } else {
#pragma unroll
        for (int i = 0; i < 8; i++) {
            int m = bm + ty * 8 + i;
            float* p = Cout + (size_t)m * N + bn + tx * 8;
            *(float4*)p       = *(float4*)&acc[i][0];
            *(float4*)(p + 4) = *(float4*)&acc[i][4];
        }
    }
}

// ---------------- RoPE (NeoX style), in-place on q and k ----------------
// one thread handles the (d, d+64) pair for one (b,h,t)
__global__ void rope_kernel() {
    int idx = blockIdx.x * blockDim.x + threadIdx.x;   // B*H*T*64
    int d  = idx & 63;
    int t  = (idx >> 6) & (TT - 1);
    int bh = idx >> 17;
    size_t base = ((size_t)bh * TT + t) * HDIM;

    // inv_freq = 10000^(-(2d)/128); compute via double exp, round to fp32 (matches ref)
    float inv = (float)exp(-(double)(2 * d) / 128.0 * 9.210340371976184);
    float ang = (float)t * inv;          // fp32 multiply, like reference
    float s, c;
    sincosf(ang, &s, &c);                // precise version (NOT __sincosf: bad at |x|~2048)

    float q1 = g_q[base + d], q2 = g_q[base + d + 64];
    g_q[base + d]      = q1 * c - q2 * s;
    g_q[base + d + 64] = q2 * c + q1 * s;
    float k1 = g_k[base + d], k2 = g_k[base + d + 64];
    g_k[base + d]      = k1 * c - k2 * s;
    g_k[base + d + 64] = k2 * c + k1 * s;
}

// ---------------- flash attention, fp32, BQ=BK=64 ----------------
// swizzle at float4 granularity: bank group = c4 mod 8, row stride 32 float4 ≡ 0 mod 8
#define SWZ(c4, row) ((c4) ^ ((row) & 7))

struct AttnSmem {
    float Q[64][128];
    float K[64][128];
    float V[64][128];
    float S[64][68];     // pad 68: row stride ≡ 4 mod 32 banks
};

__global__ __launch_bounds__(256) void attn_kernel() {
    extern __shared__ AttnSmem smem_attn[];
    AttnSmem& s = smem_attn[0];

    const int qt = blockIdx.x, h = blockIdx.y, b = blockIdx.z;
    const int tid = threadIdx.x;
    const int L = g_len[b];
    const size_t bhT = ((size_t)b * HH + h) * TT;
    const float* Qg = g_q + (bhT + (size_t)qt * 64) * HDIM;

    // load Q tile (swizzled)
#pragma unroll
    for (int l = 0; l < 8; l++) {
        int f = tid + l * 256;              // float4 idx in [0,2048)
        int row = f >> 5, c4 = f & 31;
        *(float4*)&s.Q[row][SWZ(c4, row) * 4] = *(const float4*)(Qg + row * HDIM + c4 * 4);
    }

    const int r  = tid >> 2;                // query row in tile
    const int q4 = tid & 3;                 // quad lane
    const int rg = qt * 64 + r;             // global query index
    float m_i = -1e30f, l_i = 0.f;
    float acc[32];
#pragma unroll
    for (int c = 0; c < 32; c++) acc[c] = 0.f;

    const int jmax = min(qt * 64 + 63, L - 1);
    const int ntiles = jmax / 64 + 1;
    __syncthreads();

    for (int kt = 0; kt < ntiles; kt++) {
        const float* Kg = g_k + (bhT + (size_t)kt * 64) * HDIM;
        const float* Vg = g_v + (bhT + (size_t)kt * 64) * HDIM;
#pragma unroll
        for (int l = 0; l < 8; l++) {
            int f = tid + l * 256;
            int row = f >> 5, c4 = f & 31;
            *(float4*)&s.K[row][SWZ(c4, row) * 4] = *(const float4*)(Kg + row * HDIM + c4 * 4);
            *(float4*)&s.V[row][c4 * 4]           = *(const float4*)(Vg + row * HDIM + c4 * 4);
        }
        __syncthreads();

        // S = Q K^T for 16 keys j = q4 + jj*4 (interleaved -> conflict-free bank groups)
        float sv[16];
#pragma unroll
        for (int jj = 0; jj < 16; jj++) sv[jj] = 0.f;
#pragma unroll 4
        for (int d4 = 0; d4 < 32; d4++) {
            float4 qv = *(const float4*)&s.Q[r][SWZ(d4, r) * 4];
#pragma unroll
            for (int jj = 0; jj < 16; jj++) {
                int j = q4 + jj * 4;
                float4 kv = *(const float4*)&s.K[j][SWZ(d4, j) * 4];
                sv[jj] += qv.x * kv.x + qv.y * kv.y + qv.z * kv.z + qv.w * kv.w;
            }
        }

        // mask (causal + pad) + online softmax
        const float scl = 0.08838834764831843f;   // 1/sqrt(128)
        float vmax = -1e30f;
#pragma unroll
        for (int jj = 0; jj < 16; jj++) {
            int jg = kt * 64 + q4 + jj * 4;
            float x = (jg <= rg && jg < L) ? sv[jj] * scl : -1e30f;
            sv[jj] = x;
            vmax = fmaxf(vmax, x);
        }
        vmax = fmaxf(vmax, __shfl_xor_sync(0xffffffffu, vmax, 1));
        vmax = fmaxf(vmax, __shfl_xor_sync(0xffffffffu, vmax, 2));
        float m_new = fmaxf(m_i, vmax);
        float corr = __expf(m_i - m_new);
        float psum = 0.f;
#pragma unroll
        for (int jj = 0; jj < 16; jj++) {
            float p = __expf(sv[jj] - m_new);
            sv[jj] = p;
            psum += p;
        }
        psum += __shfl_xor_sync(0xffffffffu, psum, 1);
        psum += __shfl_xor_sync(0xffffffffu, psum, 2);
        l_i = l_i * corr + psum;
        m_i = m_new;
#pragma unroll
        for (int c = 0; c < 32; c++) acc[c] *= corr;
#pragma unroll
        for (int jj = 0; jj < 16; jj++) s.S[r][q4 + jj * 4] = sv[jj];
        __syncthreads();

        // O += P V : thread owns row r, 8 interleaved float4 columns c4 = q4 + off*4
#pragma unroll 8
        for (int j = 0; j < 64; j++) {
            float p = s.S[r][j];
#pragma unroll
            for (int off = 0; off < 8; off++) {
                float4 vv = *(const float4*)&s.V[j][(q4 + off * 4) * 4];
                acc[off * 4 + 0] += p * vv.x;
                acc[off * 4 + 1] += p * vv.y;
                acc[off * 4 + 2] += p * vv.z;
                acc[off * 4 + 3] += p * vv.w;
            }
        }
        __syncthreads();
    }

    float inv_l = 1.f / l_i;
    float* Og = g_ctx + ((size_t)b * TT + qt * 64 + r) * DD + h * HDIM;
#pragma unroll
    for (int off = 0; off < 8; off++) {
        float4 o;
        o.x = acc[off * 4 + 0] * inv_l;
        o.y = acc[off * 4 + 1] * inv_l;
        o.z = acc[off * 4 + 2] * inv_l;
        o.w = acc[off * 4 + 3] * inv_l;
        *(float4*)(Og + (q4 + off * 4) * 4) = o;
    }
}

// ---------------- launcher ----------------
extern "C" void kernel_launch(void* const* d_in, const int* in_sizes, int n_in,
                              void* d_out, int out_size) {
    const float* x     = (const float*)d_in[0];
    const float* Wqkv  = (const float*)d_in[1];
    const float* Wproj = (const float*)d_in[2];
    const int*   mask  = (const int*)d_in[3];
    float* out = (float*)d_out;

    cudaFuncSetAttribute(attn_kernel, cudaFuncAttributeMaxDynamicSharedMemorySize,
                         (int)sizeof(AttnSmem));

    lengths_kernel<<<BB, 256>>>(mask);
    gemm_kernel<0><<<dim3(3 * DD / 128, MROWS / 128), 256>>>(x, Wqkv, nullptr, 3 * DD, DD);
    rope_kernel<<<(BB * HH * TT * 64) / 256, 256>>>();
    attn_kernel<<<dim3(TT / 64, HH, BB), 256, sizeof(AttnSmem)>>>();
    gemm_kernel<1><<<dim3(DD / 128, MROWS / 128), 256>>>(nullptr, Wproj, out, DD, DD);
}

// round 5
// speedup vs baseline: 1.4101x; 1.4101x over previous
#include <cuda_runtime.h>
#include <cuda_bf16.h>
#include <cstdint>
#include <math.h>

#define BB 4
#define TT 2048
#define DD 2048
#define HH 16
#define HDIM 128
#define MROWS (BB*TT)       /* 8192 */
#define K3 (3*DD)           /* 6144 */

// ---------------- scratch (device globals; uint4-backed => 16B align) ----------
__device__ uint4 g_q_raw  [(size_t)BB*HH*TT*HDIM/4];     // 64 MiB fp32 (B,H,T,hd)
__device__ uint4 g_k_raw  [(size_t)BB*HH*TT*HDIM/4];
__device__ uint4 g_v_raw  [(size_t)BB*HH*TT*HDIM/4];
__device__ uint4 g_ctx_raw[(size_t)MROWS*DD/4];          // 64 MiB fp32 (B,T,D)
__device__ uint4 g_A3_raw [(size_t)MROWS*K3/8];          // 96 MiB bf16x3 activations
__device__ uint4 g_W3_raw [(size_t)K3*K3/8];             // 72 MiB bf16x3 weights
__device__ int   g_len[BB];

// device-code-only views (NEVER use these in host code / kernel args!)
#define g_q   ((float*)g_q_raw)
#define g_k   ((float*)g_k_raw)
#define g_v   ((float*)g_v_raw)
#define g_ctx ((float*)g_ctx_raw)
#define g_A3  ((__nv_bfloat16*)g_A3_raw)
#define g_W3  ((__nv_bfloat16*)g_W3_raw)

// ============================ helpers ============================
__device__ __forceinline__ uint32_t smem_u32(const void* p) {
    uint32_t a;
    asm("{ .reg .u64 t; cvta.to.shared.u64 t, %1; cvt.u32.u64 %0, t; }" : "=r"(a) : "l"(p));
    return a;
}
__device__ __forceinline__ void cp16(uint32_t s, const void* g) {
    asm volatile("cp.async.cg.shared.global [%0], [%1], 16;" :: "r"(s), "l"(g));
}
__device__ __forceinline__ void ldmx4(uint32_t* r, uint32_t addr) {
    asm volatile("ldmatrix.sync.aligned.m8n8.x4.shared.b16 {%0,%1,%2,%3}, [%4];"
        : "=r"(r[0]), "=r"(r[1]), "=r"(r[2]), "=r"(r[3]) : "r"(addr));
}
__device__ __forceinline__ void mma16816(float* d, const uint32_t* a, uint32_t b0, uint32_t b1) {
    asm volatile("mma.sync.aligned.m16n8k16.row.col.f32.bf16.bf16.f32 "
        "{%0,%1,%2,%3}, {%4,%5,%6,%7}, {%8,%9}, {%0,%1,%2,%3};"
        : "+f"(d[0]), "+f"(d[1]), "+f"(d[2]), "+f"(d[3])
        : "r"(a[0]), "r"(a[1]), "r"(a[2]), "r"(a[3]), "r"(b0), "r"(b1));
}

// ---------------- per-batch valid lengths ----------------
__global__ void lengths_kernel(const int* __restrict__ mask) {
    __shared__ int sd[256];
    int b = blockIdx.x;
    int s = 0;
    for (int i = threadIdx.x; i < TT; i += 256) s += mask[b * TT + i];
    sd[threadIdx.x] = s;
    __syncthreads();
    for (int st = 128; st > 0; st >>= 1) {
        if (threadIdx.x < st) sd[threadIdx.x] += sd[threadIdx.x + st];
        __syncthreads();
    }
    if (threadIdx.x == 0) g_len[b] = sd[0];
}

// ---------------- fp32 -> bf16x3 split conversion ----------------
// row layout (length K3): [hi | seg1 | seg2]; LOSEG picks which seg holds lo.
// A'=[hi,lo,hi] (LOSEG=1), B'=[hi,hi,lo] (LOSEG=2) => A'.B' = hihi+lohi+hilo
// USECTX: read g_ctx instead of inarg.  DSTW: 0 -> g_A3, 1 -> g_W3 (device-code select).
template <int LOSEG, int USECTX, int DSTW>
__global__ __launch_bounds__(256) void conv3_kernel(const float* __restrict__ inarg) {
    const float* in = USECTX ? (const float*)g_ctx : inarg;
    __nv_bfloat16* out = DSTW ? g_W3 : g_A3;
    int g = blockIdx.x * 256 + threadIdx.x;        // rows * 512
    int r = g >> 9, c4 = g & 511;
    float4 v = *(const float4*)(in + (size_t)r * DD + c4 * 4);
    union { __nv_bfloat16 b[4]; uint2 u; } hi, lo;
    float vv[4] = {v.x, v.y, v.z, v.w};
#pragma unroll
    for (int i = 0; i < 4; i++) {
        hi.b[i] = __float2bfloat16_rn(vv[i]);
        lo.b[i] = __float2bfloat16_rn(vv[i] - __bfloat162float(hi.b[i]));
    }
    constexpr int HISEG = 3 - LOSEG;
    __nv_bfloat16* o = out + (size_t)r * K3 + c4 * 4;
    *(uint2*)(o)            = hi.u;
    *(uint2*)(o + HISEG*DD) = hi.u;
    *(uint2*)(o + LOSEG*DD) = lo.u;
}

// ---------------- HMMA bf16 GEMM: C[M,N] = A3[M,K3] @ W3[N,K3]^T ----------------
// 128x128 tile, BK=32, 8 warps (2x4), warp tile 64x32, 3-stage cp.async.
#define NSG 3
#define PITCHB 80                       /* bytes per smem row */
#define STAGEB (2*128*PITCHB)           /* 20480 B: A tile + B tile */
#define SMEM_GEMM_TOTAL (NSG*STAGEB)    /* 61440 B */

template <int MODE>
__global__ __launch_bounds__(256) void gemm_mma(float* __restrict__ Cout, int N) {
    extern __shared__ __align__(16) char smraw[];
    const uint32_t sb = smem_u32(smraw);
    const int tid = threadIdx.x;
    const int bm = blockIdx.y * 128, bn = blockIdx.x * 128;
    const int warp = tid >> 5, lane = tid & 31;
    const int wm = warp >> 2, wn = warp & 3;
    const int iters = K3 / 32;                     // 192

    const __nv_bfloat16* Ag = g_A3 + (size_t)bm * K3;
    const __nv_bfloat16* Bg = g_W3 + (size_t)bn * K3;

    float acc[16][4];
#pragma unroll
    for (int i = 0; i < 16; i++)
#pragma unroll
        for (int j = 0; j < 4; j++) acc[i][j] = 0.f;

    auto load_stage = [&](int s, int k0) {
        uint32_t sa = sb + s * STAGEB;
        uint32_t sbm = sa + 128 * PITCHB;
#pragma unroll
        for (int l = 0; l < 2; l++) {
            int c = tid + l * 256;                 // 512 chunks of 16B each
            int row = c >> 2, ch = c & 3;
            cp16(sa  + row * PITCHB + ch * 16, Ag + (size_t)row * K3 + k0 + ch * 8);
            cp16(sbm + row * PITCHB + ch * 16, Bg + (size_t)row * K3 + k0 + ch * 8);
        }
        asm volatile("cp.async.commit_group;" ::: "memory");
    };

    load_stage(0, 0);
    load_stage(1, 32);

    const int lrow = (lane & 7) + 8 * ((lane >> 3) & 1);   // row within 16-block
    const int lkof = (lane >> 4) * 16;                     // byte offset for k-half

    for (int i = 0; i < iters; i++) {
        const int s = i % NSG;
        if (i == iters - 1) asm volatile("cp.async.wait_group 0;" ::: "memory");
        else                asm volatile("cp.async.wait_group 1;" ::: "memory");
        __syncthreads();
        if (i + 2 < iters) load_stage((i + 2) % NSG, (i + 2) * 32);

        const uint32_t sa = sb + s * STAGEB;
        const uint32_t sbm = sa + 128 * PITCHB;
#pragma unroll
        for (int ks = 0; ks < 2; ks++) {
            uint32_t a[4][4], b[2][4];
#pragma unroll
            for (int mi = 0; mi < 4; mi++) {
                int row = wm * 64 + mi * 16 + lrow;
                ldmx4(a[mi], sa + row * PITCHB + ks * 32 + lkof);
            }
#pragma unroll
            for (int nb = 0; nb < 2; nb++) {
                int nr = wn * 32 + nb * 16 + lrow;
                ldmx4(b[nb], sbm + nr * PITCHB + ks * 32 + lkof);
            }
#pragma unroll
            for (int mi = 0; mi < 4; mi++)
#pragma unroll
                for (int ni = 0; ni < 4; ni++)
                    mma16816(acc[mi * 4 + ni], a[mi],
                             b[ni >> 1][ni & 1], b[ni >> 1][(ni & 1) + 2]);
        }
    }

    // ---- epilogue: direct float2 stores ----
    if (MODE == 0) {
        const int which = bn >> 11;                // 0=q 1=k 2=v
        const int h = (bn >> 7) & 15;
        float* dst = (which == 0) ? g_q : (which == 1) ? g_k : g_v;
#pragma unroll
        for (int mi = 0; mi < 4; mi++)
#pragma unroll
            for (int ni = 0; ni < 4; ni++) {
                int d = wn * 32 + ni * 8 + (lane & 3) * 2;
#pragma unroll
                for (int half = 0; half < 2; half++) {
                    int m = bm + wm * 64 + mi * 16 + (lane >> 2) + half * 8;
                    int b_ = m >> 11, t_ = m & (TT - 1);
                    float2 v2 = make_float2(acc[mi * 4 + ni][2 * half],
                                            acc[mi * 4 + ni][2 * half + 1]);
                    *(float2*)&dst[(((size_t)b_ * HH + h) * TT + t_) * HDIM + d] = v2;
                }
            }
    } else {
#pragma unroll
        for (int mi = 0; mi < 4; mi++)
#pragma unroll
            for (int ni = 0; ni < 4; ni++) {
                int col = bn + wn * 32 + ni * 8 + (lane & 3) * 2;
#pragma unroll
                for (int half = 0; half < 2; half++) {
                    int m = bm + wm * 64 + mi * 16 + (lane >> 2) + half * 8;
                    float2 v2 = make_float2(acc[mi * 4 + ni][2 * half],
                                            acc[mi * 4 + ni][2 * half + 1]);
                    *(float2*)&Cout[(size_t)m * N + col] = v2;
                }
            }
    }
}

// ---------------- RoPE (NeoX style), in-place on q and k ----------------
__global__ void rope_kernel() {
    int idx = blockIdx.x * blockDim.x + threadIdx.x;   // B*H*T*64
    int d  = idx & 63;
    int t  = (idx >> 6) & (TT - 1);
    int bh = idx >> 17;
    size_t base = ((size_t)bh * TT + t) * HDIM;
    float inv = (float)exp(-(double)(2 * d) / 128.0 * 9.210340371976184);
    float ang = (float)t * inv;
    float s, c;
    sincosf(ang, &s, &c);
    float q1 = g_q[base + d], q2 = g_q[base + d + 64];
    g_q[base + d]      = q1 * c - q2 * s;
    g_q[base + d + 64] = q2 * c + q1 * s;
    float k1 = g_k[base + d], k2 = g_k[base + d + 64];
    g_k[base + d]      = k1 * c - k2 * s;
    g_k[base + d + 64] = k2 * c + k1 * s;
}

// ---------------- flash attention, fp32, BQ=BK=64 ----------------
#define SWZ(c4, row) ((c4) ^ ((row) & 7))

struct AttnSmem {
    float Q[64][128];
    float K[64][128];
    float V[64][128];
    float S[64][68];
};

__global__ __launch_bounds__(256) void attn_kernel() {
    extern __shared__ AttnSmem smem_attn[];
    AttnSmem& s = smem_attn[0];

    const int qt = blockIdx.x, h = blockIdx.y, b = blockIdx.z;
    const int tid = threadIdx.x;
    const int L = g_len[b];
    const size_t bhT = ((size_t)b * HH + h) * TT;
    const float* Qg = g_q + (bhT + (size_t)qt * 64) * HDIM;

#pragma unroll
    for (int l = 0; l < 8; l++) {
        int f = tid + l * 256;
        int row = f >> 5, c4 = f & 31;
        *(float4*)&s.Q[row][SWZ(c4, row) * 4] = *(const float4*)(Qg + row * HDIM + c4 * 4);
    }

    const int r  = tid >> 2;
    const int q4 = tid & 3;
    const int rg = qt * 64 + r;
    float m_i = -1e30f, l_i = 0.f;
    float acc[32];
#pragma unroll
    for (int c = 0; c < 32; c++) acc[c] = 0.f;

    const int jmax = min(qt * 64 + 63, L - 1);
    const int ntiles = jmax / 64 + 1;
    __syncthreads();

    for (int kt = 0; kt < ntiles; kt++) {
        const float* Kg = g_k + (bhT + (size_t)kt * 64) * HDIM;
        const float* Vg = g_v + (bhT + (size_t)kt * 64) * HDIM;
#pragma unroll
        for (int l = 0; l < 8; l++) {
            int f = tid + l * 256;
            int row = f >> 5, c4 = f & 31;
            *(float4*)&s.K[row][SWZ(c4, row) * 4] = *(const float4*)(Kg + row * HDIM + c4 * 4);
            *(float4*)&s.V[row][c4 * 4]           = *(const float4*)(Vg + row * HDIM + c4 * 4);
        }
        __syncthreads();

        float sv[16];
#pragma unroll
        for (int jj = 0; jj < 16; jj++) sv[jj] = 0.f;
#pragma unroll 4
        for (int d4 = 0; d4 < 32; d4++) {
            float4 qv = *(const float4*)&s.Q[r][SWZ(d4, r) * 4];
#pragma unroll
            for (int jj = 0; jj < 16; jj++) {
                int j = q4 + jj * 4;
                float4 kv = *(const float4*)&s.K[j][SWZ(d4, j) * 4];
                sv[jj] += qv.x * kv.x + qv.y * kv.y + qv.z * kv.z + qv.w * kv.w;
            }
        }

        const float scl = 0.08838834764831843f;
        float vmax = -1e30f;
#pragma unroll
        for (int jj = 0; jj < 16; jj++) {
            int jg = kt * 64 + q4 + jj * 4;
            float x = (jg <= rg && jg < L) ? sv[jj] * scl : -1e30f;
            sv[jj] = x;
            vmax = fmaxf(vmax, x);
        }
        vmax = fmaxf(vmax, __shfl_xor_sync(0xffffffffu, vmax, 1));
        vmax = fmaxf(vmax, __shfl_xor_sync(0xffffffffu, vmax, 2));
        float m_new = fmaxf(m_i, vmax);
        float corr = __expf(m_i - m_new);
        float psum = 0.f;
#pragma unroll
        for (int jj = 0; jj < 16; jj++) {
            float p = __expf(sv[jj] - m_new);
            sv[jj] = p;
            psum += p;
        }
        psum += __shfl_xor_sync(0xffffffffu, psum, 1);
        psum += __shfl_xor_sync(0xffffffffu, psum, 2);
        l_i = l_i * corr + psum;
        m_i = m_new;
#pragma unroll
        for (int c = 0; c < 32; c++) acc[c] *= corr;
#pragma unroll
        for (int jj = 0; jj < 16; jj++) s.S[r][q4 + jj * 4] = sv[jj];
        __syncthreads();

#pragma unroll 8
        for (int j = 0; j < 64; j++) {
            float p = s.S[r][j];
#pragma unroll
            for (int off = 0; off < 8; off++) {
                float4 vv = *(const float4*)&s.V[j][(q4 + off * 4) * 4];
                acc[off * 4 + 0] += p * vv.x;
                acc[off * 4 + 1] += p * vv.y;
                acc[off * 4 + 2] += p * vv.z;
                acc[off * 4 + 3] += p * vv.w;
            }
        }
        __syncthreads();
    }

    float inv_l = 1.f / l_i;
    float* Og = g_ctx + ((size_t)b * TT + qt * 64 + r) * DD + h * HDIM;
#pragma unroll
    for (int off = 0; off < 8; off++) {
        float4 o;
        o.x = acc[off * 4 + 0] * inv_l;
        o.y = acc[off * 4 + 1] * inv_l;
        o.z = acc[off * 4 + 2] * inv_l;
        o.w = acc[off * 4 + 3] * inv_l;
        *(float4*)(Og + (q4 + off * 4) * 4) = o;
    }
}

// ---------------- launcher ----------------
extern "C" void kernel_launch(void* const* d_in, const int* in_sizes, int n_in,
                              void* d_out, int out_size) {
    const float* x     = (const float*)d_in[0];
    const float* Wqkv  = (const float*)d_in[1];
    const float* Wproj = (const float*)d_in[2];
    const int*   mask  = (const int*)d_in[3];
    float* out = (float*)d_out;

    cudaFuncSetAttribute(gemm_mma<0>, cudaFuncAttributeMaxDynamicSharedMemorySize, SMEM_GEMM_TOTAL);
    cudaFuncSetAttribute(gemm_mma<1>, cudaFuncAttributeMaxDynamicSharedMemorySize, SMEM_GEMM_TOTAL);
    cudaFuncSetAttribute(attn_kernel, cudaFuncAttributeMaxDynamicSharedMemorySize,
                         (int)sizeof(AttnSmem));

    lengths_kernel<<<BB, 256>>>(mask);
    conv3_kernel<1, 0, 0><<<MROWS * 2, 256>>>(x);       // x    -> g_A3 [hi,lo,hi]
    conv3_kernel<2, 0, 1><<<K3 * 2, 256>>>(Wqkv);       // Wqkv -> g_W3 [hi,hi,lo]
    gemm_mma<0><<<dim3(K3 / 128, MROWS / 128), 256, SMEM_GEMM_TOTAL>>>(nullptr, K3);
    rope_kernel<<<(BB * HH * TT * 64) / 256, 256>>>();
    attn_kernel<<<dim3(TT / 64, HH, BB), 256, sizeof(AttnSmem)>>>();
    conv3_kernel<1, 1, 0><<<MROWS * 2, 256>>>(nullptr); // ctx  -> g_A3 [hi,lo,hi]
    conv3_kernel<2, 0, 1><<<DD * 2, 256>>>(Wproj);      // Wproj-> g_W3 [hi,hi,lo]
    gemm_mma<1><<<dim3(DD / 128, MROWS / 128), 256, SMEM_GEMM_TOTAL>>>(out, DD);
}

// round 6
// speedup vs baseline: 3.3394x; 2.3682x over previous
#include <cuda_runtime.h>
#include <cuda_bf16.h>
#include <cstdint>
#include <math.h>

#define BB 4
#define TT 2048
#define DD 2048
#define HH 16
#define HDIM 128
#define MROWS (BB*TT)       /* 8192 */
#define K3 (3*DD)           /* 6144 */
#define PLANE_ELEMS ((size_t)BB*HH*TT*HDIM)   /* 16.8M */

// ---------------- scratch (device globals; uint4-backed => 16B align) ----------
__device__ uint4 g_q_raw  [PLANE_ELEMS/4];               // fp32 (B,H,T,hd)
__device__ uint4 g_k_raw  [PLANE_ELEMS/4];
__device__ uint4 g_v_raw  [PLANE_ELEMS/4];
__device__ uint4 g_ctx_raw[(size_t)MROWS*DD/4];          // fp32 (B,T,D)
__device__ uint4 g_A3_raw [(size_t)MROWS*K3/8];          // bf16x3 activations
__device__ uint4 g_W3_raw [(size_t)K3*K3/8];             // bf16x3 weights
__device__ uint4 g_qh_raw [PLANE_ELEMS/8];               // bf16 planes
__device__ uint4 g_ql_raw [PLANE_ELEMS/8];
__device__ uint4 g_kh_raw [PLANE_ELEMS/8];
__device__ uint4 g_kl_raw [PLANE_ELEMS/8];
__device__ uint4 g_vh_raw [PLANE_ELEMS/8];
__device__ uint4 g_vl_raw [PLANE_ELEMS/8];
__device__ int   g_len[BB];

// device-code-only views (never use in host code / kernel args)
#define g_q   ((float*)g_q_raw)
#define g_k   ((float*)g_k_raw)
#define g_v   ((float*)g_v_raw)
#define g_ctx ((float*)g_ctx_raw)
#define g_A3  ((__nv_bfloat16*)g_A3_raw)
#define g_W3  ((__nv_bfloat16*)g_W3_raw)
#define g_qh  ((__nv_bfloat16*)g_qh_raw)
#define g_ql  ((__nv_bfloat16*)g_ql_raw)
#define g_kh  ((__nv_bfloat16*)g_kh_raw)
#define g_kl  ((__nv_bfloat16*)g_kl_raw)
#define g_vh  ((__nv_bfloat16*)g_vh_raw)
#define g_vl  ((__nv_bfloat16*)g_vl_raw)

// ============================ helpers ============================
__device__ __forceinline__ uint32_t smem_u32(const void* p) {
    uint32_t a;
    asm("{ .reg .u64 t; cvta.to.shared.u64 t, %1; cvt.u32.u64 %0, t; }" : "=r"(a) : "l"(p));
    return a;
}
__device__ __forceinline__ void cp16(uint32_t s, const void* g) {
    asm volatile("cp.async.cg.shared.global [%0], [%1], 16;" :: "r"(s), "l"(g));
}
__device__ __forceinline__ void ldmx4(uint32_t* r, uint32_t addr) {
    asm volatile("ldmatrix.sync.aligned.m8n8.x4.shared.b16 {%0,%1,%2,%3}, [%4];"
        : "=r"(r[0]), "=r"(r[1]), "=r"(r[2]), "=r"(r[3]) : "r"(addr));
}
__device__ __forceinline__ void ldmx4t(uint32_t* r, uint32_t addr) {
    asm volatile("ldmatrix.sync.aligned.m8n8.x4.trans.shared.b16 {%0,%1,%2,%3}, [%4];"
        : "=r"(r[0]), "=r"(r[1]), "=r"(r[2]), "=r"(r[3]) : "r"(addr));
}
__device__ __forceinline__ void mma16816(float* d, const uint32_t* a, uint32_t b0, uint32_t b1) {
    asm volatile("mma.sync.aligned.m16n8k16.row.col.f32.bf16.bf16.f32 "
        "{%0,%1,%2,%3}, {%4,%5,%6,%7}, {%8,%9}, {%0,%1,%2,%3};"
        : "+f"(d[0]), "+f"(d[1]), "+f"(d[2]), "+f"(d[3])
        : "r"(a[0]), "r"(a[1]), "r"(a[2]), "r"(a[3]), "r"(b0), "r"(b1));
}
__device__ __forceinline__ uint32_t pack_bf16x2(float lo, float hi) {
    uint32_t r;
    asm("cvt.rn.bf16x2.f32 %0, %1, %2;" : "=r"(r) : "f"(hi), "f"(lo));
    return r;
}
// chunk swizzle: 16B chunk c within a row r (keeps ldmatrix & cp.async conflict-free)
#define SWZ8(c, r)  ((c) ^ ((r) & 7))

// ---------------- per-batch valid lengths ----------------
__global__ void lengths_kernel(const int* __restrict__ mask) {
    __shared__ int sd[256];
    int b = blockIdx.x;
    int s = 0;
    for (int i = threadIdx.x; i < TT; i += 256) s += mask[b * TT + i];
    sd[threadIdx.x] = s;
    __syncthreads();
    for (int st = 128; st > 0; st >>= 1) {
        if (threadIdx.x < st) sd[threadIdx.x] += sd[threadIdx.x + st];
        __syncthreads();
    }
    if (threadIdx.x == 0) g_len[b] = sd[0];
}

// ---------------- fp32 -> bf16x3 split conversion ----------------
// A'=[hi,lo,hi] (LOSEG=1), B'=[hi,hi,lo] (LOSEG=2) => A'.B' = hihi+lohi+hilo
template <int LOSEG, int USECTX, int DSTW>
__global__ __launch_bounds__(256) void conv3_kernel(const float* __restrict__ inarg) {
    const float* in = USECTX ? (const float*)g_ctx : inarg;
    __nv_bfloat16* out = DSTW ? g_W3 : g_A3;
    int g = blockIdx.x * 256 + threadIdx.x;        // rows * 512
    int r = g >> 9, c4 = g & 511;
    float4 v = *(const float4*)(in + (size_t)r * DD + c4 * 4);
    union { __nv_bfloat16 b[4]; uint2 u; } hi, lo;
    float vv[4] = {v.x, v.y, v.z, v.w};
#pragma unroll
    for (int i = 0; i < 4; i++) {
        hi.b[i] = __float2bfloat16_rn(vv[i]);
        lo.b[i] = __float2bfloat16_rn(vv[i] - __bfloat162float(hi.b[i]));
    }
    constexpr int HISEG = 3 - LOSEG;
    __nv_bfloat16* o = out + (size_t)r * K3 + c4 * 4;
    *(uint2*)(o)            = hi.u;
    *(uint2*)(o + HISEG*DD) = hi.u;
    *(uint2*)(o + LOSEG*DD) = lo.u;
}

// ---------------- HMMA bf16 GEMM: C[M,N] = A3[M,K3] @ W3[N,K3]^T ----------------
// 128x128 tile, BK=64 per stage, 8 warps (2x4), warp tile 64x32, 3-stage cp.async,
// XOR-swizzled 128B smem rows (no padding).
#define GSTAGE 32768                    /* 2 tiles x 128 rows x 128B */
#define SMEM_GEMM_TOTAL (3*GSTAGE)      /* 98304 B */

template <int MODE>
__global__ __launch_bounds__(256) void gemm_mma(float* __restrict__ Cout, int N) {
    extern __shared__ __align__(16) char smraw[];
    const uint32_t sb = smem_u32(smraw);
    const int tid = threadIdx.x;
    const int bm = blockIdx.y * 128, bn = blockIdx.x * 128;
    const int warp = tid >> 5, lane = tid & 31;
    const int wm = warp >> 2, wn = warp & 3;
    const int iters = K3 / 64;                     // 96

    const __nv_bfloat16* Ag = g_A3 + (size_t)bm * K3;
    const __nv_bfloat16* Bg = g_W3 + (size_t)bn * K3;

    float acc[16][4];
#pragma unroll
    for (int i = 0; i < 16; i++)
#pragma unroll
        for (int j = 0; j < 4; j++) acc[i][j] = 0.f;

    auto load_stage = [&](int s, int k0) {
        uint32_t sa = sb + s * GSTAGE;
        uint32_t sbm = sa + 16384;
#pragma unroll
        for (int l = 0; l < 4; l++) {
            int idx = tid + l * 256;               // 1024 chunks per tile
            int row = idx >> 3, c = idx & 7;
            cp16(sa  + row * 128 + SWZ8(c, row) * 16, Ag + (size_t)row * K3 + k0 + c * 8);
            cp16(sbm + row * 128 + SWZ8(c, row) * 16, Bg + (size_t)row * K3 + k0 + c * 8);
        }
        asm volatile("cp.async.commit_group;" ::: "memory");
    };

    load_stage(0, 0);
    load_stage(1, 64);

    const int lrow = (lane & 7) + 8 * ((lane >> 3) & 1);
    const int lch  = lane >> 4;                    // chunk half

    for (int i = 0; i < iters; i++) {
        const int s = i % 3;
        if (i >= iters - 2) asm volatile("cp.async.wait_group 0;" ::: "memory");
        else                asm volatile("cp.async.wait_group 1;" ::: "memory");
        __syncthreads();
        if (i + 2 < iters) load_stage((i + 2) % 3, (i + 2) * 64);

        const uint32_t sa = sb + s * GSTAGE;
        const uint32_t sbm = sa + 16384;
#pragma unroll
        for (int ks = 0; ks < 4; ks++) {
            const int ch = ks * 2 + lch;
            uint32_t a[4][4], b[2][4];
#pragma unroll
            for (int mi = 0; mi < 4; mi++) {
                int row = wm * 64 + mi * 16 + lrow;
                ldmx4(a[mi], sa + row * 128 + SWZ8(ch, row) * 16);
            }
#pragma unroll
            for (int nb = 0; nb < 2; nb++) {
                int nr = wn * 32 + nb * 16 + lrow;
                ldmx4(b[nb], sbm + nr * 128 + SWZ8(ch, nr) * 16);
            }
#pragma unroll
            for (int mi = 0; mi < 4; mi++)
#pragma unroll
                for (int ni = 0; ni < 4; ni++)
                    mma16816(acc[mi * 4 + ni], a[mi],
                             b[ni >> 1][ni & 1], b[ni >> 1][(ni & 1) + 2]);
        }
    }

    // ---- epilogue: direct float2 stores ----
    if (MODE == 0) {
        const int which = bn >> 11;                // 0=q 1=k 2=v
        const int h = (bn >> 7) & 15;
        float* dst = (which == 0) ? g_q : (which == 1) ? g_k : g_v;
#pragma unroll
        for (int mi = 0; mi < 4; mi++)
#pragma unroll
            for (int ni = 0; ni < 4; ni++) {
                int d = wn * 32 + ni * 8 + (lane & 3) * 2;
#pragma unroll
                for (int half = 0; half < 2; half++) {
                    int m = bm + wm * 64 + mi * 16 + (lane >> 2) + half * 8;
                    int b_ = m >> 11, t_ = m & (TT - 1);
                    float2 v2 = make_float2(acc[mi * 4 + ni][2 * half],
                                            acc[mi * 4 + ni][2 * half + 1]);
                    *(float2*)&dst[(((size_t)b_ * HH + h) * TT + t_) * HDIM + d] = v2;
                }
            }
    } else {
#pragma unroll
        for (int mi = 0; mi < 4; mi++)
#pragma unroll
            for (int ni = 0; ni < 4; ni++) {
                int col = bn + wn * 32 + ni * 8 + (lane & 3) * 2;
#pragma unroll
                for (int half = 0; half < 2; half++) {
                    int m = bm + wm * 64 + mi * 16 + (lane >> 2) + half * 8;
                    float2 v2 = make_float2(acc[mi * 4 + ni][2 * half],
                                            acc[mi * 4 + ni][2 * half + 1]);
                    *(float2*)&Cout[(size_t)m * N + col] = v2;
                }
            }
    }
}

// ---------------- RoPE -> bf16 hi/lo planes for q and k ----------------
__global__ void rope_split_kernel() {
    int idx = blockIdx.x * blockDim.x + threadIdx.x;   // B*H*T*64
    int d  = idx & 63;
    int t  = (idx >> 6) & (TT - 1);
    int bh = idx >> 17;
    size_t base = ((size_t)bh * TT + t) * HDIM;
    float inv = (float)exp(-(double)(2 * d) / 128.0 * 9.210340371976184);
    float ang = (float)t * inv;
    float s, c;
    sincosf(ang, &s, &c);

    float q1 = g_q[base + d], q2 = g_q[base + d + 64];
    float qa = q1 * c - q2 * s, qb = q2 * c + q1 * s;
    float k1 = g_k[base + d], k2 = g_k[base + d + 64];
    float ka = k1 * c - k2 * s, kb = k2 * c + k1 * s;

    __nv_bfloat16 h;
    h = __float2bfloat16_rn(qa); g_qh[base + d] = h;
    g_ql[base + d] = __float2bfloat16_rn(qa - __bfloat162float(h));
    h = __float2bfloat16_rn(qb); g_qh[base + d + 64] = h;
    g_ql[base + d + 64] = __float2bfloat16_rn(qb - __bfloat162float(h));
    h = __float2bfloat16_rn(ka); g_kh[base + d] = h;
    g_kl[base + d] = __float2bfloat16_rn(ka - __bfloat162float(h));
    h = __float2bfloat16_rn(kb); g_kh[base + d + 64] = h;
    g_kl[base + d + 64] = __float2bfloat16_rn(kb - __bfloat162float(h));
}

// ---------------- v -> bf16 hi/lo planes ----------------
__global__ void vconv_kernel() {
    int g = blockIdx.x * 256 + threadIdx.x;            // PLANE_ELEMS/4
    float4 v = *(const float4*)(g_v + (size_t)g * 4);
    union { __nv_bfloat16 b[4]; uint2 u; } hi, lo;
    float vv[4] = {v.x, v.y, v.z, v.w};
#pragma unroll
    for (int i = 0; i < 4; i++) {
        hi.b[i] = __float2bfloat16_rn(vv[i]);
        lo.b[i] = __float2bfloat16_rn(vv[i] - __bfloat162float(hi.b[i]));
    }
    *(uint2*)(g_vh + (size_t)g * 4) = hi.u;
    *(uint2*)(g_vl + (size_t)g * 4) = lo.u;
}

// ---------------- HMMA flash attention: BQ=128, BKV=64, 8 warps ----------------
// smem: Qh[128][256B] Ql | 2 KV stages { Kh, Kl, Vh, Vl each [64][256B] }
#define AQ_OFF   0
#define AKV_OFF  65536
#define AKV_STG  65536
#define SMEM_ATTN_TOTAL (65536 + 2*65536)   /* 196608 */

__global__ __launch_bounds__(256) void attn_mma_kernel() {
    extern __shared__ __align__(16) char smraw[];
    const uint32_t sb = smem_u32(smraw);
    const int tid = threadIdx.x;
    const int warp = tid >> 5, lane = tid & 31;
    const int qt = 15 - blockIdx.x;                 // descending work order
    const int h = blockIdx.y, b = blockIdx.z;
    const int L = g_len[b];
    const size_t bhT = ((size_t)b * HH + h) * TT;

    const int lrow = (lane & 7) + 8 * ((lane >> 3) & 1);
    const int lch  = lane >> 4;

    // ---- load Q tile (both planes) ----
    {
        const __nv_bfloat16* qp[2];
        qp[0] = g_qh; qp[1] = g_ql;
#pragma unroll
        for (int l = 0; l < 16; l++) {
            int idx = tid + l * 256;                // 4096 chunks
            int pl = idx >> 11, rem = idx & 2047;
            int row = rem >> 4, c = rem & 15;
            cp16(sb + AQ_OFF + pl * 32768 + row * 256 + SWZ8(c, row) * 16,
                 qp[pl] + (bhT + (size_t)qt * 128 + row) * HDIM + c * 8);
        }
    }

    const int nt = (min(qt * 128 + 128, L) + 63) / 64;

    // ---- load KV stage 0 ----
    auto load_kv = [&](int kt, int stg) {
        const __nv_bfloat16* pp[4];
        pp[0] = g_kh; pp[1] = g_kl; pp[2] = g_vh; pp[3] = g_vl;
        uint32_t base = sb + AKV_OFF + stg * AKV_STG;
#pragma unroll
        for (int l = 0; l < 16; l++) {
            int idx = tid + l * 256;                // 4096 chunks
            int pl = idx >> 10, rem = idx & 1023;
            int row = rem >> 4, c = rem & 15;
            cp16(base + pl * 16384 + row * 256 + SWZ8(c, row) * 16,
                 pp[pl] + (bhT + (size_t)kt * 64 + row) * HDIM + c * 8);
        }
        asm volatile("cp.async.commit_group;" ::: "memory");
    };
    load_kv(0, 0);

    float oacc[16][4];
#pragma unroll
    for (int i = 0; i < 16; i++)
#pragma unroll
        for (int j = 0; j < 4; j++) oacc[i][j] = 0.f;
    float m0 = -1e30f, m1 = -1e30f, l0 = 0.f, l1 = 0.f;

    const int wr = qt * 128 + warp * 16;           // warp's first q row
    const float scl = 0.08838834764831843f;

    for (int kt = 0; kt < nt; kt++) {
        asm volatile("cp.async.wait_group 0;" ::: "memory");
        __syncthreads();
        if (kt + 1 < nt) load_kv(kt + 1, (kt + 1) & 1);

        const uint32_t kh = sb + AKV_OFF + (kt & 1) * AKV_STG;
        const uint32_t kl = kh + 16384;
        const uint32_t vh = kh + 32768;
        const uint32_t vl = kh + 49152;
        const uint32_t qh = sb + AQ_OFF;
        const uint32_t ql = qh + 32768;

        // ---- S = Qh*Kh + Ql*Kh + Qh*Kl ----
        float sacc[8][4];
#pragma unroll
        for (int i = 0; i < 8; i++)
#pragma unroll
            for (int j = 0; j < 4; j++) sacc[i][j] = 0.f;

#pragma unroll
        for (int k16 = 0; k16 < 8; k16++) {
            const int ch = k16 * 2 + lch;
            const int arow = warp * 16 + lrow;
            uint32_t ah[4], al[4];
            ldmx4(ah, qh + arow * 256 + SWZ8(ch, arow) * 16);
            ldmx4(al, ql + arow * 256 + SWZ8(ch, arow) * 16);
#pragma unroll
            for (int n16 = 0; n16 < 4; n16++) {
                const int nr = n16 * 16 + lrow;
                uint32_t bh[4], bl[4];
                ldmx4(bh, kh + nr * 256 + SWZ8(ch, nr) * 16);
                mma16816(sacc[2*n16],   ah, bh[0], bh[2]);
                mma16816(sacc[2*n16+1], ah, bh[1], bh[3]);
                mma16816(sacc[2*n16],   al, bh[0], bh[2]);
                mma16816(sacc[2*n16+1], al, bh[1], bh[3]);
                ldmx4(bl, kl + nr * 256 + SWZ8(ch, nr) * 16);
                mma16816(sacc[2*n16],   ah, bl[0], bl[2]);
                mma16816(sacc[2*n16+1], ah, bl[1], bl[3]);
            }
        }

        // ---- mask + online softmax ----
        const bool needmask = ((kt + 1) * 64 > qt * 128) || ((kt + 1) * 64 > L);
        const int r0g = wr + (lane >> 2);
#pragma unroll
        for (int f = 0; f < 8; f++)
#pragma unroll
            for (int c = 0; c < 4; c++) {
                float x = sacc[f][c] * scl;
                if (needmask) {
                    int col = kt * 64 + f * 8 + ((lane & 3) << 1) + (c & 1);
                    int rg = r0g + ((c >> 1) << 3);
                    if (col > rg || col >= L) x = -1e30f;
                }
                sacc[f][c] = x;
            }
        float mx0 = -1e30f, mx1 = -1e30f;
#pragma unroll
        for (int f = 0; f < 8; f++) {
            mx0 = fmaxf(mx0, fmaxf(sacc[f][0], sacc[f][1]));
            mx1 = fmaxf(mx1, fmaxf(sacc[f][2], sacc[f][3]));
        }
        mx0 = fmaxf(mx0, __shfl_xor_sync(0xffffffffu, mx0, 1));
        mx0 = fmaxf(mx0, __shfl_xor_sync(0xffffffffu, mx0, 2));
        mx1 = fmaxf(mx1, __shfl_xor_sync(0xffffffffu, mx1, 1));
        mx1 = fmaxf(mx1, __shfl_xor_sync(0xffffffffu, mx1, 2));
        float mn0 = fmaxf(m0, mx0), mn1 = fmaxf(m1, mx1);
        float corr0 = __expf(m0 - mn0), corr1 = __expf(m1 - mn1);
        float sum0 = 0.f, sum1 = 0.f;
#pragma unroll
        for (int f = 0; f < 8; f++) {
            float p;
            p = __expf(sacc[f][0] - mn0); sacc[f][0] = p; sum0 += p;
            p = __expf(sacc[f][1] - mn0); sacc[f][1] = p; sum0 += p;
            p = __expf(sacc[f][2] - mn1); sacc[f][2] = p; sum1 += p;
            p = __expf(sacc[f][3] - mn1); sacc[f][3] = p; sum1 += p;
        }
        sum0 += __shfl_xor_sync(0xffffffffu, sum0, 1);
        sum0 += __shfl_xor_sync(0xffffffffu, sum0, 2);
        sum1 += __shfl_xor_sync(0xffffffffu, sum1, 1);
        sum1 += __shfl_xor_sync(0xffffffffu, sum1, 2);
        l0 = l0 * corr0 + sum0; m0 = mn0;
        l1 = l1 * corr1 + sum1; m1 = mn1;
#pragma unroll
        for (int nf = 0; nf < 16; nf++) {
            oacc[nf][0] *= corr0; oacc[nf][1] *= corr0;
            oacc[nf][2] *= corr1; oacc[nf][3] *= corr1;
        }

        // ---- O += Ph*Vh + Pl*Vh + Ph*Vl ----
#pragma unroll
        for (int j16 = 0; j16 < 4; j16++) {
            const int f0 = 2 * j16, f1 = 2 * j16 + 1;
            uint32_t aPh[4], aPl[4];
            {
                float p00 = sacc[f0][0], p01 = sacc[f0][1];
                float p02 = sacc[f0][2], p03 = sacc[f0][3];
                float p10 = sacc[f1][0], p11 = sacc[f1][1];
                float p12 = sacc[f1][2], p13 = sacc[f1][3];
                aPh[0] = pack_bf16x2(p00, p01);
                aPh[1] = pack_bf16x2(p02, p03);
                aPh[2] = pack_bf16x2(p10, p11);
                aPh[3] = pack_bf16x2(p12, p13);
                // residuals
                union { uint32_t u; __nv_bfloat162 b2; } t;
                float r00, r01, r02, r03, r10, r11, r12, r13;
                t.u = aPh[0]; r00 = p00 - __bfloat162float(t.b2.x); r01 = p01 - __bfloat162float(t.b2.y);
                t.u = aPh[1]; r02 = p02 - __bfloat162float(t.b2.x); r03 = p03 - __bfloat162float(t.b2.y);
                t.u = aPh[2]; r10 = p10 - __bfloat162float(t.b2.x); r11 = p11 - __bfloat162float(t.b2.y);
                t.u = aPh[3]; r12 = p12 - __bfloat162float(t.b2.x); r13 = p13 - __bfloat162float(t.b2.y);
                aPl[0] = pack_bf16x2(r00, r01);
                aPl[1] = pack_bf16x2(r02, r03);
                aPl[2] = pack_bf16x2(r10, r11);
                aPl[3] = pack_bf16x2(r12, r13);
            }
#pragma unroll
            for (int d16 = 0; d16 < 8; d16++) {
                const int ch = d16 * 2 + lch;
                const int vr = j16 * 16 + lrow;
                uint32_t bvh[4], bvl[4];
                ldmx4t(bvh, vh + vr * 256 + SWZ8(ch, vr) * 16);
                mma16816(oacc[2*d16],   aPh, bvh[0], bvh[1]);
                mma16816(oacc[2*d16+1], aPh, bvh[2], bvh[3]);
                mma16816(oacc[2*d16],   aPl, bvh[0], bvh[1]);
                mma16816(oacc[2*d16+1], aPl, bvh[2], bvh[3]);
                ldmx4t(bvl, vl + vr * 256 + SWZ8(ch, vr) * 16);
                mma16816(oacc[2*d16],   aPh, bvl[0], bvl[1]);
                mma16816(oacc[2*d16+1], aPh, bvl[2], bvl[3]);
            }
        }
        __syncthreads();
    }

    // ---- epilogue ----
    const float il0 = 1.f / l0, il1 = 1.f / l1;
    const int trow = qt * 128 + warp * 16 + (lane >> 2);
#pragma unroll
    for (int nf = 0; nf < 16; nf++) {
        int d = h * 128 + nf * 8 + (lane & 3) * 2;
        *(float2*)&g_ctx[((size_t)b * TT + trow) * DD + d] =
            make_float2(oacc[nf][0] * il0, oacc[nf][1] * il0);
        *(float2*)&g_ctx[((size_t)b * TT + trow + 8) * DD + d] =
            make_float2(oacc[nf][2] * il1, oacc[nf][3] * il1);
    }
}

// ---------------- launcher ----------------
extern "C" void kernel_launch(void* const* d_in, const int* in_sizes, int n_in,
                              void* d_out, int out_size) {
    const float* x     = (const float*)d_in[0];
    const float* Wqkv  = (const float*)d_in[1];
    const float* Wproj = (const float*)d_in[2];
    const int*   mask  = (const int*)d_in[3];
    float* out = (float*)d_out;

    cudaFuncSetAttribute(gemm_mma<0>, cudaFuncAttributeMaxDynamicSharedMemorySize, SMEM_GEMM_TOTAL);
    cudaFuncSetAttribute(gemm_mma<1>, cudaFuncAttributeMaxDynamicSharedMemorySize, SMEM_GEMM_TOTAL);
    cudaFuncSetAttribute(attn_mma_kernel, cudaFuncAttributeMaxDynamicSharedMemorySize, SMEM_ATTN_TOTAL);

    lengths_kernel<<<BB, 256>>>(mask);
    conv3_kernel<1, 0, 0><<<MROWS * 2, 256>>>(x);       // x    -> g_A3 [hi,lo,hi]
    conv3_kernel<2, 0, 1><<<K3 * 2, 256>>>(Wqkv);       // Wqkv -> g_W3 [hi,hi,lo]
    gemm_mma<0><<<dim3(K3 / 128, MROWS / 128), 256, SMEM_GEMM_TOTAL>>>(nullptr, K3);
    rope_split_kernel<<<(BB * HH * TT * 64) / 256, 256>>>();
    vconv_kernel<<<(int)(PLANE_ELEMS / 4 / 256), 256>>>();
    attn_mma_kernel<<<dim3(16, HH, BB), 256, SMEM_ATTN_TOTAL>>>();
    conv3_kernel<1, 1, 0><<<MROWS * 2, 256>>>(nullptr); // ctx  -> g_A3 [hi,lo,hi]
    conv3_kernel<2, 0, 1><<<DD * 2, 256>>>(Wproj);      // Wproj-> g_W3 [hi,hi,lo]
    gemm_mma<1><<<dim3(DD / 128, MROWS / 128), 256, SMEM_GEMM_TOTAL>>>(out, DD);
}

// round 7
// speedup vs baseline: 3.4109x; 1.0214x over previous
#include <cuda_runtime.h>
#include <cuda_bf16.h>
#include <cstdint>
#include <math.h>

#define BB 4
#define TT 2048
#define DD 2048
#define HH 16
#define HDIM 128
#define MROWS (BB*TT)       /* 8192 */
#define K3 (3*DD)           /* 6144 */
#define PLANE_ELEMS ((size_t)BB*HH*TT*HDIM)   /* 16.8M */

// ---------------- scratch (device globals; uint4-backed => 16B align) ----------
__device__ uint4 g_q_raw  [PLANE_ELEMS/4];               // fp32 (B,H,T,hd)
__device__ uint4 g_k_raw  [PLANE_ELEMS/4];
__device__ uint4 g_A3_raw [(size_t)MROWS*K3/8];          // bf16x3 activations
__device__ uint4 g_W3_raw [(size_t)K3*K3/8];             // bf16x3 weights
__device__ uint4 g_qh_raw [PLANE_ELEMS/8];               // bf16 planes
__device__ uint4 g_ql_raw [PLANE_ELEMS/8];
__device__ uint4 g_kh_raw [PLANE_ELEMS/8];
__device__ uint4 g_kl_raw [PLANE_ELEMS/8];
__device__ uint4 g_vh_raw [PLANE_ELEMS/8];
__device__ uint4 g_vl_raw [PLANE_ELEMS/8];
__device__ int   g_len[BB];

// device-code-only views (never use in host code / kernel args)
#define g_q   ((float*)g_q_raw)
#define g_k   ((float*)g_k_raw)
#define g_A3  ((__nv_bfloat16*)g_A3_raw)
#define g_W3  ((__nv_bfloat16*)g_W3_raw)
#define g_qh  ((__nv_bfloat16*)g_qh_raw)
#define g_ql  ((__nv_bfloat16*)g_ql_raw)
#define g_kh  ((__nv_bfloat16*)g_kh_raw)
#define g_kl  ((__nv_bfloat16*)g_kl_raw)
#define g_vh  ((__nv_bfloat16*)g_vh_raw)
#define g_vl  ((__nv_bfloat16*)g_vl_raw)

// ============================ helpers ============================
__device__ __forceinline__ uint32_t smem_u32(const void* p) {
    uint32_t a;
    asm("{ .reg .u64 t; cvta.to.shared.u64 t, %1; cvt.u32.u64 %0, t; }" : "=r"(a) : "l"(p));
    return a;
}
__device__ __forceinline__ void cp16(uint32_t s, const void* g) {
    asm volatile("cp.async.cg.shared.global [%0], [%1], 16;" :: "r"(s), "l"(g));
}
__device__ __forceinline__ void ldmx4(uint32_t* r, uint32_t addr) {
    asm volatile("ldmatrix.sync.aligned.m8n8.x4.shared.b16 {%0,%1,%2,%3}, [%4];"
        : "=r"(r[0]), "=r"(r[1]), "=r"(r[2]), "=r"(r[3]) : "r"(addr));
}
__device__ __forceinline__ void ldmx4t(uint32_t* r, uint32_t addr) {
    asm volatile("ldmatrix.sync.aligned.m8n8.x4.trans.shared.b16 {%0,%1,%2,%3}, [%4];"
        : "=r"(r[0]), "=r"(r[1]), "=r"(r[2]), "=r"(r[3]) : "r"(addr));
}
__device__ __forceinline__ void mma16816(float* d, const uint32_t* a, uint32_t b0, uint32_t b1) {
    asm volatile("mma.sync.aligned.m16n8k16.row.col.f32.bf16.bf16.f32 "
        "{%0,%1,%2,%3}, {%4,%5,%6,%7}, {%8,%9}, {%0,%1,%2,%3};"
        : "+f"(d[0]), "+f"(d[1]), "+f"(d[2]), "+f"(d[3])
        : "r"(a[0]), "r"(a[1]), "r"(a[2]), "r"(a[3]), "r"(b0), "r"(b1));
}
__device__ __forceinline__ uint32_t pack_bf16x2(float lo, float hi) {
    uint32_t r;
    asm("cvt.rn.bf16x2.f32 %0, %1, %2;" : "=r"(r) : "f"(hi), "f"(lo));
    return r;
}
#define SWZ8(c, r)  ((c) ^ ((r) & 7))

// ---------------- per-batch valid lengths ----------------
__global__ void lengths_kernel(const int* __restrict__ mask) {
    __shared__ int sd[256];
    int b = blockIdx.x;
    int s = 0;
    for (int i = threadIdx.x; i < TT; i += 256) s += mask[b * TT + i];
    sd[threadIdx.x] = s;
    __syncthreads();
    for (int st = 128; st > 0; st >>= 1) {
        if (threadIdx.x < st) sd[threadIdx.x] += sd[threadIdx.x + st];
        __syncthreads();
    }
    if (threadIdx.x == 0) g_len[b] = sd[0];
}

// ---------------- fp32 -> bf16x3 split conversion ----------------
// A'=[hi,lo,hi] (LOSEG=1), B'=[hi,hi,lo] (LOSEG=2)
template <int LOSEG, int DSTW>
__global__ __launch_bounds__(256) void conv3_kernel(const float* __restrict__ in) {
    __nv_bfloat16* out = DSTW ? g_W3 : g_A3;
    int g = blockIdx.x * 256 + threadIdx.x;        // rows * 512
    int r = g >> 9, c4 = g & 511;
    float4 v = *(const float4*)(in + (size_t)r * DD + c4 * 4);
    union { __nv_bfloat16 b[4]; uint2 u; } hi, lo;
    float vv[4] = {v.x, v.y, v.z, v.w};
#pragma unroll
    for (int i = 0; i < 4; i++) {
        hi.b[i] = __float2bfloat16_rn(vv[i]);
        lo.b[i] = __float2bfloat16_rn(vv[i] - __bfloat162float(hi.b[i]));
    }
    constexpr int HISEG = 3 - LOSEG;
    __nv_bfloat16* o = out + (size_t)r * K3 + c4 * 4;
    *(uint2*)(o)            = hi.u;
    *(uint2*)(o + HISEG*DD) = hi.u;
    *(uint2*)(o + LOSEG*DD) = lo.u;
}

// ---------------- HMMA bf16 GEMM: C[M,N] = A3[M,K3] @ W3[N,K3]^T ----------------
// 128x128 tile, BK=64/stage, 8 warps (2x4), warp tile 64x32, 3-stage cp.async,
// XOR-swizzled 128B rows, hoisted addressing, pipeline unrolled x3.
#define GSTAGE 32768
#define SMEM_GEMM_TOTAL (3*GSTAGE)      /* 98304 B */

template <int MODE>
__global__ __launch_bounds__(256, 2) void gemm_mma(float* __restrict__ Cout, int N) {
    extern __shared__ __align__(16) char smraw[];
    const uint32_t sb = smem_u32(smraw);
    const int tid = threadIdx.x;
    const int bm = blockIdx.y * 128, bn = blockIdx.x * 128;
    const int warp = tid >> 5, lane = tid & 31;
    const int wm = warp >> 2, wn = warp & 3;
    const int iters = K3 / 64;                     // 96

    float acc[16][4];
#pragma unroll
    for (int i = 0; i < 16; i++)
#pragma unroll
        for (int j = 0; j < 4; j++) acc[i][j] = 0.f;

    // hoisted cp.async addressing: 4 A chunks + 4 B chunks per thread
    const __nv_bfloat16* pA[4];
    const __nv_bfloat16* pB[4];
    uint32_t soA[4], soB[4];
#pragma unroll
    for (int l = 0; l < 4; l++) {
        int idx = tid + l * 256;
        int row = idx >> 3, c = idx & 7;
        uint32_t so = row * 128 + SWZ8(c, row) * 16;
        soA[l] = so; soB[l] = so + 16384;
        pA[l] = g_A3 + (size_t)(bm + row) * K3 + c * 8;
        pB[l] = g_W3 + (size_t)(bn + row) * K3 + c * 8;
    }
    auto load_stage = [&](uint32_t sbase) {
#pragma unroll
        for (int l = 0; l < 4; l++) {
            cp16(sbase + soA[l], pA[l]);
            cp16(sbase + soB[l], pB[l]);
        }
        asm volatile("cp.async.commit_group;" ::: "memory");
#pragma unroll
        for (int l = 0; l < 4; l++) { pA[l] += 64; pB[l] += 64; }
    };

    load_stage(sb);
    load_stage(sb + GSTAGE);

    const int lrow = (lane & 7) + 8 * ((lane >> 3) & 1);
    const int lch  = lane >> 4;
    // hoisted ldmatrix row offsets
    uint32_t aro[4], bro[2];
#pragma unroll
    for (int mi = 0; mi < 4; mi++) {
        int row = wm * 64 + mi * 16 + lrow;
        aro[mi] = row * 128 + ((row & 7) << 4);
    }
#pragma unroll
    for (int nb = 0; nb < 2; nb++) {
        int nr = wn * 32 + nb * 16 + lrow;
        bro[nb] = 16384 + nr * 128 + ((nr & 7) << 4);
    }

    for (int i = 0; i < iters; i += 3) {
#pragma unroll
        for (int u = 0; u < 3; u++) {
            const int idx = i + u;
            if (idx >= iters - 2) asm volatile("cp.async.wait_group 0;" ::: "memory");
            else                  asm volatile("cp.async.wait_group 1;" ::: "memory");
            __syncthreads();
            if (idx + 2 < iters) load_stage(sb + ((u + 2) % 3) * GSTAGE);

            const uint32_t sa = sb + u * GSTAGE;
#pragma unroll
            for (int ks = 0; ks < 4; ks++) {
                const uint32_t chx = (uint32_t)(ks * 2 + lch) << 4;
                uint32_t a[4][4], b[2][4];
#pragma unroll
                for (int mi = 0; mi < 4; mi++)
                    ldmx4(a[mi], sa + (aro[mi] ^ chx));
#pragma unroll
                for (int nb = 0; nb < 2; nb++)
                    ldmx4(b[nb], sa + (bro[nb] ^ chx));
#pragma unroll
                for (int mi = 0; mi < 4; mi++)
#pragma unroll
                    for (int ni = 0; ni < 4; ni++)
                        mma16816(acc[mi * 4 + ni], a[mi],
                                 b[ni >> 1][ni & 1], b[ni >> 1][(ni & 1) + 2]);
            }
        }
    }

    // ---- epilogue ----
    if (MODE == 0) {
        const int which = bn >> 11;                // 0=q 1=k 2=v
        const int h = (bn >> 7) & 15;
        if (which == 2) {
            // V: write bf16 hi/lo planes directly
#pragma unroll
            for (int mi = 0; mi < 4; mi++)
#pragma unroll
                for (int ni = 0; ni < 4; ni++) {
                    int d = wn * 32 + ni * 8 + (lane & 3) * 2;
#pragma unroll
                    for (int half = 0; half < 2; half++) {
                        int m = bm + wm * 64 + mi * 16 + (lane >> 2) + half * 8;
                        int b_ = m >> 11, t_ = m & (TT - 1);
                        size_t off = (((size_t)b_ * HH + h) * TT + t_) * HDIM + d;
                        float v0 = acc[mi * 4 + ni][2 * half];
                        float v1 = acc[mi * 4 + ni][2 * half + 1];
                        __nv_bfloat16 h0 = __float2bfloat16_rn(v0);
                        __nv_bfloat16 h1 = __float2bfloat16_rn(v1);
                        float r0 = v0 - __bfloat162float(h0);
                        float r1 = v1 - __bfloat162float(h1);
                        union { __nv_bfloat16 b[2]; uint32_t u; } ph, pl;
                        ph.b[0] = h0; ph.b[1] = h1;
                        pl.b[0] = __float2bfloat16_rn(r0);
                        pl.b[1] = __float2bfloat16_rn(r1);
                        *(uint32_t*)&g_vh[off] = ph.u;
                        *(uint32_t*)&g_vl[off] = pl.u;
                    }
                }
        } else {
            float* dst = (which == 0) ? g_q : g_k;
#pragma unroll
            for (int mi = 0; mi < 4; mi++)
#pragma unroll
                for (int ni = 0; ni < 4; ni++) {
                    int d = wn * 32 + ni * 8 + (lane & 3) * 2;
#pragma unroll
                    for (int half = 0; half < 2; half++) {
                        int m = bm + wm * 64 + mi * 16 + (lane >> 2) + half * 8;
                        int b_ = m >> 11, t_ = m & (TT - 1);
                        float2 v2 = make_float2(acc[mi * 4 + ni][2 * half],
                                                acc[mi * 4 + ni][2 * half + 1]);
                        *(float2*)&dst[(((size_t)b_ * HH + h) * TT + t_) * HDIM + d] = v2;
                    }
                }
        }
    } else {
#pragma unroll
        for (int mi = 0; mi < 4; mi++)
#pragma unroll
            for (int ni = 0; ni < 4; ni++) {
                int col = bn + wn * 32 + ni * 8 + (lane & 3) * 2;
#pragma unroll
                for (int half = 0; half < 2; half++) {
                    int m = bm + wm * 64 + mi * 16 + (lane >> 2) + half * 8;
                    float2 v2 = make_float2(acc[mi * 4 + ni][2 * half],
                                            acc[mi * 4 + ni][2 * half + 1]);
                    *(float2*)&Cout[(size_t)m * N + col] = v2;
                }
            }
    }
}

// ---------------- RoPE -> bf16 hi/lo planes for q and k ----------------
__global__ void rope_split_kernel() {
    int idx = blockIdx.x * blockDim.x + threadIdx.x;   // B*H*T*64
    int d  = idx & 63;
    int t  = (idx >> 6) & (TT - 1);
    int bh = idx >> 17;
    size_t base = ((size_t)bh * TT + t) * HDIM;
    float inv = (float)exp(-(double)(2 * d) / 128.0 * 9.210340371976184);
    float ang = (float)t * inv;
    float s, c;
    sincosf(ang, &s, &c);

    float q1 = g_q[base + d], q2 = g_q[base + d + 64];
    float qa = q1 * c - q2 * s, qb = q2 * c + q1 * s;
    float k1 = g_k[base + d], k2 = g_k[base + d + 64];
    float ka = k1 * c - k2 * s, kb = k2 * c + k1 * s;

    __nv_bfloat16 h;
    h = __float2bfloat16_rn(qa); g_qh[base + d] = h;
    g_ql[base + d] = __float2bfloat16_rn(qa - __bfloat162float(h));
    h = __float2bfloat16_rn(qb); g_qh[base + d + 64] = h;
    g_ql[base + d + 64] = __float2bfloat16_rn(qb - __bfloat162float(h));
    h = __float2bfloat16_rn(ka); g_kh[base + d] = h;
    g_kl[base + d] = __float2bfloat16_rn(ka - __bfloat162float(h));
    h = __float2bfloat16_rn(kb); g_kh[base + d + 64] = h;
    g_kl[base + d + 64] = __float2bfloat16_rn(kb - __bfloat162float(h));
}

// ---------------- HMMA flash attention: BQ=128, BKV=64, 8 warps ----------------
#define AQ_OFF   0
#define AKV_OFF  65536
#define AKV_STG  65536
#define SMEM_ATTN_TOTAL (65536 + 2*65536)   /* 196608 */

__global__ __launch_bounds__(256) void attn_mma_kernel() {
    extern __shared__ __align__(16) char smraw[];
    const uint32_t sb = smem_u32(smraw);
    const int tid = threadIdx.x;
    const int warp = tid >> 5, lane = tid & 31;
    const int qt = 15 - blockIdx.x;                 // descending work order
    const int h = blockIdx.y, b = blockIdx.z;
    const int L = g_len[b];
    const size_t bhT = ((size_t)b * HH + h) * TT;

    const int lrow = (lane & 7) + 8 * ((lane >> 3) & 1);
    const int lch  = lane >> 4;

    // ---- load Q tile (both planes), own commit group ----
    {
        const __nv_bfloat16* qp[2];
        qp[0] = g_qh; qp[1] = g_ql;
#pragma unroll
        for (int l = 0; l < 16; l++) {
            int idx = tid + l * 256;                // 4096 chunks
            int pl = idx >> 11, rem = idx & 2047;
            int row = rem >> 4, c = rem & 15;
            cp16(sb + AQ_OFF + pl * 32768 + row * 256 + SWZ8(c, row) * 16,
                 qp[pl] + (bhT + (size_t)qt * 128 + row) * HDIM + c * 8);
        }
        asm volatile("cp.async.commit_group;" ::: "memory");
    }

    const int nt = (min(qt * 128 + 128, L) + 63) / 64;

    auto load_kv = [&](int kt, int stg) {
        const __nv_bfloat16* pp[4];
        pp[0] = g_kh; pp[1] = g_kl; pp[2] = g_vh; pp[3] = g_vl;
        uint32_t base = sb + AKV_OFF + stg * AKV_STG;
#pragma unroll
        for (int l = 0; l < 16; l++) {
            int idx = tid + l * 256;
            int pl = idx >> 10, rem = idx & 1023;
            int row = rem >> 4, c = rem & 15;
            cp16(base + pl * 16384 + row * 256 + SWZ8(c, row) * 16,
                 pp[pl] + (bhT + (size_t)kt * 64 + row) * HDIM + c * 8);
        }
        asm volatile("cp.async.commit_group;" ::: "memory");
    };
    load_kv(0, 0);

    // ---- hoist Q fragments (wait only for the Q group) ----
    uint32_t qhf[8][4], qlf[8][4];
    {
        asm volatile("cp.async.wait_group 1;" ::: "memory");
        __syncthreads();
        const uint32_t qh = sb + AQ_OFF, ql = qh + 32768;
        const int arow = warp * 16 + lrow;
#pragma unroll
        for (int k16 = 0; k16 < 8; k16++) {
            const int ch = k16 * 2 + lch;
            ldmx4(qhf[k16], qh + arow * 256 + SWZ8(ch, arow) * 16);
            ldmx4(qlf[k16], ql + arow * 256 + SWZ8(ch, arow) * 16);
        }
    }

    float oacc[16][4];
#pragma unroll
    for (int i = 0; i < 16; i++)
#pragma unroll
        for (int j = 0; j < 4; j++) oacc[i][j] = 0.f;
    float m0 = -1e30f, m1 = -1e30f, l0 = 0.f, l1 = 0.f;

    const int wr = qt * 128 + warp * 16;
    const float scl = 0.08838834764831843f;

    for (int kt = 0; kt < nt; kt++) {
        asm volatile("cp.async.wait_group 0;" ::: "memory");
        __syncthreads();
        if (kt + 1 < nt) load_kv(kt + 1, (kt + 1) & 1);

        const uint32_t kh = sb + AKV_OFF + (kt & 1) * AKV_STG;
        const uint32_t kl = kh + 16384;
        const uint32_t vh = kh + 32768;
        const uint32_t vl = kh + 49152;

        // ---- S = Qh*Kh + Ql*Kh + Qh*Kl ----
        float sacc[8][4];
#pragma unroll
        for (int i = 0; i < 8; i++)
#pragma unroll
            for (int j = 0; j < 4; j++) sacc[i][j] = 0.f;

#pragma unroll
        for (int k16 = 0; k16 < 8; k16++) {
            const int ch = k16 * 2 + lch;
#pragma unroll
            for (int n16 = 0; n16 < 4; n16++) {
                const int nr = n16 * 16 + lrow;
                uint32_t bh[4], bl[4];
                ldmx4(bh, kh + nr * 256 + SWZ8(ch, nr) * 16);
                mma16816(sacc[2*n16],   qhf[k16], bh[0], bh[2]);
                mma16816(sacc[2*n16+1], qhf[k16], bh[1], bh[3]);
                mma16816(sacc[2*n16],   qlf[k16], bh[0], bh[2]);
                mma16816(sacc[2*n16+1], qlf[k16], bh[1], bh[3]);
                ldmx4(bl, kl + nr * 256 + SWZ8(ch, nr) * 16);
                mma16816(sacc[2*n16],   qhf[k16], bl[0], bl[2]);
                mma16816(sacc[2*n16+1], qhf[k16], bl[1], bl[3]);
            }
        }

        // ---- mask + online softmax ----
        const bool needmask = ((kt + 1) * 64 > qt * 128) || ((kt + 1) * 64 > L);
        const int r0g = wr + (lane >> 2);
#pragma unroll
        for (int f = 0; f < 8; f++)
#pragma unroll
            for (int c = 0; c < 4; c++) {
                float x = sacc[f][c] * scl;
                if (needmask) {
                    int col = kt * 64 + f * 8 + ((lane & 3) << 1) + (c & 1);
                    int rg = r0g + ((c >> 1) << 3);
                    if (col > rg || col >= L) x = -1e30f;
                }
                sacc[f][c] = x;
            }
        float mx0 = -1e30f, mx1 = -1e30f;
#pragma unroll
        for (int f = 0; f < 8; f++) {
            mx0 = fmaxf(mx0, fmaxf(sacc[f][0], sacc[f][1]));
            mx1 = fmaxf(mx1, fmaxf(sacc[f][2], sacc[f][3]));
        }
        mx0 = fmaxf(mx0, __shfl_xor_sync(0xffffffffu, mx0, 1));
        mx0 = fmaxf(mx0, __shfl_xor_sync(0xffffffffu, mx0, 2));
        mx1 = fmaxf(mx1, __shfl_xor_sync(0xffffffffu, mx1, 1));
        mx1 = fmaxf(mx1, __shfl_xor_sync(0xffffffffu, mx1, 2));
        float mn0 = fmaxf(m0, mx0), mn1 = fmaxf(m1, mx1);
        float corr0 = __expf(m0 - mn0), corr1 = __expf(m1 - mn1);
        float sum0 = 0.f, sum1 = 0.f;
#pragma unroll
        for (int f = 0; f < 8; f++) {
            float p;
            p = __expf(sacc[f][0] - mn0); sacc[f][0] = p; sum0 += p;
            p = __expf(sacc[f][1] - mn0); sacc[f][1] = p; sum0 += p;
            p = __expf(sacc[f][2] - mn1); sacc[f][2] = p; sum1 += p;
            p = __expf(sacc[f][3] - mn1); sacc[f][3] = p; sum1 += p;
        }
        sum0 += __shfl_xor_sync(0xffffffffu, sum0, 1);
        sum0 += __shfl_xor_sync(0xffffffffu, sum0, 2);
        sum1 += __shfl_xor_sync(0xffffffffu, sum1, 1);
        sum1 += __shfl_xor_sync(0xffffffffu, sum1, 2);
        l0 = l0 * corr0 + sum0; m0 = mn0;
        l1 = l1 * corr1 + sum1; m1 = mn1;
#pragma unroll
        for (int nf = 0; nf < 16; nf++) {
            oacc[nf][0] *= corr0; oacc[nf][1] *= corr0;
            oacc[nf][2] *= corr1; oacc[nf][3] *= corr1;
        }

        // ---- O += Ph*Vh + Pl*Vh + Ph*Vl ----
#pragma unroll
        for (int j16 = 0; j16 < 4; j16++) {
            const int f0 = 2 * j16, f1 = 2 * j16 + 1;
            uint32_t aPh[4], aPl[4];
            {
                float p00 = sacc[f0][0], p01 = sacc[f0][1];
                float p02 = sacc[f0][2], p03 = sacc[f0][3];
                float p10 = sacc[f1][0], p11 = sacc[f1][1];
                float p12 = sacc[f1][2], p13 = sacc[f1][3];
                aPh[0] = pack_bf16x2(p00, p01);
                aPh[1] = pack_bf16x2(p02, p03);
                aPh[2] = pack_bf16x2(p10, p11);
                aPh[3] = pack_bf16x2(p12, p13);
                union { uint32_t u; __nv_bfloat162 b2; } t;
                float r00, r01, r02, r03, r10, r11, r12, r13;
                t.u = aPh[0]; r00 = p00 - __bfloat162float(t.b2.x); r01 = p01 - __bfloat162float(t.b2.y);
                t.u = aPh[1]; r02 = p02 - __bfloat162float(t.b2.x); r03 = p03 - __bfloat162float(t.b2.y);
                t.u = aPh[2]; r10 = p10 - __bfloat162float(t.b2.x); r11 = p11 - __bfloat162float(t.b2.y);
                t.u = aPh[3]; r12 = p12 - __bfloat162float(t.b2.x); r13 = p13 - __bfloat162float(t.b2.y);
                aPl[0] = pack_bf16x2(r00, r01);
                aPl[1] = pack_bf16x2(r02, r03);
                aPl[2] = pack_bf16x2(r10, r11);
                aPl[3] = pack_bf16x2(r12, r13);
            }
#pragma unroll
            for (int d16 = 0; d16 < 8; d16++) {
                const int ch = d16 * 2 + lch;
                const int vr = j16 * 16 + lrow;
                uint32_t bvh[4], bvl[4];
                ldmx4t(bvh, vh + vr * 256 + SWZ8(ch, vr) * 16);
                mma16816(oacc[2*d16],   aPh, bvh[0], bvh[1]);
                mma16816(oacc[2*d16+1], aPh, bvh[2], bvh[3]);
                mma16816(oacc[2*d16],   aPl, bvh[0], bvh[1]);
                mma16816(oacc[2*d16+1], aPl, bvh[2], bvh[3]);
                ldmx4t(bvl, vl + vr * 256 + SWZ8(ch, vr) * 16);
                mma16816(oacc[2*d16],   aPh, bvl[0], bvl[1]);
                mma16816(oacc[2*d16+1], aPh, bvl[2], bvl[3]);
            }
        }
        __syncthreads();
    }

    // ---- epilogue: write directly into g_A3 bf16x3 [hi|lo|hi] ----
    const float il0 = 1.f / l0, il1 = 1.f / l1;
    const int trow = qt * 128 + warp * 16 + (lane >> 2);
#pragma unroll
    for (int nf = 0; nf < 16; nf++) {
        int col = h * 128 + nf * 8 + (lane & 3) * 2;
#pragma unroll
        for (int half = 0; half < 2; half++) {
            float v0 = oacc[nf][2 * half]     * (half ? il1 : il0);
            float v1 = oacc[nf][2 * half + 1] * (half ? il1 : il0);
            __nv_bfloat16 h0 = __float2bfloat16_rn(v0);
            __nv_bfloat16 h1 = __float2bfloat16_rn(v1);
            union { __nv_bfloat16 b[2]; uint32_t u; } ph, pl;
            ph.b[0] = h0; ph.b[1] = h1;
            pl.b[0] = __float2bfloat16_rn(v0 - __bfloat162float(h0));
            pl.b[1] = __float2bfloat16_rn(v1 - __bfloat162float(h1));
            __nv_bfloat16* row = g_A3 + ((size_t)b * TT + trow + half * 8) * K3;
            *(uint32_t*)&row[col]          = ph.u;
            *(uint32_t*)&row[col + 2*DD]   = ph.u;
            *(uint32_t*)&row[col + DD]     = pl.u;
        }
    }
}

// ---------------- launcher ----------------
extern "C" void kernel_launch(void* const* d_in, const int* in_sizes, int n_in,
                              void* d_out, int out_size) {
    const float* x     = (const float*)d_in[0];
    const float* Wqkv  = (const float*)d_in[1];
    const float* Wproj = (const float*)d_in[2];
    const int*   mask  = (const int*)d_in[3];
    float* out = (float*)d_out;

    cudaFuncSetAttribute(gemm_mma<0>, cudaFuncAttributeMaxDynamicSharedMemorySize, SMEM_GEMM_TOTAL);
    cudaFuncSetAttribute(gemm_mma<1>, cudaFuncAttributeMaxDynamicSharedMemorySize, SMEM_GEMM_TOTAL);
    cudaFuncSetAttribute(attn_mma_kernel, cudaFuncAttributeMaxDynamicSharedMemorySize, SMEM_ATTN_TOTAL);

    lengths_kernel<<<BB, 256>>>(mask);
    conv3_kernel<1, 0><<<MROWS * 2, 256>>>(x);       // x    -> g_A3 [hi,lo,hi]
    conv3_kernel<2, 1><<<K3 * 2, 256>>>(Wqkv);       // Wqkv -> g_W3 [hi,hi,lo]
    gemm_mma<0><<<dim3(K3 / 128, MROWS / 128), 256, SMEM_GEMM_TOTAL>>>(nullptr, K3);
    rope_split_kernel<<<(BB * HH * TT * 64) / 256, 256>>>();
    attn_mma_kernel<<<dim3(16, HH, BB), 256, SMEM_ATTN_TOTAL>>>();
    conv3_kernel<2, 1><<<DD * 2, 256>>>(Wproj);      // Wproj-> g_W3 [hi,hi,lo]
    gemm_mma<1><<<dim3(DD / 128, MROWS / 128), 256, SMEM_GEMM_TOTAL>>>(out, DD);
}

// round 8
// speedup vs baseline: 3.5576x; 1.0430x over previous
#include <cuda_runtime.h>
#include <cuda_bf16.h>
#include <cstdint>
#include <math.h>

#define BB 4
#define TT 2048
#define DD 2048
#define HH 16
#define HDIM 128
#define MROWS (BB*TT)       /* 8192 */
#define K3 (3*DD)           /* 6144 */
#define PLANE_ELEMS ((size_t)BB*HH*TT*HDIM)   /* 16.8M */

// ---------------- scratch (device globals; uint4-backed => 16B align) ----------
__device__ uint4 g_q_raw  [PLANE_ELEMS/4];               // fp32 (B,H,T,hd)
__device__ uint4 g_k_raw  [PLANE_ELEMS/4];
__device__ uint4 g_A3_raw [(size_t)MROWS*K3/8];          // bf16x3 activations
__device__ uint4 g_W3_raw [(size_t)K3*K3/8];             // bf16x3 weights
__device__ uint4 g_qh_raw [PLANE_ELEMS/8];               // bf16 planes
__device__ uint4 g_ql_raw [PLANE_ELEMS/8];
__device__ uint4 g_kh_raw [PLANE_ELEMS/8];
__device__ uint4 g_kl_raw [PLANE_ELEMS/8];
__device__ uint4 g_vh_raw [PLANE_ELEMS/8];
__device__ uint4 g_vl_raw [PLANE_ELEMS/8];
__device__ int   g_len[BB];

// device-code-only views (never use in host code / kernel args)
#define g_q   ((float*)g_q_raw)
#define g_k   ((float*)g_k_raw)
#define g_A3  ((__nv_bfloat16*)g_A3_raw)
#define g_W3  ((__nv_bfloat16*)g_W3_raw)
#define g_qh  ((__nv_bfloat16*)g_qh_raw)
#define g_ql  ((__nv_bfloat16*)g_ql_raw)
#define g_kh  ((__nv_bfloat16*)g_kh_raw)
#define g_kl  ((__nv_bfloat16*)g_kl_raw)
#define g_vh  ((__nv_bfloat16*)g_vh_raw)
#define g_vl  ((__nv_bfloat16*)g_vl_raw)

// ============================ helpers ============================
__device__ __forceinline__ uint32_t smem_u32(const void* p) {
    uint32_t a;
    asm("{ .reg .u64 t; cvta.to.shared.u64 t, %1; cvt.u32.u64 %0, t; }" : "=r"(a) : "l"(p));
    return a;
}
__device__ __forceinline__ void cp16(uint32_t s, const void* g) {
    asm volatile("cp.async.cg.shared.global [%0], [%1], 16;" :: "r"(s), "l"(g));
}
__device__ __forceinline__ void ldmx4(uint32_t* r, uint32_t addr) {
    asm volatile("ldmatrix.sync.aligned.m8n8.x4.shared.b16 {%0,%1,%2,%3}, [%4];"
        : "=r"(r[0]), "=r"(r[1]), "=r"(r[2]), "=r"(r[3]) : "r"(addr));
}
__device__ __forceinline__ void ldmx4t(uint32_t* r, uint32_t addr) {
    asm volatile("ldmatrix.sync.aligned.m8n8.x4.trans.shared.b16 {%0,%1,%2,%3}, [%4];"
        : "=r"(r[0]), "=r"(r[1]), "=r"(r[2]), "=r"(r[3]) : "r"(addr));
}
__device__ __forceinline__ void mma16816(float* d, const uint32_t* a, uint32_t b0, uint32_t b1) {
    asm volatile("mma.sync.aligned.m16n8k16.row.col.f32.bf16.bf16.f32 "
        "{%0,%1,%2,%3}, {%4,%5,%6,%7}, {%8,%9}, {%0,%1,%2,%3};"
        : "+f"(d[0]), "+f"(d[1]), "+f"(d[2]), "+f"(d[3])
        : "r"(a[0]), "r"(a[1]), "r"(a[2]), "r"(a[3]), "r"(b0), "r"(b1));
}
__device__ __forceinline__ uint32_t pack_bf16x2(float lo, float hi) {
    uint32_t r;
    asm("cvt.rn.bf16x2.f32 %0, %1, %2;" : "=r"(r) : "f"(hi), "f"(lo));
    return r;
}
#define SWZ8(c, r)  ((c) ^ ((r) & 7))

// ---------------- per-batch valid lengths ----------------
__global__ void lengths_kernel(const int* __restrict__ mask) {
    __shared__ int sd[256];
    int b = blockIdx.x;
    int s = 0;
    for (int i = threadIdx.x; i < TT; i += 256) s += mask[b * TT + i];
    sd[threadIdx.x] = s;
    __syncthreads();
    for (int st = 128; st > 0; st >>= 1) {
        if (threadIdx.x < st) sd[threadIdx.x] += sd[threadIdx.x + st];
        __syncthreads();
    }
    if (threadIdx.x == 0) g_len[b] = sd[0];
}

// ---------------- fp32 -> bf16x3 split conversion ----------------
// A'=[hi,lo,hi] (LOSEG=1), B'=[hi,hi,lo] (LOSEG=2)
template <int LOSEG, int DSTW>
__global__ __launch_bounds__(256) void conv3_kernel(const float* __restrict__ in) {
    __nv_bfloat16* out = DSTW ? g_W3 : g_A3;
    int g = blockIdx.x * 256 + threadIdx.x;        // rows * 512
    int r = g >> 9, c4 = g & 511;
    float4 v = *(const float4*)(in + (size_t)r * DD + c4 * 4);
    union { __nv_bfloat16 b[4]; uint2 u; } hi, lo;
    float vv[4] = {v.x, v.y, v.z, v.w};
#pragma unroll
    for (int i = 0; i < 4; i++) {
        hi.b[i] = __float2bfloat16_rn(vv[i]);
        lo.b[i] = __float2bfloat16_rn(vv[i] - __bfloat162float(hi.b[i]));
    }
    constexpr int HISEG = 3 - LOSEG;
    __nv_bfloat16* o = out + (size_t)r * K3 + c4 * 4;
    *(uint2*)(o)            = hi.u;
    *(uint2*)(o + HISEG*DD) = hi.u;
    *(uint2*)(o + LOSEG*DD) = lo.u;
}

// ---------------- HMMA bf16 GEMM: C[M,N] = A3[M,K3] @ W3[N,K3]^T ----------------
// 128x128 CTA tile, 4 warps, warp tile 64x64 (32 MMA per 8 ldmatrix per k16),
// BK=64/stage, 3-stage cp.async, XOR-swizzled 128B rows, 2 CTAs/SM.
#define GSTAGE 32768
#define SMEM_GEMM_TOTAL (3*GSTAGE)      /* 98304 B */

template <int MODE>
__global__ __launch_bounds__(128, 2) void gemm_mma(float* __restrict__ Cout, int N) {
    extern __shared__ __align__(16) char smraw[];
    const uint32_t sb = smem_u32(smraw);
    const int tid = threadIdx.x;
    const int bm = blockIdx.y * 128, bn = blockIdx.x * 128;
    const int warp = tid >> 5, lane = tid & 31;
    const int wm = warp >> 1, wn = warp & 1;
    const int iters = K3 / 64;                     // 96

    float acc[32][4];
#pragma unroll
    for (int i = 0; i < 32; i++)
#pragma unroll
        for (int j = 0; j < 4; j++) acc[i][j] = 0.f;

    // cp.async addressing: rows step uniformly by 16 => 1 base ptr + imm offsets
    const int r0 = tid >> 3;                       // 0..15
    const int c0 = tid & 7;
    const uint32_t soA0 = r0 * 128 + SWZ8(c0, r0) * 16;
    const uint32_t soB0 = 16384 + soA0;
    const __nv_bfloat16* pA = g_A3 + (size_t)(bm + r0) * K3 + c0 * 8;
    const __nv_bfloat16* pB = g_W3 + (size_t)(bn + r0) * K3 + c0 * 8;

    auto load_stage = [&](uint32_t sbase) {
#pragma unroll
        for (int l = 0; l < 8; l++) {
            cp16(sbase + soA0 + l * 2048, pA + (size_t)l * 16 * K3);
            cp16(sbase + soB0 + l * 2048, pB + (size_t)l * 16 * K3);
        }
        asm volatile("cp.async.commit_group;" ::: "memory");
        pA += 64; pB += 64;
    };

    load_stage(sb);
    load_stage(sb + GSTAGE);

    const int lrow = (lane & 7) + 8 * ((lane >> 3) & 1);
    const int lch  = lane >> 4;
    uint32_t aro[4], bro[4];
#pragma unroll
    for (int mi = 0; mi < 4; mi++) {
        int row = wm * 64 + mi * 16 + lrow;
        aro[mi] = row * 128 + ((row & 7) << 4);
    }
#pragma unroll
    for (int n16 = 0; n16 < 4; n16++) {
        int nr = wn * 64 + n16 * 16 + lrow;
        bro[n16] = 16384 + nr * 128 + ((nr & 7) << 4);
    }

    for (int i = 0; i < iters; i += 3) {
#pragma unroll
        for (int u = 0; u < 3; u++) {
            const int idx = i + u;
            if (idx >= iters - 2) asm volatile("cp.async.wait_group 0;" ::: "memory");
            else                  asm volatile("cp.async.wait_group 1;" ::: "memory");
            __syncthreads();
            if (idx + 2 < iters) load_stage(sb + ((u + 2) % 3) * GSTAGE);

            const uint32_t sa = sb + u * GSTAGE;
#pragma unroll
            for (int ks = 0; ks < 4; ks++) {
                const uint32_t chx = (uint32_t)(ks * 2 + lch) << 4;
                uint32_t a[4][4], b[4][4];
#pragma unroll
                for (int mi = 0; mi < 4; mi++)
                    ldmx4(a[mi], sa + (aro[mi] ^ chx));
#pragma unroll
                for (int n16 = 0; n16 < 4; n16++)
                    ldmx4(b[n16], sa + (bro[n16] ^ chx));
#pragma unroll
                for (int mi = 0; mi < 4; mi++)
#pragma unroll
                    for (int n16 = 0; n16 < 4; n16++) {
                        mma16816(acc[mi * 8 + n16 * 2],     a[mi], b[n16][0], b[n16][2]);
                        mma16816(acc[mi * 8 + n16 * 2 + 1], a[mi], b[n16][1], b[n16][3]);
                    }
            }
        }
    }

    // ---- epilogue ----
    if (MODE == 0) {
        const int which = bn >> 11;                // 0=q 1=k 2=v
        const int h = (bn >> 7) & 15;
        if (which == 2) {
#pragma unroll
            for (int mi = 0; mi < 4; mi++)
#pragma unroll
                for (int nn = 0; nn < 8; nn++) {
                    int d = wn * 64 + (nn >> 1) * 16 + (nn & 1) * 8 + (lane & 3) * 2;
#pragma unroll
                    for (int half = 0; half < 2; half++) {
                        int m = bm + wm * 64 + mi * 16 + (lane >> 2) + half * 8;
                        int b_ = m >> 11, t_ = m & (TT - 1);
                        size_t off = (((size_t)b_ * HH + h) * TT + t_) * HDIM + d;
                        float v0 = acc[mi * 8 + nn][2 * half];
                        float v1 = acc[mi * 8 + nn][2 * half + 1];
                        __nv_bfloat16 h0 = __float2bfloat16_rn(v0);
                        __nv_bfloat16 h1 = __float2bfloat16_rn(v1);
                        union { __nv_bfloat16 b[2]; uint32_t u; } ph, pl;
                        ph.b[0] = h0; ph.b[1] = h1;
                        pl.b[0] = __float2bfloat16_rn(v0 - __bfloat162float(h0));
                        pl.b[1] = __float2bfloat16_rn(v1 - __bfloat162float(h1));
                        *(uint32_t*)&g_vh[off] = ph.u;
                        *(uint32_t*)&g_vl[off] = pl.u;
                    }
                }
        } else {
            float* dst = (which == 0) ? g_q : g_k;
#pragma unroll
            for (int mi = 0; mi < 4; mi++)
#pragma unroll
                for (int nn = 0; nn < 8; nn++) {
                    int d = wn * 64 + (nn >> 1) * 16 + (nn & 1) * 8 + (lane & 3) * 2;
#pragma unroll
                    for (int half = 0; half < 2; half++) {
                        int m = bm + wm * 64 + mi * 16 + (lane >> 2) + half * 8;
                        int b_ = m >> 11, t_ = m & (TT - 1);
                        float2 v2 = make_float2(acc[mi * 8 + nn][2 * half],
                                                acc[mi * 8 + nn][2 * half + 1]);
                        *(float2*)&dst[(((size_t)b_ * HH + h) * TT + t_) * HDIM + d] = v2;
                    }
                }
        }
    } else {
#pragma unroll
        for (int mi = 0; mi < 4; mi++)
#pragma unroll
            for (int nn = 0; nn < 8; nn++) {
                int col = bn + wn * 64 + (nn >> 1) * 16 + (nn & 1) * 8 + (lane & 3) * 2;
#pragma unroll
                for (int half = 0; half < 2; half++) {
                    int m = bm + wm * 64 + mi * 16 + (lane >> 2) + half * 8;
                    float2 v2 = make_float2(acc[mi * 8 + nn][2 * half],
                                            acc[mi * 8 + nn][2 * half + 1]);
                    *(float2*)&Cout[(size_t)m * N + col] = v2;
                }
            }
    }
}

// ---------------- RoPE -> bf16 hi/lo planes for q and k ----------------
__global__ void rope_split_kernel() {
    int idx = blockIdx.x * blockDim.x + threadIdx.x;   // B*H*T*64
    int d  = idx & 63;
    int t  = (idx >> 6) & (TT - 1);
    int bh = idx >> 17;
    size_t base = ((size_t)bh * TT + t) * HDIM;
    float inv = (float)exp(-(double)(2 * d) / 128.0 * 9.210340371976184);
    float ang = (float)t * inv;
    float s, c;
    sincosf(ang, &s, &c);

    float q1 = g_q[base + d], q2 = g_q[base + d + 64];
    float qa = q1 * c - q2 * s, qb = q2 * c + q1 * s;
    float k1 = g_k[base + d], k2 = g_k[base + d + 64];
    float ka = k1 * c - k2 * s, kb = k2 * c + k1 * s;

    __nv_bfloat16 h;
    h = __float2bfloat16_rn(qa); g_qh[base + d] = h;
    g_ql[base + d] = __float2bfloat16_rn(qa - __bfloat162float(h));
    h = __float2bfloat16_rn(qb); g_qh[base + d + 64] = h;
    g_ql[base + d + 64] = __float2bfloat16_rn(qb - __bfloat162float(h));
    h = __float2bfloat16_rn(ka); g_kh[base + d] = h;
    g_kl[base + d] = __float2bfloat16_rn(ka - __bfloat162float(h));
    h = __float2bfloat16_rn(kb); g_kh[base + d + 64] = h;
    g_kl[base + d + 64] = __float2bfloat16_rn(kb - __bfloat162float(h));
}

// ---------------- HMMA flash attention: BQ=128, BKV=64, 8 warps ----------------
#define AQ_OFF   0
#define AKV_OFF  65536
#define AKV_STG  65536
#define SMEM_ATTN_TOTAL (65536 + 2*65536)   /* 196608 */

__global__ __launch_bounds__(256) void attn_mma_kernel() {
    extern __shared__ __align__(16) char smraw[];
    const uint32_t sb = smem_u32(smraw);
    const int tid = threadIdx.x;
    const int warp = tid >> 5, lane = tid & 31;
    const int qt = 15 - blockIdx.x;                 // descending work order
    const int h = blockIdx.y, b = blockIdx.z;
    const int L = g_len[b];
    const size_t bhT = ((size_t)b * HH + h) * TT;

    const int lrow = (lane & 7) + 8 * ((lane >> 3) & 1);
    const int lch  = lane >> 4;

    // ---- load Q tile (both planes), own commit group ----
    {
        const __nv_bfloat16* qp[2];
        qp[0] = g_qh; qp[1] = g_ql;
#pragma unroll
        for (int l = 0; l < 16; l++) {
            int idx = tid + l * 256;                // 4096 chunks
            int pl = idx >> 11, rem = idx & 2047;
            int row = rem >> 4, c = rem & 15;
            cp16(sb + AQ_OFF + pl * 32768 + row * 256 + SWZ8(c, row) * 16,
                 qp[pl] + (bhT + (size_t)qt * 128 + row) * HDIM + c * 8);
        }
        asm volatile("cp.async.commit_group;" ::: "memory");
    }

    const int nt = (min(qt * 128 + 128, L) + 63) / 64;

    auto load_kv = [&](int kt, int stg) {
        const __nv_bfloat16* pp[4];
        pp[0] = g_kh; pp[1] = g_kl; pp[2] = g_vh; pp[3] = g_vl;
        uint32_t base = sb + AKV_OFF + stg * AKV_STG;
#pragma unroll
        for (int l = 0; l < 16; l++) {
            int idx = tid + l * 256;
            int pl = idx >> 10, rem = idx & 1023;
            int row = rem >> 4, c = rem & 15;
            cp16(base + pl * 16384 + row * 256 + SWZ8(c, row) * 16,
                 pp[pl] + (bhT + (size_t)kt * 64 + row) * HDIM + c * 8);
        }
        asm volatile("cp.async.commit_group;" ::: "memory");
    };
    load_kv(0, 0);

    // ---- hoist Q fragments (wait only for the Q group) ----
    uint32_t qhf[8][4], qlf[8][4];
    {
        asm volatile("cp.async.wait_group 1;" ::: "memory");
        __syncthreads();
        const uint32_t qh = sb + AQ_OFF, ql = qh + 32768;
        const int arow = warp * 16 + lrow;
#pragma unroll
        for (int k16 = 0; k16 < 8; k16++) {
            const int ch = k16 * 2 + lch;
            ldmx4(qhf[k16], qh + arow * 256 + SWZ8(ch, arow) * 16);
            ldmx4(qlf[k16], ql + arow * 256 + SWZ8(ch, arow) * 16);
        }
    }

    float oacc[16][4];
#pragma unroll
    for (int i = 0; i < 16; i++)
#pragma unroll
        for (int j = 0; j < 4; j++) oacc[i][j] = 0.f;
    float m0 = -1e30f, m1 = -1e30f, l0 = 0.f, l1 = 0.f;

    const int wr = qt * 128 + warp * 16;
    const float scl = 0.08838834764831843f;

    for (int kt = 0; kt < nt; kt++) {
        asm volatile("cp.async.wait_group 0;" ::: "memory");
        __syncthreads();
        if (kt + 1 < nt) load_kv(kt + 1, (kt + 1) & 1);

        const uint32_t kh = sb + AKV_OFF + (kt & 1) * AKV_STG;
        const uint32_t kl = kh + 16384;
        const uint32_t vh = kh + 32768;
        const uint32_t vl = kh + 49152;

        // ---- S = Qh*Kh + Ql*Kh + Qh*Kl ----
        float sacc[8][4];
#pragma unroll
        for (int i = 0; i < 8; i++)
#pragma unroll
            for (int j = 0; j < 4; j++) sacc[i][j] = 0.f;

#pragma unroll
        for (int k16 = 0; k16 < 8; k16++) {
            const int ch = k16 * 2 + lch;
#pragma unroll
            for (int n16 = 0; n16 < 4; n16++) {
                const int nr = n16 * 16 + lrow;
                uint32_t bh[4], bl[4];
                ldmx4(bh, kh + nr * 256 + SWZ8(ch, nr) * 16);
                mma16816(sacc[2*n16],   qhf[k16], bh[0], bh[2]);
                mma16816(sacc[2*n16+1], qhf[k16], bh[1], bh[3]);
                mma16816(sacc[2*n16],   qlf[k16], bh[0], bh[2]);
                mma16816(sacc[2*n16+1], qlf[k16], bh[1], bh[3]);
                ldmx4(bl, kl + nr * 256 + SWZ8(ch, nr) * 16);
                mma16816(sacc[2*n16],   qhf[k16], bl[0], bl[2]);
                mma16816(sacc[2*n16+1], qhf[k16], bl[1], bl[3]);
            }
        }

        // ---- mask + online softmax ----
        const bool needmask = ((kt + 1) * 64 > qt * 128) || ((kt + 1) * 64 > L);
        const int r0g = wr + (lane >> 2);
#pragma unroll
        for (int f = 0; f < 8; f++)
#pragma unroll
            for (int c = 0; c < 4; c++) {
                float x = sacc[f][c] * scl;
                if (needmask) {
                    int col = kt * 64 + f * 8 + ((lane & 3) << 1) + (c & 1);
                    int rg = r0g + ((c >> 1) << 3);
                    if (col > rg || col >= L) x = -1e30f;
                }
                sacc[f][c] = x;
            }
        float mx0 = -1e30f, mx1 = -1e30f;
#pragma unroll
        for (int f = 0; f < 8; f++) {
            mx0 = fmaxf(mx0, fmaxf(sacc[f][0], sacc[f][1]));
            mx1 = fmaxf(mx1, fmaxf(sacc[f][2], sacc[f][3]));
        }
        mx0 = fmaxf(mx0, __shfl_xor_sync(0xffffffffu, mx0, 1));
        mx0 = fmaxf(mx0, __shfl_xor_sync(0xffffffffu, mx0, 2));
        mx1 = fmaxf(mx1, __shfl_xor_sync(0xffffffffu, mx1, 1));
        mx1 = fmaxf(mx1, __shfl_xor_sync(0xffffffffu, mx1, 2));
        float mn0 = fmaxf(m0, mx0), mn1 = fmaxf(m1, mx1);
        float corr0 = __expf(m0 - mn0), corr1 = __expf(m1 - mn1);
        float sum0 = 0.f, sum1 = 0.f;
#pragma unroll
        for (int f = 0; f < 8; f++) {
            float p;
            p = __expf(sacc[f][0] - mn0); sacc[f][0] = p; sum0 += p;
            p = __expf(sacc[f][1] - mn0); sacc[f][1] = p; sum0 += p;
            p = __expf(sacc[f][2] - mn1); sacc[f][2] = p; sum1 += p;
            p = __expf(sacc[f][3] - mn1); sacc[f][3] = p; sum1 += p;
        }
        sum0 += __shfl_xor_sync(0xffffffffu, sum0, 1);
        sum0 += __shfl_xor_sync(0xffffffffu, sum0, 2);
        sum1 += __shfl_xor_sync(0xffffffffu, sum1, 1);
        sum1 += __shfl_xor_sync(0xffffffffu, sum1, 2);
        l0 = l0 * corr0 + sum0; m0 = mn0;
        l1 = l1 * corr1 + sum1; m1 = mn1;
#pragma unroll
        for (int nf = 0; nf < 16; nf++) {
            oacc[nf][0] *= corr0; oacc[nf][1] *= corr0;
            oacc[nf][2] *= corr1; oacc[nf][3] *= corr1;
        }

        // ---- O += Ph*Vh + Pl*Vh + Ph*Vl ----
#pragma unroll
        for (int j16 = 0; j16 < 4; j16++) {
            const int f0 = 2 * j16, f1 = 2 * j16 + 1;
            uint32_t aPh[4], aPl[4];
            {
                float p00 = sacc[f0][0], p01 = sacc[f0][1];
                float p02 = sacc[f0][2], p03 = sacc[f0][3];
                float p10 = sacc[f1][0], p11 = sacc[f1][1];
                float p12 = sacc[f1][2], p13 = sacc[f1][3];
                aPh[0] = pack_bf16x2(p00, p01);
                aPh[1] = pack_bf16x2(p02, p03);
                aPh[2] = pack_bf16x2(p10, p11);
                aPh[3] = pack_bf16x2(p12, p13);
                union { uint32_t u; __nv_bfloat162 b2; } t;
                float r00, r01, r02, r03, r10, r11, r12, r13;
                t.u = aPh[0]; r00 = p00 - __bfloat162float(t.b2.x); r01 = p01 - __bfloat162float(t.b2.y);
                t.u = aPh[1]; r02 = p02 - __bfloat162float(t.b2.x); r03 = p03 - __bfloat162float(t.b2.y);
                t.u = aPh[2]; r10 = p10 - __bfloat162float(t.b2.x); r11 = p11 - __bfloat162float(t.b2.y);
                t.u = aPh[3]; r12 = p12 - __bfloat162float(t.b2.x); r13 = p13 - __bfloat162float(t.b2.y);
                aPl[0] = pack_bf16x2(r00, r01);
                aPl[1] = pack_bf16x2(r02, r03);
                aPl[2] = pack_bf16x2(r10, r11);
                aPl[3] = pack_bf16x2(r12, r13);
            }
#pragma unroll
            for (int d16 = 0; d16 < 8; d16++) {
                const int ch = d16 * 2 + lch;
                const int vr = j16 * 16 + lrow;
                uint32_t bvh[4], bvl[4];
                ldmx4t(bvh, vh + vr * 256 + SWZ8(ch, vr) * 16);
                mma16816(oacc[2*d16],   aPh, bvh[0], bvh[1]);
                mma16816(oacc[2*d16+1], aPh, bvh[2], bvh[3]);
                mma16816(oacc[2*d16],   aPl, bvh[0], bvh[1]);
                mma16816(oacc[2*d16+1], aPl, bvh[2], bvh[3]);
                ldmx4t(bvl, vl + vr * 256 + SWZ8(ch, vr) * 16);
                mma16816(oacc[2*d16],   aPh, bvl[0], bvl[1]);
                mma16816(oacc[2*d16+1], aPh, bvl[2], bvl[3]);
            }
        }
        __syncthreads();
    }

    // ---- epilogue: write directly into g_A3 bf16x3 [hi|lo|hi] ----
    const float il0 = 1.f / l0, il1 = 1.f / l1;
    const int trow = qt * 128 + warp * 16 + (lane >> 2);
#pragma unroll
    for (int nf = 0; nf < 16; nf++) {
        int col = h * 128 + nf * 8 + (lane & 3) * 2;
#pragma unroll
        for (int half = 0; half < 2; half++) {
            float v0 = oacc[nf][2 * half]     * (half ? il1 : il0);
            float v1 = oacc[nf][2 * half + 1] * (half ? il1 : il0);
            __nv_bfloat16 h0 = __float2bfloat16_rn(v0);
            __nv_bfloat16 h1 = __float2bfloat16_rn(v1);
            union { __nv_bfloat16 b[2]; uint32_t u; } ph, pl;
            ph.b[0] = h0; ph.b[1] = h1;
            pl.b[0] = __float2bfloat16_rn(v0 - __bfloat162float(h0));
            pl.b[1] = __float2bfloat16_rn(v1 - __bfloat162float(h1));
            __nv_bfloat16* row = g_A3 + ((size_t)b * TT + trow + half * 8) * K3;
            *(uint32_t*)&row[col]          = ph.u;
            *(uint32_t*)&row[col + 2*DD]   = ph.u;
            *(uint32_t*)&row[col + DD]     = pl.u;
        }
    }
}

// ---------------- launcher ----------------
extern "C" void kernel_launch(void* const* d_in, const int* in_sizes, int n_in,
                              void* d_out, int out_size) {
    const float* x     = (const float*)d_in[0];
    const float* Wqkv  = (const float*)d_in[1];
    const float* Wproj = (const float*)d_in[2];
    const int*   mask  = (const int*)d_in[3];
    float* out = (float*)d_out;

    cudaFuncSetAttribute(gemm_mma<0>, cudaFuncAttributeMaxDynamicSharedMemorySize, SMEM_GEMM_TOTAL);
    cudaFuncSetAttribute(gemm_mma<1>, cudaFuncAttributeMaxDynamicSharedMemorySize, SMEM_GEMM_TOTAL);
    cudaFuncSetAttribute(attn_mma_kernel, cudaFuncAttributeMaxDynamicSharedMemorySize, SMEM_ATTN_TOTAL);

    lengths_kernel<<<BB, 256>>>(mask);
    conv3_kernel<1, 0><<<MROWS * 2, 256>>>(x);       // x    -> g_A3 [hi,lo,hi]
    conv3_kernel<2, 1><<<K3 * 2, 256>>>(Wqkv);       // Wqkv -> g_W3 [hi,hi,lo]
    gemm_mma<0><<<dim3(K3 / 128, MROWS / 128), 128, SMEM_GEMM_TOTAL>>>(nullptr, K3);
    rope_split_kernel<<<(BB * HH * TT * 64) / 256, 256>>>();
    attn_mma_kernel<<<dim3(16, HH, BB), 256, SMEM_ATTN_TOTAL>>>();
    conv3_kernel<2, 1><<<DD * 2, 256>>>(Wproj);      // Wproj-> g_W3 [hi,hi,lo]
    gemm_mma<1><<<dim3(DD / 128, MROWS / 128), 128, SMEM_GEMM_TOTAL>>>(out, DD);
}

// round 9
// speedup vs baseline: 4.6081x; 1.2953x over previous
#include <cuda_runtime.h>
#include <cuda_bf16.h>
#include <cuda_fp16.h>
#include <cstdint>
#include <math.h>

#define BB 4
#define TT 2048
#define DD 2048
#define HH 16
#define HDIM 128
#define MROWS (BB*TT)       /* 8192 */
#define K2 (2*DD)           /* 4096: fp16x2 split GEMM contraction */
#define PLANE_ELEMS ((size_t)BB*HH*TT*HDIM)   /* 16.8M */

// ---------------- scratch (device globals; uint4-backed => 16B align) ----------
__device__ uint4 g_q_raw  [PLANE_ELEMS/4];               // fp32 (B,H,T,hd)
__device__ uint4 g_k_raw  [PLANE_ELEMS/4];
__device__ uint4 g_A2_raw [(size_t)MROWS*K2/8];          // fp16 [ah|al] activations
__device__ uint4 g_W2_raw [(size_t)(3*DD)*K2/8];         // fp16 [wh|wh] weights
__device__ uint4 g_qh_raw [PLANE_ELEMS/8];               // bf16 planes (attention)
__device__ uint4 g_ql_raw [PLANE_ELEMS/8];
__device__ uint4 g_kh_raw [PLANE_ELEMS/8];
__device__ uint4 g_kl_raw [PLANE_ELEMS/8];
__device__ uint4 g_vh_raw [PLANE_ELEMS/8];
__device__ uint4 g_vl_raw [PLANE_ELEMS/8];
__device__ int   g_len[BB];

// device-code-only views (never use in host code / kernel args)
#define g_q   ((float*)g_q_raw)
#define g_k   ((float*)g_k_raw)
#define g_A2  ((__half*)g_A2_raw)
#define g_W2  ((__half*)g_W2_raw)
#define g_qh  ((__nv_bfloat16*)g_qh_raw)
#define g_ql  ((__nv_bfloat16*)g_ql_raw)
#define g_kh  ((__nv_bfloat16*)g_kh_raw)
#define g_kl  ((__nv_bfloat16*)g_kl_raw)
#define g_vh  ((__nv_bfloat16*)g_vh_raw)
#define g_vl  ((__nv_bfloat16*)g_vl_raw)

// ============================ helpers ============================
__device__ __forceinline__ uint32_t smem_u32(const void* p) {
    uint32_t a;
    asm("{ .reg .u64 t; cvta.to.shared.u64 t, %1; cvt.u32.u64 %0, t; }" : "=r"(a) : "l"(p));
    return a;
}
__device__ __forceinline__ void cp16(uint32_t s, const void* g) {
    asm volatile("cp.async.cg.shared.global [%0], [%1], 16;" :: "r"(s), "l"(g));
}
__device__ __forceinline__ void ldmx4(uint32_t* r, uint32_t addr) {
    asm volatile("ldmatrix.sync.aligned.m8n8.x4.shared.b16 {%0,%1,%2,%3}, [%4];"
        : "=r"(r[0]), "=r"(r[1]), "=r"(r[2]), "=r"(r[3]) : "r"(addr));
}
__device__ __forceinline__ void ldmx4t(uint32_t* r, uint32_t addr) {
    asm volatile("ldmatrix.sync.aligned.m8n8.x4.trans.shared.b16 {%0,%1,%2,%3}, [%4];"
        : "=r"(r[0]), "=r"(r[1]), "=r"(r[2]), "=r"(r[3]) : "r"(addr));
}
// bf16 MMA (attention)
__device__ __forceinline__ void mma16816(float* d, const uint32_t* a, uint32_t b0, uint32_t b1) {
    asm volatile("mma.sync.aligned.m16n8k16.row.col.f32.bf16.bf16.f32 "
        "{%0,%1,%2,%3}, {%4,%5,%6,%7}, {%8,%9}, {%0,%1,%2,%3};"
        : "+f"(d[0]), "+f"(d[1]), "+f"(d[2]), "+f"(d[3])
        : "r"(a[0]), "r"(a[1]), "r"(a[2]), "r"(a[3]), "r"(b0), "r"(b1));
}
// fp16 MMA (GEMMs)
__device__ __forceinline__ void mma16816h(float* d, const uint32_t* a, uint32_t b0, uint32_t b1) {
    asm volatile("mma.sync.aligned.m16n8k16.row.col.f32.f16.f16.f32 "
        "{%0,%1,%2,%3}, {%4,%5,%6,%7}, {%8,%9}, {%0,%1,%2,%3};"
        : "+f"(d[0]), "+f"(d[1]), "+f"(d[2]), "+f"(d[3])
        : "r"(a[0]), "r"(a[1]), "r"(a[2]), "r"(a[3]), "r"(b0), "r"(b1));
}
__device__ __forceinline__ uint32_t pack_bf16x2(float lo, float hi) {
    uint32_t r;
    asm("cvt.rn.bf16x2.f32 %0, %1, %2;" : "=r"(r) : "f"(hi), "f"(lo));
    return r;
}
#define SWZ8(c, r)  ((c) ^ ((r) & 7))

// ---------------- per-batch valid lengths ----------------
__global__ void lengths_kernel(const int* __restrict__ mask) {
    __shared__ int sd[256];
    int b = blockIdx.x;
    int s = 0;
    for (int i = threadIdx.x; i < TT; i += 256) s += mask[b * TT + i];
    sd[threadIdx.x] = s;
    __syncthreads();
    for (int st = 128; st > 0; st >>= 1) {
        if (threadIdx.x < st) sd[threadIdx.x] += sd[threadIdx.x + st];
        __syncthreads();
    }
    if (threadIdx.x == 0) g_len[b] = sd[0];
}

// ---------------- fp32 -> fp16x2 split conversion ----------------
// Activations (ISW=0): [ah | al], ah+al == a (to 22 bits) => A'.W' = a.wh EXACT.
// Weights (ISW=1):     [wh | wh] duplicated.
template <int ISW, int DSTW>
__global__ __launch_bounds__(256) void conv2_kernel(const float* __restrict__ in) {
    __half* out = DSTW ? g_W2 : g_A2;
    int g = blockIdx.x * 256 + threadIdx.x;        // rows * 512
    int r = g >> 9, c4 = g & 511;
    float4 v = *(const float4*)(in + (size_t)r * DD + c4 * 4);
    union { __half b[4]; uint2 u; } hi, lo;
    float vv[4] = {v.x, v.y, v.z, v.w};
#pragma unroll
    for (int i = 0; i < 4; i++) {
        hi.b[i] = __float2half_rn(vv[i]);
        lo.b[i] = ISW ? hi.b[i] : __float2half_rn(vv[i] - __half2float(hi.b[i]));
    }
    __half* o = out + (size_t)r * K2 + c4 * 4;
    *(uint2*)(o)      = hi.u;
    *(uint2*)(o + DD) = lo.u;
}

// ---------------- HMMA fp16 GEMM: C[M,N] = A2[M,K2] @ W2[N,K2]^T ----------------
// 128x128 CTA tile, 4 warps, warp tile 64x64, BK=64/stage, 3-stage cp.async.
#define GSTAGE 32768
#define SMEM_GEMM_TOTAL (3*GSTAGE)      /* 98304 B */

template <int MODE>
__global__ __launch_bounds__(128, 2) void gemm_mma(float* __restrict__ Cout, int N) {
    extern __shared__ __align__(16) char smraw[];
    const uint32_t sb = smem_u32(smraw);
    const int tid = threadIdx.x;
    const int bm = blockIdx.y * 128, bn = blockIdx.x * 128;
    const int warp = tid >> 5, lane = tid & 31;
    const int wm = warp >> 1, wn = warp & 1;
    const int iters = K2 / 64;                     // 64

    float acc[32][4];
#pragma unroll
    for (int i = 0; i < 32; i++)
#pragma unroll
        for (int j = 0; j < 4; j++) acc[i][j] = 0.f;

    const int r0 = tid >> 3;                       // 0..15
    const int c0 = tid & 7;
    const uint32_t soA0 = r0 * 128 + SWZ8(c0, r0) * 16;
    const uint32_t soB0 = 16384 + soA0;
    const __half* pA = g_A2 + (size_t)(bm + r0) * K2 + c0 * 8;
    const __half* pB = g_W2 + (size_t)(bn + r0) * K2 + c0 * 8;

    auto load_stage = [&](uint32_t sbase) {
#pragma unroll
        for (int l = 0; l < 8; l++) {
            cp16(sbase + soA0 + l * 2048, pA + (size_t)l * 16 * K2);
            cp16(sbase + soB0 + l * 2048, pB + (size_t)l * 16 * K2);
        }
        asm volatile("cp.async.commit_group;" ::: "memory");
        pA += 64; pB += 64;
    };

    load_stage(sb);
    load_stage(sb + GSTAGE);

    const int lrow = (lane & 7) + 8 * ((lane >> 3) & 1);
    const int lch  = lane >> 4;
    uint32_t aro[4], bro[4];
#pragma unroll
    for (int mi = 0; mi < 4; mi++) {
        int row = wm * 64 + mi * 16 + lrow;
        aro[mi] = row * 128 + ((row & 7) << 4);
    }
#pragma unroll
    for (int n16 = 0; n16 < 4; n16++) {
        int nr = wn * 64 + n16 * 16 + lrow;
        bro[n16] = 16384 + nr * 128 + ((nr & 7) << 4);
    }

    for (int i = 0; i < iters; i += 3) {
#pragma unroll
        for (int u = 0; u < 3; u++) {
            const int idx = i + u;
            if (idx >= iters) break;
            if (idx >= iters - 2) asm volatile("cp.async.wait_group 0;" ::: "memory");
            else                  asm volatile("cp.async.wait_group 1;" ::: "memory");
            __syncthreads();
            if (idx + 2 < iters) load_stage(sb + ((u + 2) % 3) * GSTAGE);

            const uint32_t sa = sb + u * GSTAGE;
#pragma unroll
            for (int ks = 0; ks < 4; ks++) {
                const uint32_t chx = (uint32_t)(ks * 2 + lch) << 4;
                uint32_t a[4][4], b[4][4];
#pragma unroll
                for (int mi = 0; mi < 4; mi++)
                    ldmx4(a[mi], sa + (aro[mi] ^ chx));
#pragma unroll
                for (int n16 = 0; n16 < 4; n16++)
                    ldmx4(b[n16], sa + (bro[n16] ^ chx));
#pragma unroll
                for (int mi = 0; mi < 4; mi++)
#pragma unroll
                    for (int n16 = 0; n16 < 4; n16++) {
                        mma16816h(acc[mi * 8 + n16 * 2],     a[mi], b[n16][0], b[n16][2]);
                        mma16816h(acc[mi * 8 + n16 * 2 + 1], a[mi], b[n16][1], b[n16][3]);
                    }
            }
        }
    }

    // ---- epilogue ----
    if (MODE == 0) {
        const int which = bn >> 11;                // 0=q 1=k 2=v
        const int h = (bn >> 7) & 15;
        if (which == 2) {
#pragma unroll
            for (int mi = 0; mi < 4; mi++)
#pragma unroll
                for (int nn = 0; nn < 8; nn++) {
                    int d = wn * 64 + (nn >> 1) * 16 + (nn & 1) * 8 + (lane & 3) * 2;
#pragma unroll
                    for (int half = 0; half < 2; half++) {
                        int m = bm + wm * 64 + mi * 16 + (lane >> 2) + half * 8;
                        int b_ = m >> 11, t_ = m & (TT - 1);
                        size_t off = (((size_t)b_ * HH + h) * TT + t_) * HDIM + d;
                        float v0 = acc[mi * 8 + nn][2 * half];
                        float v1 = acc[mi * 8 + nn][2 * half + 1];
                        __nv_bfloat16 h0 = __float2bfloat16_rn(v0);
                        __nv_bfloat16 h1 = __float2bfloat16_rn(v1);
                        union { __nv_bfloat16 b[2]; uint32_t u; } ph, pl;
                        ph.b[0] = h0; ph.b[1] = h1;
                        pl.b[0] = __float2bfloat16_rn(v0 - __bfloat162float(h0));
                        pl.b[1] = __float2bfloat16_rn(v1 - __bfloat162float(h1));
                        *(uint32_t*)&g_vh[off] = ph.u;
                        *(uint32_t*)&g_vl[off] = pl.u;
                    }
                }
        } else {
            float* dst = (which == 0) ? g_q : g_k;
#pragma unroll
            for (int mi = 0; mi < 4; mi++)
#pragma unroll
                for (int nn = 0; nn < 8; nn++) {
                    int d = wn * 64 + (nn >> 1) * 16 + (nn & 1) * 8 + (lane & 3) * 2;
#pragma unroll
                    for (int half = 0; half < 2; half++) {
                        int m = bm + wm * 64 + mi * 16 + (lane >> 2) + half * 8;
                        int b_ = m >> 11, t_ = m & (TT - 1);
                        float2 v2 = make_float2(acc[mi * 8 + nn][2 * half],
                                                acc[mi * 8 + nn][2 * half + 1]);
                        *(float2*)&dst[(((size_t)b_ * HH + h) * TT + t_) * HDIM + d] = v2;
                    }
                }
        }
    } else {
#pragma unroll
        for (int mi = 0; mi < 4; mi++)
#pragma unroll
            for (int nn = 0; nn < 8; nn++) {
                int col = bn + wn * 64 + (nn >> 1) * 16 + (nn & 1) * 8 + (lane & 3) * 2;
#pragma unroll
                for (int half = 0; half < 2; half++) {
                    int m = bm + wm * 64 + mi * 16 + (lane >> 2) + half * 8;
                    float2 v2 = make_float2(acc[mi * 8 + nn][2 * half],
                                            acc[mi * 8 + nn][2 * half + 1]);
                    *(float2*)&Cout[(size_t)m * N + col] = v2;
                }
            }
    }
}

// ---------------- RoPE -> bf16 hi/lo planes for q and k ----------------
__global__ void rope_split_kernel() {
    int idx = blockIdx.x * blockDim.x + threadIdx.x;   // B*H*T*64
    int d  = idx & 63;
    int t  = (idx >> 6) & (TT - 1);
    int bh = idx >> 17;
    size_t base = ((size_t)bh * TT + t) * HDIM;
    float inv = (float)exp(-(double)(2 * d) / 128.0 * 9.210340371976184);
    float ang = (float)t * inv;
    float s, c;
    sincosf(ang, &s, &c);

    float q1 = g_q[base + d], q2 = g_q[base + d + 64];
    float qa = q1 * c - q2 * s, qb = q2 * c + q1 * s;
    float k1 = g_k[base + d], k2 = g_k[base + d + 64];
    float ka = k1 * c - k2 * s, kb = k2 * c + k1 * s;

    __nv_bfloat16 h;
    h = __float2bfloat16_rn(qa); g_qh[base + d] = h;
    g_ql[base + d] = __float2bfloat16_rn(qa - __bfloat162float(h));
    h = __float2bfloat16_rn(qb); g_qh[base + d + 64] = h;
    g_ql[base + d + 64] = __float2bfloat16_rn(qb - __bfloat162float(h));
    h = __float2bfloat16_rn(ka); g_kh[base + d] = h;
    g_kl[base + d] = __float2bfloat16_rn(ka - __bfloat162float(h));
    h = __float2bfloat16_rn(kb); g_kh[base + d + 64] = h;
    g_kl[base + d + 64] = __float2bfloat16_rn(kb - __bfloat162float(h));
}

// ---------------- HMMA flash attention: BQ=128, BKV=64, 8 warps (bf16x3) ------
#define AQ_OFF   0
#define AKV_OFF  65536
#define AKV_STG  65536
#define SMEM_ATTN_TOTAL (65536 + 2*65536)   /* 196608 */

__global__ __launch_bounds__(256) void attn_mma_kernel() {
    extern __shared__ __align__(16) char smraw[];
    const uint32_t sb = smem_u32(smraw);
    const int tid = threadIdx.x;
    const int warp = tid >> 5, lane = tid & 31;
    const int qt = 15 - blockIdx.x;                 // descending work order
    const int h = blockIdx.y, b = blockIdx.z;
    const int L = g_len[b];
    const size_t bhT = ((size_t)b * HH + h) * TT;

    const int lrow = (lane & 7) + 8 * ((lane >> 3) & 1);
    const int lch  = lane >> 4;

    // ---- load Q tile (both planes), own commit group ----
    {
        const __nv_bfloat16* qp[2];
        qp[0] = g_qh; qp[1] = g_ql;
#pragma unroll
        for (int l = 0; l < 16; l++) {
            int idx = tid + l * 256;                // 4096 chunks
            int pl = idx >> 11, rem = idx & 2047;
            int row = rem >> 4, c = rem & 15;
            cp16(sb + AQ_OFF + pl * 32768 + row * 256 + SWZ8(c, row) * 16,
                 qp[pl] + (bhT + (size_t)qt * 128 + row) * HDIM + c * 8);
        }
        asm volatile("cp.async.commit_group;" ::: "memory");
    }

    const int nt = (min(qt * 128 + 128, L) + 63) / 64;

    auto load_kv = [&](int kt, int stg) {
        const __nv_bfloat16* pp[4];
        pp[0] = g_kh; pp[1] = g_kl; pp[2] = g_vh; pp[3] = g_vl;
        uint32_t base = sb + AKV_OFF + stg * AKV_STG;
#pragma unroll
        for (int l = 0; l < 16; l++) {
            int idx = tid + l * 256;
            int pl = idx >> 10, rem = idx & 1023;
            int row = rem >> 4, c = rem & 15;
            cp16(base + pl * 16384 + row * 256 + SWZ8(c, row) * 16,
                 pp[pl] + (bhT + (size_t)kt * 64 + row) * HDIM + c * 8);
        }
        asm volatile("cp.async.commit_group;" ::: "memory");
    };
    load_kv(0, 0);

    // ---- hoist Q fragments (wait only for the Q group) ----
    uint32_t qhf[8][4], qlf[8][4];
    {
        asm volatile("cp.async.wait_group 1;" ::: "memory");
        __syncthreads();
        const uint32_t qh = sb + AQ_OFF, ql = qh + 32768;
        const int arow = warp * 16 + lrow;
#pragma unroll
        for (int k16 = 0; k16 < 8; k16++) {
            const int ch = k16 * 2 + lch;
            ldmx4(qhf[k16], qh + arow * 256 + SWZ8(ch, arow) * 16);
            ldmx4(qlf[k16], ql + arow * 256 + SWZ8(ch, arow) * 16);
        }
    }

    float oacc[16][4];
#pragma unroll
    for (int i = 0; i < 16; i++)
#pragma unroll
        for (int j = 0; j < 4; j++) oacc[i][j] = 0.f;
    float m0 = -1e30f, m1 = -1e30f, l0 = 0.f, l1 = 0.f;

    const int wr = qt * 128 + warp * 16;
    const float scl = 0.08838834764831843f;

    for (int kt = 0; kt < nt; kt++) {
        asm volatile("cp.async.wait_group 0;" ::: "memory");
        __syncthreads();
        if (kt + 1 < nt) load_kv(kt + 1, (kt + 1) & 1);

        const uint32_t kh = sb + AKV_OFF + (kt & 1) * AKV_STG;
        const uint32_t kl = kh + 16384;
        const uint32_t vh = kh + 32768;
        const uint32_t vl = kh + 49152;

        // ---- S = Qh*Kh + Ql*Kh + Qh*Kl ----
        float sacc[8][4];
#pragma unroll
        for (int i = 0; i < 8; i++)
#pragma unroll
            for (int j = 0; j < 4; j++) sacc[i][j] = 0.f;

#pragma unroll
        for (int k16 = 0; k16 < 8; k16++) {
            const int ch = k16 * 2 + lch;
#pragma unroll
            for (int n16 = 0; n16 < 4; n16++) {
                const int nr = n16 * 16 + lrow;
                uint32_t bh[4], bl[4];
                ldmx4(bh, kh + nr * 256 + SWZ8(ch, nr) * 16);
                mma16816(sacc[2*n16],   qhf[k16], bh[0], bh[2]);
                mma16816(sacc[2*n16+1], qhf[k16], bh[1], bh[3]);
                mma16816(sacc[2*n16],   qlf[k16], bh[0], bh[2]);
                mma16816(sacc[2*n16+1], qlf[k16], bh[1], bh[3]);
                ldmx4(bl, kl + nr * 256 + SWZ8(ch, nr) * 16);
                mma16816(sacc[2*n16],   qhf[k16], bl[0], bl[2]);
                mma16816(sacc[2*n16+1], qhf[k16], bl[1], bl[3]);
            }
        }

        // ---- mask + online softmax ----
        const bool needmask = ((kt + 1) * 64 > qt * 128) || ((kt + 1) * 64 > L);
        const int r0g = wr + (lane >> 2);
#pragma unroll
        for (int f = 0; f < 8; f++)
#pragma unroll
            for (int c = 0; c < 4; c++) {
                float x = sacc[f][c] * scl;
                if (needmask) {
                    int col = kt * 64 + f * 8 + ((lane & 3) << 1) + (c & 1);
                    int rg = r0g + ((c >> 1) << 3);
                    if (col > rg || col >= L) x = -1e30f;
                }
                sacc[f][c] = x;
            }
        float mx0 = -1e30f, mx1 = -1e30f;
#pragma unroll
        for (int f = 0; f < 8; f++) {
            mx0 = fmaxf(mx0, fmaxf(sacc[f][0], sacc[f][1]));
            mx1 = fmaxf(mx1, fmaxf(sacc[f][2], sacc[f][3]));
        }
        mx0 = fmaxf(mx0, __shfl_xor_sync(0xffffffffu, mx0, 1));
        mx0 = fmaxf(mx0, __shfl_xor_sync(0xffffffffu, mx0, 2));
        mx1 = fmaxf(mx1, __shfl_xor_sync(0xffffffffu, mx1, 1));
        mx1 = fmaxf(mx1, __shfl_xor_sync(0xffffffffu, mx1, 2));
        float mn0 = fmaxf(m0, mx0), mn1 = fmaxf(m1, mx1);
        float corr0 = __expf(m0 - mn0), corr1 = __expf(m1 - mn1);
        float sum0 = 0.f, sum1 = 0.f;
#pragma unroll
        for (int f = 0; f < 8; f++) {
            float p;
            p = __expf(sacc[f][0] - mn0); sacc[f][0] = p; sum0 += p;
            p = __expf(sacc[f][1] - mn0); sacc[f][1] = p; sum0 += p;
            p = __expf(sacc[f][2] - mn1); sacc[f][2] = p; sum1 += p;
            p = __expf(sacc[f][3] - mn1); sacc[f][3] = p; sum1 += p;
        }
        sum0 += __shfl_xor_sync(0xffffffffu, sum0, 1);
        sum0 += __shfl_xor_sync(0xffffffffu, sum0, 2);
        sum1 += __shfl_xor_sync(0xffffffffu, sum1, 1);
        sum1 += __shfl_xor_sync(0xffffffffu, sum1, 2);
        l0 = l0 * corr0 + sum0; m0 = mn0;
        l1 = l1 * corr1 + sum1; m1 = mn1;
#pragma unroll
        for (int nf = 0; nf < 16; nf++) {
            oacc[nf][0] *= corr0; oacc[nf][1] *= corr0;
            oacc[nf][2] *= corr1; oacc[nf][3] *= corr1;
        }

        // ---- O += Ph*Vh + Pl*Vh + Ph*Vl ----
#pragma unroll
        for (int j16 = 0; j16 < 4; j16++) {
            const int f0 = 2 * j16, f1 = 2 * j16 + 1;
            uint32_t aPh[4], aPl[4];
            {
                float p00 = sacc[f0][0], p01 = sacc[f0][1];
                float p02 = sacc[f0][2], p03 = sacc[f0][3];
                float p10 = sacc[f1][0], p11 = sacc[f1][1];
                float p12 = sacc[f1][2], p13 = sacc[f1][3];
                aPh[0] = pack_bf16x2(p00, p01);
                aPh[1] = pack_bf16x2(p02, p03);
                aPh[2] = pack_bf16x2(p10, p11);
                aPh[3] = pack_bf16x2(p12, p13);
                union { uint32_t u; __nv_bfloat162 b2; } t;
                float r00, r01, r02, r03, r10, r11, r12, r13;
                t.u = aPh[0]; r00 = p00 - __bfloat162float(t.b2.x); r01 = p01 - __bfloat162float(t.b2.y);
                t.u = aPh[1]; r02 = p02 - __bfloat162float(t.b2.x); r03 = p03 - __bfloat162float(t.b2.y);
                t.u = aPh[2]; r10 = p10 - __bfloat162float(t.b2.x); r11 = p11 - __bfloat162float(t.b2.y);
                t.u = aPh[3]; r12 = p12 - __bfloat162float(t.b2.x); r13 = p13 - __bfloat162float(t.b2.y);
                aPl[0] = pack_bf16x2(r00, r01);
                aPl[1] = pack_bf16x2(r02, r03);
                aPl[2] = pack_bf16x2(r10, r11);
                aPl[3] = pack_bf16x2(r12, r13);
            }
#pragma unroll
            for (int d16 = 0; d16 < 8; d16++) {
                const int ch = d16 * 2 + lch;
                const int vr = j16 * 16 + lrow;
                uint32_t bvh[4], bvl[4];
                ldmx4t(bvh, vh + vr * 256 + SWZ8(ch, vr) * 16);
                mma16816(oacc[2*d16],   aPh, bvh[0], bvh[1]);
                mma16816(oacc[2*d16+1], aPh, bvh[2], bvh[3]);
                mma16816(oacc[2*d16],   aPl, bvh[0], bvh[1]);
                mma16816(oacc[2*d16+1], aPl, bvh[2], bvh[3]);
                ldmx4t(bvl, vl + vr * 256 + SWZ8(ch, vr) * 16);
                mma16816(oacc[2*d16],   aPh, bvl[0], bvl[1]);
                mma16816(oacc[2*d16+1], aPh, bvl[2], bvl[3]);
            }
        }
        __syncthreads();
    }

    // ---- epilogue: write directly into g_A2 fp16 [ah|al] ----
    const float il0 = 1.f / l0, il1 = 1.f / l1;
    const int trow = qt * 128 + warp * 16 + (lane >> 2);
#pragma unroll
    for (int nf = 0; nf < 16; nf++) {
        int col = h * 128 + nf * 8 + (lane & 3) * 2;
#pragma unroll
        for (int half = 0; half < 2; half++) {
            float v0 = oacc[nf][2 * half]     * (half ? il1 : il0);
            float v1 = oacc[nf][2 * half + 1] * (half ? il1 : il0);
            __half h0 = __float2half_rn(v0);
            __half h1 = __float2half_rn(v1);
            union { __half b[2]; uint32_t u; } ph, pl;
            ph.b[0] = h0; ph.b[1] = h1;
            pl.b[0] = __float2half_rn(v0 - __half2float(h0));
            pl.b[1] = __float2half_rn(v1 - __half2float(h1));
            __half* row = g_A2 + ((size_t)b * TT + trow + half * 8) * K2;
            *(uint32_t*)&row[col]      = ph.u;
            *(uint32_t*)&row[col + DD] = pl.u;
        }
    }
}

// ---------------- launcher ----------------
extern "C" void kernel_launch(void* const* d_in, const int* in_sizes, int n_in,
                              void* d_out, int out_size) {
    const float* x     = (const float*)d_in[0];
    const float* Wqkv  = (const float*)d_in[1];
    const float* Wproj = (const float*)d_in[2];
    const int*   mask  = (const int*)d_in[3];
    float* out = (float*)d_out;

    cudaFuncSetAttribute(gemm_mma<0>, cudaFuncAttributeMaxDynamicSharedMemorySize, SMEM_GEMM_TOTAL);
    cudaFuncSetAttribute(gemm_mma<1>, cudaFuncAttributeMaxDynamicSharedMemorySize, SMEM_GEMM_TOTAL);
    cudaFuncSetAttribute(attn_mma_kernel, cudaFuncAttributeMaxDynamicSharedMemorySize, SMEM_ATTN_TOTAL);

    lengths_kernel<<<BB, 256>>>(mask);
    conv2_kernel<0, 0><<<MROWS * 2, 256>>>(x);         // x    -> g_A2 [ah|al]
    conv2_kernel<1, 1><<<(3 * DD) * 2, 256>>>(Wqkv);   // Wqkv -> g_W2 [wh|wh]
    gemm_mma<0><<<dim3(3 * DD / 128, MROWS / 128), 128, SMEM_GEMM_TOTAL>>>(nullptr, 3 * DD);
    rope_split_kernel<<<(BB * HH * TT * 64) / 256, 256>>>();
    attn_mma_kernel<<<dim3(16, HH, BB), 256, SMEM_ATTN_TOTAL>>>();
    conv2_kernel<1, 1><<<DD * 2, 256>>>(Wproj);        // Wproj-> g_W2 [wh|wh]
    gemm_mma<1><<<dim3(DD / 128, MROWS / 128), 128, SMEM_GEMM_TOTAL>>>(out, DD);
}

// round 10
// speedup vs baseline: 5.6096x; 1.2173x over previous
#include <cuda_runtime.h>
#include <cuda_bf16.h>
#include <cuda_fp16.h>
#include <cstdint>
#include <math.h>

#define BB 4
#define TT 2048
#define DD 2048
#define HH 16
#define HDIM 128
#define MROWS (BB*TT)       /* 8192 */
#define K2 (2*DD)           /* 4096: fp16x2 split GEMM contraction */
#define PLANE_ELEMS ((size_t)BB*HH*TT*HDIM)   /* 16.8M */

// ---------------- scratch (device globals; uint4-backed => 16B align) ----------
__device__ uint4 g_q_raw  [PLANE_ELEMS/4];               // fp32 (B,H,T,hd)
__device__ uint4 g_k_raw  [PLANE_ELEMS/4];
__device__ uint4 g_A2_raw [(size_t)MROWS*K2/8];          // fp16 [ah|al] activations
__device__ uint4 g_W2_raw [(size_t)(3*DD)*K2/8];         // fp16 [wh|wh] weights
__device__ uint4 g_qh_raw [PLANE_ELEMS/8];               // bf16 planes (attention)
__device__ uint4 g_ql_raw [PLANE_ELEMS/8];
__device__ uint4 g_kh_raw [PLANE_ELEMS/8];
__device__ uint4 g_kl_raw [PLANE_ELEMS/8];
__device__ uint4 g_vh_raw [PLANE_ELEMS/8];
__device__ uint4 g_vl_raw [PLANE_ELEMS/8];
__device__ float g_sin[TT*64];
__device__ float g_cos[TT*64];
__device__ int   g_len[BB];

// device-code-only views (never use in host code / kernel args)
#define g_q   ((float*)g_q_raw)
#define g_k   ((float*)g_k_raw)
#define g_A2  ((__half*)g_A2_raw)
#define g_W2  ((__half*)g_W2_raw)
#define g_qh  ((__nv_bfloat16*)g_qh_raw)
#define g_ql  ((__nv_bfloat16*)g_ql_raw)
#define g_kh  ((__nv_bfloat16*)g_kh_raw)
#define g_kl  ((__nv_bfloat16*)g_kl_raw)
#define g_vh  ((__nv_bfloat16*)g_vh_raw)
#define g_vl  ((__nv_bfloat16*)g_vl_raw)

// ============================ helpers ============================
__device__ __forceinline__ uint32_t smem_u32(const void* p) {
    uint32_t a;
    asm("{ .reg .u64 t; cvta.to.shared.u64 t, %1; cvt.u32.u64 %0, t; }" : "=r"(a) : "l"(p));
    return a;
}
__device__ __forceinline__ void cp16(uint32_t s, const void* g) {
    asm volatile("cp.async.cg.shared.global [%0], [%1], 16;" :: "r"(s), "l"(g));
}
__device__ __forceinline__ void ldmx4(uint32_t* r, uint32_t addr) {
    asm volatile("ldmatrix.sync.aligned.m8n8.x4.shared.b16 {%0,%1,%2,%3}, [%4];"
        : "=r"(r[0]), "=r"(r[1]), "=r"(r[2]), "=r"(r[3]) : "r"(addr));
}
__device__ __forceinline__ void ldmx4t(uint32_t* r, uint32_t addr) {
    asm volatile("ldmatrix.sync.aligned.m8n8.x4.trans.shared.b16 {%0,%1,%2,%3}, [%4];"
        : "=r"(r[0]), "=r"(r[1]), "=r"(r[2]), "=r"(r[3]) : "r"(addr));
}
// bf16 MMA (attention)
__device__ __forceinline__ void mma16816(float* d, const uint32_t* a, uint32_t b0, uint32_t b1) {
    asm volatile("mma.sync.aligned.m16n8k16.row.col.f32.bf16.bf16.f32 "
        "{%0,%1,%2,%3}, {%4,%5,%6,%7}, {%8,%9}, {%0,%1,%2,%3};"
        : "+f"(d[0]), "+f"(d[1]), "+f"(d[2]), "+f"(d[3])
        : "r"(a[0]), "r"(a[1]), "r"(a[2]), "r"(a[3]), "r"(b0), "r"(b1));
}
// fp16 MMA (GEMMs)
__device__ __forceinline__ void mma16816h(float* d, const uint32_t* a, uint32_t b0, uint32_t b1) {
    asm volatile("mma.sync.aligned.m16n8k16.row.col.f32.f16.f16.f32 "
        "{%0,%1,%2,%3}, {%4,%5,%6,%7}, {%8,%9}, {%0,%1,%2,%3};"
        : "+f"(d[0]), "+f"(d[1]), "+f"(d[2]), "+f"(d[3])
        : "r"(a[0]), "r"(a[1]), "r"(a[2]), "r"(a[3]), "r"(b0), "r"(b1));
}
__device__ __forceinline__ uint32_t pack_bf16x2(float lo, float hi) {
    uint32_t r;
    asm("cvt.rn.bf16x2.f32 %0, %1, %2;" : "=r"(r) : "f"(hi), "f"(lo));
    return r;
}
#define SWZ8(c, r)  ((c) ^ ((r) & 7))

// ---------------- per-batch valid lengths ----------------
__global__ void lengths_kernel(const int* __restrict__ mask) {
    __shared__ int sd[256];
    int b = blockIdx.x;
    int s = 0;
    for (int i = threadIdx.x; i < TT; i += 256) s += mask[b * TT + i];
    sd[threadIdx.x] = s;
    __syncthreads();
    for (int st = 128; st > 0; st >>= 1) {
        if (threadIdx.x < st) sd[threadIdx.x] += sd[threadIdx.x + st];
        __syncthreads();
    }
    if (threadIdx.x == 0) g_len[b] = sd[0];
}

// ---------------- RoPE sin/cos table (same numerics as before) ----------------
__global__ void sctab_kernel() {
    int idx = blockIdx.x * 256 + threadIdx.x;      // TT*64
    int d = idx & 63, t = idx >> 6;
    float inv = (float)exp(-(double)(2 * d) / 128.0 * 9.210340371976184);
    float ang = (float)t * inv;
    float s, c;
    sincosf(ang, &s, &c);
    g_sin[idx] = s;
    g_cos[idx] = c;
}

// ---------------- fp32 -> fp16x2 split conversion ----------------
// Activations (ISW=0): [ah | al], ah+al == a (to 22 bits) => A'.W' = a.wh EXACT.
// Weights (ISW=1):     [wh | wh] duplicated.
template <int ISW, int DSTW>
__global__ __launch_bounds__(256) void conv2_kernel(const float* __restrict__ in) {
    __half* out = DSTW ? g_W2 : g_A2;
    int g = blockIdx.x * 256 + threadIdx.x;        // rows * 512
    int r = g >> 9, c4 = g & 511;
    float4 v = *(const float4*)(in + (size_t)r * DD + c4 * 4);
    union { __half b[4]; uint2 u; } hi, lo;
    float vv[4] = {v.x, v.y, v.z, v.w};
#pragma unroll
    for (int i = 0; i < 4; i++) {
        hi.b[i] = __float2half_rn(vv[i]);
        lo.b[i] = ISW ? hi.b[i] : __float2half_rn(vv[i] - __half2float(hi.b[i]));
    }
    __half* o = out + (size_t)r * K2 + c4 * 4;
    *(uint2*)(o)      = hi.u;
    *(uint2*)(o + DD) = lo.u;
}

// ---------------- HMMA fp16 GEMM: C[M,Nrange] = A2[M,K'] @ W2[rows,K']^T -------
// 128x128 CTA tile, 4 warps, warp tile 64x64, BK=64/stage, 3-stage cp.async.
// Runtime iters (K'/64) + bnbase (N offset into W2 rows / output columns).
#define GSTAGE 32768
#define SMEM_GEMM_TOTAL (3*GSTAGE)      /* 98304 B */

template <int MODE>
__global__ __launch_bounds__(128, 2) void gemm_mma(float* __restrict__ Cout, int N,
                                                   int bnbase, int iters) {
    extern __shared__ __align__(16) char smraw[];
    const uint32_t sb = smem_u32(smraw);
    const int tid = threadIdx.x;
    const int bm = blockIdx.y * 128, bn = blockIdx.x * 128 + bnbase;
    const int warp = tid >> 5, lane = tid & 31;
    const int wm = warp >> 1, wn = warp & 1;

    float acc[32][4];
#pragma unroll
    for (int i = 0; i < 32; i++)
#pragma unroll
        for (int j = 0; j < 4; j++) acc[i][j] = 0.f;

    const int r0 = tid >> 3;                       // 0..15
    const int c0 = tid & 7;
    const uint32_t soA0 = r0 * 128 + SWZ8(c0, r0) * 16;
    const uint32_t soB0 = 16384 + soA0;
    const __half* pA = g_A2 + (size_t)(bm + r0) * K2 + c0 * 8;
    const __half* pB = g_W2 + (size_t)(bn + r0) * K2 + c0 * 8;

    auto load_stage = [&](uint32_t sbase) {
#pragma unroll
        for (int l = 0; l < 8; l++) {
            cp16(sbase + soA0 + l * 2048, pA + (size_t)l * 16 * K2);
            cp16(sbase + soB0 + l * 2048, pB + (size_t)l * 16 * K2);
        }
        asm volatile("cp.async.commit_group;" ::: "memory");
        pA += 64; pB += 64;
    };

    load_stage(sb);
    load_stage(sb + GSTAGE);

    const int lrow = (lane & 7) + 8 * ((lane >> 3) & 1);
    const int lch  = lane >> 4;
    uint32_t aro[4], bro[4];
#pragma unroll
    for (int mi = 0; mi < 4; mi++) {
        int row = wm * 64 + mi * 16 + lrow;
        aro[mi] = row * 128 + ((row & 7) << 4);
    }
#pragma unroll
    for (int n16 = 0; n16 < 4; n16++) {
        int nr = wn * 64 + n16 * 16 + lrow;
        bro[n16] = 16384 + nr * 128 + ((nr & 7) << 4);
    }

    for (int i = 0; i < iters; i += 3) {
#pragma unroll
        for (int u = 0; u < 3; u++) {
            const int idx = i + u;
            if (idx >= iters) break;
            if (idx >= iters - 2) asm volatile("cp.async.wait_group 0;" ::: "memory");
            else                  asm volatile("cp.async.wait_group 1;" ::: "memory");
            __syncthreads();
            if (idx + 2 < iters) load_stage(sb + ((u + 2) % 3) * GSTAGE);

            const uint32_t sa = sb + u * GSTAGE;
#pragma unroll
            for (int ks = 0; ks < 4; ks++) {
                const uint32_t chx = (uint32_t)(ks * 2 + lch) << 4;
                uint32_t a[4][4], b[4][4];
#pragma unroll
                for (int mi = 0; mi < 4; mi++)
                    ldmx4(a[mi], sa + (aro[mi] ^ chx));
#pragma unroll
                for (int n16 = 0; n16 < 4; n16++)
                    ldmx4(b[n16], sa + (bro[n16] ^ chx));
#pragma unroll
                for (int mi = 0; mi < 4; mi++)
#pragma unroll
                    for (int n16 = 0; n16 < 4; n16++) {
                        mma16816h(acc[mi * 8 + n16 * 2],     a[mi], b[n16][0], b[n16][2]);
                        mma16816h(acc[mi * 8 + n16 * 2 + 1], a[mi], b[n16][1], b[n16][3]);
                    }
            }
        }
    }

    // ---- epilogue ----
    if (MODE == 0) {
        const int which = bn >> 11;                // 0=q 1=k 2=v
        const int h = (bn >> 7) & 15;
        if (which == 2) {
#pragma unroll
            for (int mi = 0; mi < 4; mi++)
#pragma unroll
                for (int nn = 0; nn < 8; nn++) {
                    int d = wn * 64 + (nn >> 1) * 16 + (nn & 1) * 8 + (lane & 3) * 2;
#pragma unroll
                    for (int half = 0; half < 2; half++) {
                        int m = bm + wm * 64 + mi * 16 + (lane >> 2) + half * 8;
                        int b_ = m >> 11, t_ = m & (TT - 1);
                        size_t off = (((size_t)b_ * HH + h) * TT + t_) * HDIM + d;
                        float v0 = acc[mi * 8 + nn][2 * half];
                        float v1 = acc[mi * 8 + nn][2 * half + 1];
                        __nv_bfloat16 h0 = __float2bfloat16_rn(v0);
                        __nv_bfloat16 h1 = __float2bfloat16_rn(v1);
                        union { __nv_bfloat16 b[2]; uint32_t u; } ph, pl;
                        ph.b[0] = h0; ph.b[1] = h1;
                        pl.b[0] = __float2bfloat16_rn(v0 - __bfloat162float(h0));
                        pl.b[1] = __float2bfloat16_rn(v1 - __bfloat162float(h1));
                        *(uint32_t*)&g_vh[off] = ph.u;
                        *(uint32_t*)&g_vl[off] = pl.u;
                    }
                }
        } else {
            float* dst = (which == 0) ? g_q : g_k;
#pragma unroll
            for (int mi = 0; mi < 4; mi++)
#pragma unroll
                for (int nn = 0; nn < 8; nn++) {
                    int d = wn * 64 + (nn >> 1) * 16 + (nn & 1) * 8 + (lane & 3) * 2;
#pragma unroll
                    for (int half = 0; half < 2; half++) {
                        int m = bm + wm * 64 + mi * 16 + (lane >> 2) + half * 8;
                        int b_ = m >> 11, t_ = m & (TT - 1);
                        float2 v2 = make_float2(acc[mi * 8 + nn][2 * half],
                                                acc[mi * 8 + nn][2 * half + 1]);
                        *(float2*)&dst[(((size_t)b_ * HH + h) * TT + t_) * HDIM + d] = v2;
                    }
                }
        }
    } else {
#pragma unroll
        for (int mi = 0; mi < 4; mi++)
#pragma unroll
            for (int nn = 0; nn < 8; nn++) {
                int col = bn + wn * 64 + (nn >> 1) * 16 + (nn & 1) * 8 + (lane & 3) * 2;
#pragma unroll
                for (int half = 0; half < 2; half++) {
                    int m = bm + wm * 64 + mi * 16 + (lane >> 2) + half * 8;
                    float2 v2 = make_float2(acc[mi * 8 + nn][2 * half],
                                            acc[mi * 8 + nn][2 * half + 1]);
                    *(float2*)&Cout[(size_t)m * N + col] = v2;
                }
            }
    }
}

// ---------------- RoPE -> bf16 hi/lo planes for q and k (table-based) ----------
__global__ void rope_split_kernel() {
    int idx = blockIdx.x * blockDim.x + threadIdx.x;   // B*H*T*64
    int d  = idx & 63;
    int t  = (idx >> 6) & (TT - 1);
    int bh = idx >> 17;
    size_t base = ((size_t)bh * TT + t) * HDIM;
    int ti = (t << 6) + d;
    float s = g_sin[ti], c = g_cos[ti];

    float q1 = g_q[base + d], q2 = g_q[base + d + 64];
    float qa = q1 * c - q2 * s, qb = q2 * c + q1 * s;
    float k1 = g_k[base + d], k2 = g_k[base + d + 64];
    float ka = k1 * c - k2 * s, kb = k2 * c + k1 * s;

    __nv_bfloat16 h;
    h = __float2bfloat16_rn(qa); g_qh[base + d] = h;
    g_ql[base + d] = __float2bfloat16_rn(qa - __bfloat162float(h));
    h = __float2bfloat16_rn(qb); g_qh[base + d + 64] = h;
    g_ql[base + d + 64] = __float2bfloat16_rn(qb - __bfloat162float(h));
    h = __float2bfloat16_rn(ka); g_kh[base + d] = h;
    g_kl[base + d] = __float2bfloat16_rn(ka - __bfloat162float(h));
    h = __float2bfloat16_rn(kb); g_kh[base + d + 64] = h;
    g_kl[base + d + 64] = __float2bfloat16_rn(kb - __bfloat162float(h));
}

// ---------------- HMMA flash attention: BQ=128, BKV=64, 8 warps (bf16x3) ------
#define AQ_OFF   0
#define AKV_OFF  65536
#define AKV_STG  65536
#define SMEM_ATTN_TOTAL (65536 + 2*65536)   /* 196608 */

__global__ __launch_bounds__(256) void attn_mma_kernel() {
    extern __shared__ __align__(16) char smraw[];
    const uint32_t sb = smem_u32(smraw);
    const int tid = threadIdx.x;
    const int warp = tid >> 5, lane = tid & 31;
    const int qt = 15 - blockIdx.x;                 // descending work order
    const int h = blockIdx.y, b = blockIdx.z;
    const int L = g_len[b];
    const size_t bhT = ((size_t)b * HH + h) * TT;

    const int lrow = (lane & 7) + 8 * ((lane >> 3) & 1);
    const int lch  = lane >> 4;

    // ---- load Q tile (both planes), own commit group ----
    {
        const __nv_bfloat16* qp[2];
        qp[0] = g_qh; qp[1] = g_ql;
#pragma unroll
        for (int l = 0; l < 16; l++) {
            int idx = tid + l * 256;                // 4096 chunks
            int pl = idx >> 11, rem = idx & 2047;
            int row = rem >> 4, c = rem & 15;
            cp16(sb + AQ_OFF + pl * 32768 + row * 256 + SWZ8(c, row) * 16,
                 qp[pl] + (bhT + (size_t)qt * 128 + row) * HDIM + c * 8);
        }
        asm volatile("cp.async.commit_group;" ::: "memory");
    }

    const int nt = (min(qt * 128 + 128, L) + 63) / 64;

    auto load_kv = [&](int kt, int stg) {
        const __nv_bfloat16* pp[4];
        pp[0] = g_kh; pp[1] = g_kl; pp[2] = g_vh; pp[3] = g_vl;
        uint32_t base = sb + AKV_OFF + stg * AKV_STG;
#pragma unroll
        for (int l = 0; l < 16; l++) {
            int idx = tid + l * 256;
            int pl = idx >> 10, rem = idx & 1023;
            int row = rem >> 4, c = rem & 15;
            cp16(base + pl * 16384 + row * 256 + SWZ8(c, row) * 16,
                 pp[pl] + (bhT + (size_t)kt * 64 + row) * HDIM + c * 8);
        }
        asm volatile("cp.async.commit_group;" ::: "memory");
    };
    load_kv(0, 0);

    // ---- hoist Q fragments (wait only for the Q group) ----
    uint32_t qhf[8][4], qlf[8][4];
    {
        asm volatile("cp.async.wait_group 1;" ::: "memory");
        __syncthreads();
        const uint32_t qh = sb + AQ_OFF, ql = qh + 32768;
        const int arow = warp * 16 + lrow;
#pragma unroll
        for (int k16 = 0; k16 < 8; k16++) {
            const int ch = k16 * 2 + lch;
            ldmx4(qhf[k16], qh + arow * 256 + SWZ8(ch, arow) * 16);
            ldmx4(qlf[k16], ql + arow * 256 + SWZ8(ch, arow) * 16);
        }
    }

    float oacc[16][4];
#pragma unroll
    for (int i = 0; i < 16; i++)
#pragma unroll
        for (int j = 0; j < 4; j++) oacc[i][j] = 0.f;
    float m0 = -1e30f, m1 = -1e30f, l0 = 0.f, l1 = 0.f;

    const int wr = qt * 128 + warp * 16;
    const float scl = 0.08838834764831843f;

    for (int kt = 0; kt < nt; kt++) {
        asm volatile("cp.async.wait_group 0;" ::: "memory");
        __syncthreads();
        if (kt + 1 < nt) load_kv(kt + 1, (kt + 1) & 1);

        const uint32_t kh = sb + AKV_OFF + (kt & 1) * AKV_STG;
        const uint32_t kl = kh + 16384;
        const uint32_t vh = kh + 32768;
        const uint32_t vl = kh + 49152;

        // ---- S = Qh*Kh + Ql*Kh + Qh*Kl ----
        float sacc[8][4];
#pragma unroll
        for (int i = 0; i < 8; i++)
#pragma unroll
            for (int j = 0; j < 4; j++) sacc[i][j] = 0.f;

#pragma unroll
        for (int k16 = 0; k16 < 8; k16++) {
            const int ch = k16 * 2 + lch;
#pragma unroll
            for (int n16 = 0; n16 < 4; n16++) {
                const int nr = n16 * 16 + lrow;
                uint32_t bh[4], bl[4];
                ldmx4(bh, kh + nr * 256 + SWZ8(ch, nr) * 16);
                mma16816(sacc[2*n16],   qhf[k16], bh[0], bh[2]);
                mma16816(sacc[2*n16+1], qhf[k16], bh[1], bh[3]);
                mma16816(sacc[2*n16],   qlf[k16], bh[0], bh[2]);
                mma16816(sacc[2*n16+1], qlf[k16], bh[1], bh[3]);
                ldmx4(bl, kl + nr * 256 + SWZ8(ch, nr) * 16);
                mma16816(sacc[2*n16],   qhf[k16], bl[0], bl[2]);
                mma16816(sacc[2*n16+1], qhf[k16], bl[1], bl[3]);
            }
        }

        // ---- mask + online softmax ----
        const bool needmask = ((kt + 1) * 64 > qt * 128) || ((kt + 1) * 64 > L);
        const int r0g = wr + (lane >> 2);
#pragma unroll
        for (int f = 0; f < 8; f++)
#pragma unroll
            for (int c = 0; c < 4; c++) {
                float x = sacc[f][c] * scl;
                if (needmask) {
                    int col = kt * 64 + f * 8 + ((lane & 3) << 1) + (c & 1);
                    int rg = r0g + ((c >> 1) << 3);
                    if (col > rg || col >= L) x = -1e30f;
                }
                sacc[f][c] = x;
            }
        float mx0 = -1e30f, mx1 = -1e30f;
#pragma unroll
        for (int f = 0; f < 8; f++) {
            mx0 = fmaxf(mx0, fmaxf(sacc[f][0], sacc[f][1]));
            mx1 = fmaxf(mx1, fmaxf(sacc[f][2], sacc[f][3]));
        }
        mx0 = fmaxf(mx0, __shfl_xor_sync(0xffffffffu, mx0, 1));
        mx0 = fmaxf(mx0, __shfl_xor_sync(0xffffffffu, mx0, 2));
        mx1 = fmaxf(mx1, __shfl_xor_sync(0xffffffffu, mx1, 1));
        mx1 = fmaxf(mx1, __shfl_xor_sync(0xffffffffu, mx1, 2));
        float mn0 = fmaxf(m0, mx0), mn1 = fmaxf(m1, mx1);
        float corr0 = __expf(m0 - mn0), corr1 = __expf(m1 - mn1);
        float sum0 = 0.f, sum1 = 0.f;
#pragma unroll
        for (int f = 0; f < 8; f++) {
            float p;
            p = __expf(sacc[f][0] - mn0); sacc[f][0] = p; sum0 += p;
            p = __expf(sacc[f][1] - mn0); sacc[f][1] = p; sum0 += p;
            p = __expf(sacc[f][2] - mn1); sacc[f][2] = p; sum1 += p;
            p = __expf(sacc[f][3] - mn1); sacc[f][3] = p; sum1 += p;
        }
        sum0 += __shfl_xor_sync(0xffffffffu, sum0, 1);
        sum0 += __shfl_xor_sync(0xffffffffu, sum0, 2);
        sum1 += __shfl_xor_sync(0xffffffffu, sum1, 1);
        sum1 += __shfl_xor_sync(0xffffffffu, sum1, 2);
        l0 = l0 * corr0 + sum0; m0 = mn0;
        l1 = l1 * corr1 + sum1; m1 = mn1;
#pragma unroll
        for (int nf = 0; nf < 16; nf++) {
            oacc[nf][0] *= corr0; oacc[nf][1] *= corr0;
            oacc[nf][2] *= corr1; oacc[nf][3] *= corr1;
        }

        // ---- O += Ph*Vh + Pl*Vh + Ph*Vl ----
#pragma unroll
        for (int j16 = 0; j16 < 4; j16++) {
            const int f0 = 2 * j16, f1 = 2 * j16 + 1;
            uint32_t aPh[4], aPl[4];
            {
                float p00 = sacc[f0][0], p01 = sacc[f0][1];
                float p02 = sacc[f0][2], p03 = sacc[f0][3];
                float p10 = sacc[f1][0], p11 = sacc[f1][1];
                float p12 = sacc[f1][2], p13 = sacc[f1][3];
                aPh[0] = pack_bf16x2(p00, p01);
                aPh[1] = pack_bf16x2(p02, p03);
                aPh[2] = pack_bf16x2(p10, p11);
                aPh[3] = pack_bf16x2(p12, p13);
                union { uint32_t u; __nv_bfloat162 b2; } t;
                float r00, r01, r02, r03, r10, r11, r12, r13;
                t.u = aPh[0]; r00 = p00 - __bfloat162float(t.b2.x); r01 = p01 - __bfloat162float(t.b2.y);
                t.u = aPh[1]; r02 = p02 - __bfloat162float(t.b2.x); r03 = p03 - __bfloat162float(t.b2.y);
                t.u = aPh[2]; r10 = p10 - __bfloat162float(t.b2.x); r11 = p11 - __bfloat162float(t.b2.y);
                t.u = aPh[3]; r12 = p12 - __bfloat162float(t.b2.x); r13 = p13 - __bfloat162float(t.b2.y);
                aPl[0] = pack_bf16x2(r00, r01);
                aPl[1] = pack_bf16x2(r02, r03);
                aPl[2] = pack_bf16x2(r10, r11);
                aPl[3] = pack_bf16x2(r12, r13);
            }
#pragma unroll
            for (int d16 = 0; d16 < 8; d16++) {
                const int ch = d16 * 2 + lch;
                const int vr = j16 * 16 + lrow;
                uint32_t bvh[4], bvl[4];
                ldmx4t(bvh, vh + vr * 256 + SWZ8(ch, vr) * 16);
                mma16816(oacc[2*d16],   aPh, bvh[0], bvh[1]);
                mma16816(oacc[2*d16+1], aPh, bvh[2], bvh[3]);
                mma16816(oacc[2*d16],   aPl, bvh[0], bvh[1]);
                mma16816(oacc[2*d16+1], aPl, bvh[2], bvh[3]);
                ldmx4t(bvl, vl + vr * 256 + SWZ8(ch, vr) * 16);
                mma16816(oacc[2*d16],   aPh, bvl[0], bvl[1]);
                mma16816(oacc[2*d16+1], aPh, bvl[2], bvl[3]);
            }
        }
        __syncthreads();
    }

    // ---- epilogue: write directly into g_A2 fp16 [ah|al] ----
    const float il0 = 1.f / l0, il1 = 1.f / l1;
    const int trow = qt * 128 + warp * 16 + (lane >> 2);
#pragma unroll
    for (int nf = 0; nf < 16; nf++) {
        int col = h * 128 + nf * 8 + (lane & 3) * 2;
#pragma unroll
        for (int half = 0; half < 2; half++) {
            float v0 = oacc[nf][2 * half]     * (half ? il1 : il0);
            float v1 = oacc[nf][2 * half + 1] * (half ? il1 : il0);
            __half h0 = __float2half_rn(v0);
            __half h1 = __float2half_rn(v1);
            union { __half b[2]; uint32_t u; } ph, pl;
            ph.b[0] = h0; ph.b[1] = h1;
            pl.b[0] = __float2half_rn(v0 - __half2float(h0));
            pl.b[1] = __float2half_rn(v1 - __half2float(h1));
            __half* row = g_A2 + ((size_t)b * TT + trow + half * 8) * K2;
            *(uint32_t*)&row[col]      = ph.u;
            *(uint32_t*)&row[col + DD] = pl.u;
        }
    }
}

// ---------------- launcher ----------------
extern "C" void kernel_launch(void* const* d_in, const int* in_sizes, int n_in,
                              void* d_out, int out_size) {
    const float* x     = (const float*)d_in[0];
    const float* Wqkv  = (const float*)d_in[1];
    const float* Wproj = (const float*)d_in[2];
    const int*   mask  = (const int*)d_in[3];
    float* out = (float*)d_out;

    cudaFuncSetAttribute(gemm_mma<0>, cudaFuncAttributeMaxDynamicSharedMemorySize, SMEM_GEMM_TOTAL);
    cudaFuncSetAttribute(gemm_mma<1>, cudaFuncAttributeMaxDynamicSharedMemorySize, SMEM_GEMM_TOTAL);
    cudaFuncSetAttribute(attn_mma_kernel, cudaFuncAttributeMaxDynamicSharedMemorySize, SMEM_ATTN_TOTAL);

    sctab_kernel<<<(TT * 64) / 256, 256>>>();
    lengths_kernel<<<BB, 256>>>(mask);
    conv2_kernel<0, 0><<<MROWS * 2, 256>>>(x);         // x    -> g_A2 [ah|al]
    conv2_kernel<1, 1><<<(3 * DD) * 2, 256>>>(Wqkv);   // Wqkv -> g_W2 [wh|wh]
    // q,k: full fp16x2 (K'=4096); v: single-plane (K'=2048, exactness not needed)
    gemm_mma<0><<<dim3(32, 64), 128, SMEM_GEMM_TOTAL>>>(nullptr, 0, 0,    K2 / 64);
    gemm_mma<0><<<dim3(16, 64), 128, SMEM_GEMM_TOTAL>>>(nullptr, 0, 4096, DD / 64);
    rope_split_kernel<<<(BB * HH * TT * 64) / 256, 256>>>();
    attn_mma_kernel<<<dim3(16, HH, BB), 256, SMEM_ATTN_TOTAL>>>();
    conv2_kernel<1, 1><<<DD * 2, 256>>>(Wproj);        // Wproj-> g_W2 [wh|wh]
    gemm_mma<1><<<dim3(16, 64), 128, SMEM_GEMM_TOTAL>>>(out, DD, 0, K2 / 64);
}

// round 11
// speedup vs baseline: 7.6910x; 1.3710x over previous
#include <cuda_runtime.h>
#include <cuda_bf16.h>
#include <cuda_fp16.h>
#include <cstdint>
#include <math.h>

#define BB 4
#define TT 2048
#define DD 2048
#define HH 16
#define HDIM 128
#define MROWS (BB*TT)       /* 8192 */
#define K2 (2*DD)           /* 4096 */
#define PLANE_ELEMS ((size_t)BB*HH*TT*HDIM)   /* 16.8M */

// ---------------- scratch (device globals; uint4-backed => 16B align) ----------
__device__ uint4 g_q_raw  [PLANE_ELEMS/4];               // fp32 (B,H,T,hd)
__device__ uint4 g_k_raw  [PLANE_ELEMS/4];
__device__ uint4 g_A2_raw [(size_t)MROWS*K2/8];          // fp16 [ah|al] activations
__device__ uint4 g_W2_raw [(size_t)(3*DD)*K2/8];         // fp16 [wh|wh] weights
__device__ uint4 g_qh_raw [PLANE_ELEMS/8];               // fp16 planes (attention)
__device__ uint4 g_ql_raw [PLANE_ELEMS/8];
__device__ uint4 g_kh_raw [PLANE_ELEMS/8];
__device__ uint4 g_vh_raw [PLANE_ELEMS/8];
__device__ float g_sin[TT*64];
__device__ float g_cos[TT*64];
__device__ int   g_len[BB];

// device-code-only views (never use in host code / kernel args)
#define g_q   ((float*)g_q_raw)
#define g_k   ((float*)g_k_raw)
#define g_A2  ((__half*)g_A2_raw)
#define g_W2  ((__half*)g_W2_raw)
#define g_qh  ((__half*)g_qh_raw)
#define g_ql  ((__half*)g_ql_raw)
#define g_kh  ((__half*)g_kh_raw)
#define g_vh  ((__half*)g_vh_raw)

// ============================ helpers ============================
__device__ __forceinline__ uint32_t smem_u32(const void* p) {
    uint32_t a;
    asm("{ .reg .u64 t; cvta.to.shared.u64 t, %1; cvt.u32.u64 %0, t; }" : "=r"(a) : "l"(p));
    return a;
}
__device__ __forceinline__ void cp16(uint32_t s, const void* g) {
    asm volatile("cp.async.cg.shared.global [%0], [%1], 16;" :: "r"(s), "l"(g));
}
__device__ __forceinline__ void ldmx4(uint32_t* r, uint32_t addr) {
    asm volatile("ldmatrix.sync.aligned.m8n8.x4.shared.b16 {%0,%1,%2,%3}, [%4];"
        : "=r"(r[0]), "=r"(r[1]), "=r"(r[2]), "=r"(r[3]) : "r"(addr));
}
__device__ __forceinline__ void ldmx4t(uint32_t* r, uint32_t addr) {
    asm volatile("ldmatrix.sync.aligned.m8n8.x4.trans.shared.b16 {%0,%1,%2,%3}, [%4];"
        : "=r"(r[0]), "=r"(r[1]), "=r"(r[2]), "=r"(r[3]) : "r"(addr));
}
// fp16 MMA
__device__ __forceinline__ void mma16816h(float* d, const uint32_t* a, uint32_t b0, uint32_t b1) {
    asm volatile("mma.sync.aligned.m16n8k16.row.col.f32.f16.f16.f32 "
        "{%0,%1,%2,%3}, {%4,%5,%6,%7}, {%8,%9}, {%0,%1,%2,%3};"
        : "+f"(d[0]), "+f"(d[1]), "+f"(d[2]), "+f"(d[3])
        : "r"(a[0]), "r"(a[1]), "r"(a[2]), "r"(a[3]), "r"(b0), "r"(b1));
}
__device__ __forceinline__ uint32_t pack_h2(float lo, float hi) {
    union { __half2 h; uint32_t u; } t;
    t.h = __floats2half2_rn(lo, hi);
    return t.u;
}
#define SWZ8(c, r)  ((c) ^ ((r) & 7))

// ---------------- per-batch valid lengths ----------------
__global__ void lengths_kernel(const int* __restrict__ mask) {
    __shared__ int sd[256];
    int b = blockIdx.x;
    int s = 0;
    for (int i = threadIdx.x; i < TT; i += 256) s += mask[b * TT + i];
    sd[threadIdx.x] = s;
    __syncthreads();
    for (int st = 128; st > 0; st >>= 1) {
        if (threadIdx.x < st) sd[threadIdx.x] += sd[threadIdx.x + st];
        __syncthreads();
    }
    if (threadIdx.x == 0) g_len[b] = sd[0];
}

// ---------------- RoPE sin/cos table ----------------
__global__ void sctab_kernel() {
    int idx = blockIdx.x * 256 + threadIdx.x;      // TT*64
    int d = idx & 63, t = idx >> 6;
    float inv = (float)exp(-(double)(2 * d) / 128.0 * 9.210340371976184);
    float ang = (float)t * inv;
    float s, c;
    sincosf(ang, &s, &c);
    g_sin[idx] = s;
    g_cos[idx] = c;
}

// ---------------- fp32 -> fp16x2 split conversion ----------------
template <int ISW, int DSTW>
__global__ __launch_bounds__(256) void conv2_kernel(const float* __restrict__ in) {
    __half* out = DSTW ? g_W2 : g_A2;
    int g = blockIdx.x * 256 + threadIdx.x;        // rows * 512
    int r = g >> 9, c4 = g & 511;
    float4 v = *(const float4*)(in + (size_t)r * DD + c4 * 4);
    union { __half b[4]; uint2 u; } hi, lo;
    float vv[4] = {v.x, v.y, v.z, v.w};
#pragma unroll
    for (int i = 0; i < 4; i++) {
        hi.b[i] = __float2half_rn(vv[i]);
        lo.b[i] = ISW ? hi.b[i] : __float2half_rn(vv[i] - __half2float(hi.b[i]));
    }
    __half* o = out + (size_t)r * K2 + c4 * 4;
    *(uint2*)(o)      = hi.u;
    *(uint2*)(o + DD) = lo.u;
}

// ---------------- HMMA fp16 GEMM ----------------
#define GSTAGE 32768
#define SMEM_GEMM_TOTAL (3*GSTAGE)      /* 98304 B */

template <int MODE>
__global__ __launch_bounds__(128, 2) void gemm_mma(float* __restrict__ Cout, int N,
                                                   int bnbase, int iters) {
    extern __shared__ __align__(16) char smraw[];
    const uint32_t sb = smem_u32(smraw);
    const int tid = threadIdx.x;
    const int bm = blockIdx.y * 128, bn = blockIdx.x * 128 + bnbase;
    const int warp = tid >> 5, lane = tid & 31;
    const int wm = warp >> 1, wn = warp & 1;

    float acc[32][4];
#pragma unroll
    for (int i = 0; i < 32; i++)
#pragma unroll
        for (int j = 0; j < 4; j++) acc[i][j] = 0.f;

    const int r0 = tid >> 3;                       // 0..15
    const int c0 = tid & 7;
    const uint32_t soA0 = r0 * 128 + SWZ8(c0, r0) * 16;
    const uint32_t soB0 = 16384 + soA0;
    const __half* pA = g_A2 + (size_t)(bm + r0) * K2 + c0 * 8;
    const __half* pB = g_W2 + (size_t)(bn + r0) * K2 + c0 * 8;

    auto load_stage = [&](uint32_t sbase) {
#pragma unroll
        for (int l = 0; l < 8; l++) {
            cp16(sbase + soA0 + l * 2048, pA + (size_t)l * 16 * K2);
            cp16(sbase + soB0 + l * 2048, pB + (size_t)l * 16 * K2);
        }
        asm volatile("cp.async.commit_group;" ::: "memory");
        pA += 64; pB += 64;
    };

    load_stage(sb);
    load_stage(sb + GSTAGE);

    const int lrow = (lane & 7) + 8 * ((lane >> 3) & 1);
    const int lch  = lane >> 4;
    uint32_t aro[4], bro[4];
#pragma unroll
    for (int mi = 0; mi < 4; mi++) {
        int row = wm * 64 + mi * 16 + lrow;
        aro[mi] = row * 128 + ((row & 7) << 4);
    }
#pragma unroll
    for (int n16 = 0; n16 < 4; n16++) {
        int nr = wn * 64 + n16 * 16 + lrow;
        bro[n16] = 16384 + nr * 128 + ((nr & 7) << 4);
    }

    for (int i = 0; i < iters; i += 3) {
#pragma unroll
        for (int u = 0; u < 3; u++) {
            const int idx = i + u;
            if (idx >= iters) break;
            if (idx >= iters - 2) asm volatile("cp.async.wait_group 0;" ::: "memory");
            else                  asm volatile("cp.async.wait_group 1;" ::: "memory");
            __syncthreads();
            if (idx + 2 < iters) load_stage(sb + ((u + 2) % 3) * GSTAGE);

            const uint32_t sa = sb + u * GSTAGE;
#pragma unroll
            for (int ks = 0; ks < 4; ks++) {
                const uint32_t chx = (uint32_t)(ks * 2 + lch) << 4;
                uint32_t a[4][4], b[4][4];
#pragma unroll
                for (int mi = 0; mi < 4; mi++)
                    ldmx4(a[mi], sa + (aro[mi] ^ chx));
#pragma unroll
                for (int n16 = 0; n16 < 4; n16++)
                    ldmx4(b[n16], sa + (bro[n16] ^ chx));
#pragma unroll
                for (int mi = 0; mi < 4; mi++)
#pragma unroll
                    for (int n16 = 0; n16 < 4; n16++) {
                        mma16816h(acc[mi * 8 + n16 * 2],     a[mi], b[n16][0], b[n16][2]);
                        mma16816h(acc[mi * 8 + n16 * 2 + 1], a[mi], b[n16][1], b[n16][3]);
                    }
            }
        }
    }

    // ---- epilogue ----
    if (MODE == 0) {
        const int which = bn >> 11;                // 0=q 1=k 2=v
        const int h = (bn >> 7) & 15;
        if (which == 2) {
            // V: single fp16 plane
#pragma unroll
            for (int mi = 0; mi < 4; mi++)
#pragma unroll
                for (int nn = 0; nn < 8; nn++) {
                    int d = wn * 64 + (nn >> 1) * 16 + (nn & 1) * 8 + (lane & 3) * 2;
#pragma unroll
                    for (int half = 0; half < 2; half++) {
                        int m = bm + wm * 64 + mi * 16 + (lane >> 2) + half * 8;
                        int b_ = m >> 11, t_ = m & (TT - 1);
                        size_t off = (((size_t)b_ * HH + h) * TT + t_) * HDIM + d;
                        *(uint32_t*)&g_vh[off] = pack_h2(acc[mi * 8 + nn][2 * half],
                                                         acc[mi * 8 + nn][2 * half + 1]);
                    }
                }
        } else {
            float* dst = (which == 0) ? g_q : g_k;
#pragma unroll
            for (int mi = 0; mi < 4; mi++)
#pragma unroll
                for (int nn = 0; nn < 8; nn++) {
                    int d = wn * 64 + (nn >> 1) * 16 + (nn & 1) * 8 + (lane & 3) * 2;
#pragma unroll
                    for (int half = 0; half < 2; half++) {
                        int m = bm + wm * 64 + mi * 16 + (lane >> 2) + half * 8;
                        int b_ = m >> 11, t_ = m & (TT - 1);
                        float2 v2 = make_float2(acc[mi * 8 + nn][2 * half],
                                                acc[mi * 8 + nn][2 * half + 1]);
                        *(float2*)&dst[(((size_t)b_ * HH + h) * TT + t_) * HDIM + d] = v2;
                    }
                }
        }
    } else {
#pragma unroll
        for (int mi = 0; mi < 4; mi++)
#pragma unroll
            for (int nn = 0; nn < 8; nn++) {
                int col = bn + wn * 64 + (nn >> 1) * 16 + (nn & 1) * 8 + (lane & 3) * 2;
#pragma unroll
                for (int half = 0; half < 2; half++) {
                    int m = bm + wm * 64 + mi * 16 + (lane >> 2) + half * 8;
                    float2 v2 = make_float2(acc[mi * 8 + nn][2 * half],
                                            acc[mi * 8 + nn][2 * half + 1]);
                    *(float2*)&Cout[(size_t)m * N + col] = v2;
                }
            }
    }
}

// ---------------- RoPE -> fp16 planes: qh,ql (exact split), kh ----------------
__global__ void rope_split_kernel() {
    int idx = blockIdx.x * blockDim.x + threadIdx.x;   // B*H*T*64
    int d  = idx & 63;
    int t  = (idx >> 6) & (TT - 1);
    int bh = idx >> 17;
    size_t base = ((size_t)bh * TT + t) * HDIM;
    int ti = (t << 6) + d;
    float s = g_sin[ti], c = g_cos[ti];

    float q1 = g_q[base + d], q2 = g_q[base + d + 64];
    float qa = q1 * c - q2 * s, qb = q2 * c + q1 * s;
    float k1 = g_k[base + d], k2 = g_k[base + d + 64];
    float ka = k1 * c - k2 * s, kb = k2 * c + k1 * s;

    __half h;
    h = __float2half_rn(qa); g_qh[base + d] = h;
    g_ql[base + d] = __float2half_rn(qa - __half2float(h));
    h = __float2half_rn(qb); g_qh[base + d + 64] = h;
    g_ql[base + d + 64] = __float2half_rn(qb - __half2float(h));
    g_kh[base + d]      = __float2half_rn(ka);
    g_kh[base + d + 64] = __float2half_rn(kb);
}

// ---------------- fp16 flash attention: BQ=128, BKV=64, 8 warps ----------------
// S = (Qh+Ql)*Kh (2 terms); O = (Ph+Pl)*Vh (2 terms)
#define AQ_OFF   0
#define AKV_OFF  65536
#define AKV_STG  32768
#define SMEM_ATTN_TOTAL (65536 + 2*32768)   /* 131072 */

__global__ __launch_bounds__(256) void attn_mma_kernel() {
    extern __shared__ __align__(16) char smraw[];
    const uint32_t sb = smem_u32(smraw);
    const int tid = threadIdx.x;
    const int warp = tid >> 5, lane = tid & 31;
    const int qt = 15 - blockIdx.x;                 // descending work order
    const int h = blockIdx.y, b = blockIdx.z;
    const int L = g_len[b];
    const size_t bhT = ((size_t)b * HH + h) * TT;

    const int lrow = (lane & 7) + 8 * ((lane >> 3) & 1);
    const int lch  = lane >> 4;

    // ---- load Q tile (qh, ql planes), own commit group ----
    {
        const __half* qp[2];
        qp[0] = g_qh; qp[1] = g_ql;
#pragma unroll
        for (int l = 0; l < 16; l++) {
            int idx = tid + l * 256;                // 4096 chunks
            int pl = idx >> 11, rem = idx & 2047;
            int row = rem >> 4, c = rem & 15;
            cp16(sb + AQ_OFF + pl * 32768 + row * 256 + SWZ8(c, row) * 16,
                 qp[pl] + (bhT + (size_t)qt * 128 + row) * HDIM + c * 8);
        }
        asm volatile("cp.async.commit_group;" ::: "memory");
    }

    const int nt = (min(qt * 128 + 128, L) + 63) / 64;

    auto load_kv = [&](int kt, int stg) {
        const __half* pp[2];
        pp[0] = g_kh; pp[1] = g_vh;
        uint32_t base = sb + AKV_OFF + stg * AKV_STG;
#pragma unroll
        for (int l = 0; l < 8; l++) {
            int idx = tid + l * 256;                // 2048 chunks
            int pl = idx >> 10, rem = idx & 1023;
            int row = rem >> 4, c = rem & 15;
            cp16(base + pl * 16384 + row * 256 + SWZ8(c, row) * 16,
                 pp[pl] + (bhT + (size_t)kt * 64 + row) * HDIM + c * 8);
        }
        asm volatile("cp.async.commit_group;" ::: "memory");
    };
    load_kv(0, 0);

    // ---- hoist Q fragments (wait only for the Q group) ----
    uint32_t qhf[8][4], qlf[8][4];
    {
        asm volatile("cp.async.wait_group 1;" ::: "memory");
        __syncthreads();
        const uint32_t qh = sb + AQ_OFF, ql = qh + 32768;
        const int arow = warp * 16 + lrow;
#pragma unroll
        for (int k16 = 0; k16 < 8; k16++) {
            const int ch = k16 * 2 + lch;
            ldmx4(qhf[k16], qh + arow * 256 + SWZ8(ch, arow) * 16);
            ldmx4(qlf[k16], ql + arow * 256 + SWZ8(ch, arow) * 16);
        }
    }

    float oacc[16][4];
#pragma unroll
    for (int i = 0; i < 16; i++)
#pragma unroll
        for (int j = 0; j < 4; j++) oacc[i][j] = 0.f;
    float m0 = -1e30f, m1 = -1e30f, l0 = 0.f, l1 = 0.f;

    const int wr = qt * 128 + warp * 16;
    const float scl = 0.08838834764831843f;

    for (int kt = 0; kt < nt; kt++) {
        asm volatile("cp.async.wait_group 0;" ::: "memory");
        __syncthreads();
        if (kt + 1 < nt) load_kv(kt + 1, (kt + 1) & 1);

        const uint32_t kh = sb + AKV_OFF + (kt & 1) * AKV_STG;
        const uint32_t vh = kh + 16384;

        // ---- S = Qh*Kh + Ql*Kh ----
        float sacc[8][4];
#pragma unroll
        for (int i = 0; i < 8; i++)
#pragma unroll
            for (int j = 0; j < 4; j++) sacc[i][j] = 0.f;

#pragma unroll
        for (int k16 = 0; k16 < 8; k16++) {
            const int ch = k16 * 2 + lch;
#pragma unroll
            for (int n16 = 0; n16 < 4; n16++) {
                const int nr = n16 * 16 + lrow;
                uint32_t bh[4];
                ldmx4(bh, kh + nr * 256 + SWZ8(ch, nr) * 16);
                mma16816h(sacc[2*n16],   qhf[k16], bh[0], bh[2]);
                mma16816h(sacc[2*n16+1], qhf[k16], bh[1], bh[3]);
                mma16816h(sacc[2*n16],   qlf[k16], bh[0], bh[2]);
                mma16816h(sacc[2*n16+1], qlf[k16], bh[1], bh[3]);
            }
        }

        // ---- mask + online softmax ----
        const bool needmask = ((kt + 1) * 64 > qt * 128) || ((kt + 1) * 64 > L);
        const int r0g = wr + (lane >> 2);
#pragma unroll
        for (int f = 0; f < 8; f++)
#pragma unroll
            for (int c = 0; c < 4; c++) {
                float x = sacc[f][c] * scl;
                if (needmask) {
                    int col = kt * 64 + f * 8 + ((lane & 3) << 1) + (c & 1);
                    int rg = r0g + ((c >> 1) << 3);
                    if (col > rg || col >= L) x = -1e30f;
                }
                sacc[f][c] = x;
            }
        float mx0 = -1e30f, mx1 = -1e30f;
#pragma unroll
        for (int f = 0; f < 8; f++) {
            mx0 = fmaxf(mx0, fmaxf(sacc[f][0], sacc[f][1]));
            mx1 = fmaxf(mx1, fmaxf(sacc[f][2], sacc[f][3]));
        }
        mx0 = fmaxf(mx0, __shfl_xor_sync(0xffffffffu, mx0, 1));
        mx0 = fmaxf(mx0, __shfl_xor_sync(0xffffffffu, mx0, 2));
        mx1 = fmaxf(mx1, __shfl_xor_sync(0xffffffffu, mx1, 1));
        mx1 = fmaxf(mx1, __shfl_xor_sync(0xffffffffu, mx1, 2));
        float mn0 = fmaxf(m0, mx0), mn1 = fmaxf(m1, mx1);
        float corr0 = __expf(m0 - mn0), corr1 = __expf(m1 - mn1);
        float sum0 = 0.f, sum1 = 0.f;
#pragma unroll
        for (int f = 0; f < 8; f++) {
            float p;
            p = __expf(sacc[f][0] - mn0); sacc[f][0] = p; sum0 += p;
            p = __expf(sacc[f][1] - mn0); sacc[f][1] = p; sum0 += p;
            p = __expf(sacc[f][2] - mn1); sacc[f][2] = p; sum1 += p;
            p = __expf(sacc[f][3] - mn1); sacc[f][3] = p; sum1 += p;
        }
        sum0 += __shfl_xor_sync(0xffffffffu, sum0, 1);
        sum0 += __shfl_xor_sync(0xffffffffu, sum0, 2);
        sum1 += __shfl_xor_sync(0xffffffffu, sum1, 1);
        sum1 += __shfl_xor_sync(0xffffffffu, sum1, 2);
        l0 = l0 * corr0 + sum0; m0 = mn0;
        l1 = l1 * corr1 + sum1; m1 = mn1;
#pragma unroll
        for (int nf = 0; nf < 16; nf++) {
            oacc[nf][0] *= corr0; oacc[nf][1] *= corr0;
            oacc[nf][2] *= corr1; oacc[nf][3] *= corr1;
        }

        // ---- O += Ph*Vh + Pl*Vh (P split exact in fp16) ----
#pragma unroll
        for (int j16 = 0; j16 < 4; j16++) {
            const int f0 = 2 * j16, f1 = 2 * j16 + 1;
            uint32_t aPh[4], aPl[4];
            {
                float p00 = sacc[f0][0], p01 = sacc[f0][1];
                float p02 = sacc[f0][2], p03 = sacc[f0][3];
                float p10 = sacc[f1][0], p11 = sacc[f1][1];
                float p12 = sacc[f1][2], p13 = sacc[f1][3];
                aPh[0] = pack_h2(p00, p01);
                aPh[1] = pack_h2(p02, p03);
                aPh[2] = pack_h2(p10, p11);
                aPh[3] = pack_h2(p12, p13);
                union { uint32_t u; __half2 h2; } t;
                float r00, r01, r02, r03, r10, r11, r12, r13;
                t.u = aPh[0]; r00 = p00 - __half2float(t.h2.x); r01 = p01 - __half2float(t.h2.y);
                t.u = aPh[1]; r02 = p02 - __half2float(t.h2.x); r03 = p03 - __half2float(t.h2.y);
                t.u = aPh[2]; r10 = p10 - __half2float(t.h2.x); r11 = p11 - __half2float(t.h2.y);
                t.u = aPh[3]; r12 = p12 - __half2float(t.h2.x); r13 = p13 - __half2float(t.h2.y);
                aPl[0] = pack_h2(r00, r01);
                aPl[1] = pack_h2(r02, r03);
                aPl[2] = pack_h2(r10, r11);
                aPl[3] = pack_h2(r12, r13);
            }
#pragma unroll
            for (int d16 = 0; d16 < 8; d16++) {
                const int ch = d16 * 2 + lch;
                const int vr = j16 * 16 + lrow;
                uint32_t bvh[4];
                ldmx4t(bvh, vh + vr * 256 + SWZ8(ch, vr) * 16);
                mma16816h(oacc[2*d16],   aPh, bvh[0], bvh[1]);
                mma16816h(oacc[2*d16+1], aPh, bvh[2], bvh[3]);
                mma16816h(oacc[2*d16],   aPl, bvh[0], bvh[1]);
                mma16816h(oacc[2*d16+1], aPl, bvh[2], bvh[3]);
            }
        }
        __syncthreads();
    }

    // ---- epilogue: write directly into g_A2 fp16 [ah|al] ----
    const float il0 = 1.f / l0, il1 = 1.f / l1;
    const int trow = qt * 128 + warp * 16 + (lane >> 2);
#pragma unroll
    for (int nf = 0; nf < 16; nf++) {
        int col = h * 128 + nf * 8 + (lane & 3) * 2;
#pragma unroll
        for (int half = 0; half < 2; half++) {
            float v0 = oacc[nf][2 * half]     * (half ? il1 : il0);
            float v1 = oacc[nf][2 * half + 1] * (half ? il1 : il0);
            __half h0 = __float2half_rn(v0);
            __half h1 = __float2half_rn(v1);
            union { __half b[2]; uint32_t u; } ph, pl;
            ph.b[0] = h0; ph.b[1] = h1;
            pl.b[0] = __float2half_rn(v0 - __half2float(h0));
            pl.b[1] = __float2half_rn(v1 - __half2float(h1));
            __half* row = g_A2 + ((size_t)b * TT + trow + half * 8) * K2;
            *(uint32_t*)&row[col]      = ph.u;
            *(uint32_t*)&row[col + DD] = pl.u;
        }
    }
}

// ---------------- launcher ----------------
extern "C" void kernel_launch(void* const* d_in, const int* in_sizes, int n_in,
                              void* d_out, int out_size) {
    const float* x     = (const float*)d_in[0];
    const float* Wqkv  = (const float*)d_in[1];
    const float* Wproj = (const float*)d_in[2];
    const int*   mask  = (const int*)d_in[3];
    float* out = (float*)d_out;

    cudaFuncSetAttribute(gemm_mma<0>, cudaFuncAttributeMaxDynamicSharedMemorySize, SMEM_GEMM_TOTAL);
    cudaFuncSetAttribute(gemm_mma<1>, cudaFuncAttributeMaxDynamicSharedMemorySize, SMEM_GEMM_TOTAL);
    cudaFuncSetAttribute(attn_mma_kernel, cudaFuncAttributeMaxDynamicSharedMemorySize, SMEM_ATTN_TOTAL);

    sctab_kernel<<<(TT * 64) / 256, 256>>>();
    lengths_kernel<<<BB, 256>>>(mask);
    conv2_kernel<0, 0><<<MROWS * 2, 256>>>(x);         // x    -> g_A2 [ah|al]
    conv2_kernel<1, 1><<<(3 * DD) * 2, 256>>>(Wqkv);   // Wqkv -> g_W2 [wh|wh]
    // all of QKV single-plane fp16 (K'=2048)
    gemm_mma<0><<<dim3(48, 64), 128, SMEM_GEMM_TOTAL>>>(nullptr, 0, 0, DD / 64);
    rope_split_kernel<<<(BB * HH * TT * 64) / 256, 256>>>();
    attn_mma_kernel<<<dim3(16, HH, BB), 256, SMEM_ATTN_TOTAL>>>();
    conv2_kernel<1, 1><<<DD * 2, 256>>>(Wproj);        // Wproj-> g_W2 [wh|wh]
    // proj: exact fp16x2 (K'=4096)
    gemm_mma<1><<<dim3(16, 64), 128, SMEM_GEMM_TOTAL>>>(out, DD, 0, K2 / 64);
}

// round 12
// speedup vs baseline: 9.2530x; 1.2031x over previous
#include <cuda_runtime.h>
#include <cuda_fp16.h>
#include <cstdint>
#include <math.h>

#define BB 4
#define TT 2048
#define DD 2048
#define HH 16
#define HDIM 128
#define MROWS (BB*TT)       /* 8192 */
#define K2 (2*DD)           /* 4096 row stride (only hi plane used now) */
#define PLANE_ELEMS ((size_t)BB*HH*TT*HDIM)   /* 16.8M */

// ---------------- scratch (device globals; uint4-backed => 16B align) ----------
__device__ uint4 g_q_raw  [PLANE_ELEMS/4];               // fp32 (B,H,T,hd)
__device__ uint4 g_k_raw  [PLANE_ELEMS/4];
__device__ uint4 g_A2_raw [(size_t)MROWS*K2/8];          // fp16, rows stride K2 (hi plane)
__device__ uint4 g_W2_raw [(size_t)(3*DD)*K2/8];         // fp16, rows stride K2 (hi plane)
__device__ uint4 g_qh_raw [PLANE_ELEMS/8];               // fp16 planes (attention)
__device__ uint4 g_kh_raw [PLANE_ELEMS/8];
__device__ uint4 g_vh_raw [PLANE_ELEMS/8];
__device__ float g_sin[TT*64];
__device__ float g_cos[TT*64];
__device__ int   g_len[BB];

// device-code-only views (never use in host code / kernel args)
#define g_q   ((float*)g_q_raw)
#define g_k   ((float*)g_k_raw)
#define g_A2  ((__half*)g_A2_raw)
#define g_W2  ((__half*)g_W2_raw)
#define g_qh  ((__half*)g_qh_raw)
#define g_kh  ((__half*)g_kh_raw)
#define g_vh  ((__half*)g_vh_raw)

// ============================ helpers ============================
__device__ __forceinline__ uint32_t smem_u32(const void* p) {
    uint32_t a;
    asm("{ .reg .u64 t; cvta.to.shared.u64 t, %1; cvt.u32.u64 %0, t; }" : "=r"(a) : "l"(p));
    return a;
}
__device__ __forceinline__ void cp16(uint32_t s, const void* g) {
    asm volatile("cp.async.cg.shared.global [%0], [%1], 16;" :: "r"(s), "l"(g));
}
__device__ __forceinline__ void ldmx4(uint32_t* r, uint32_t addr) {
    asm volatile("ldmatrix.sync.aligned.m8n8.x4.shared.b16 {%0,%1,%2,%3}, [%4];"
        : "=r"(r[0]), "=r"(r[1]), "=r"(r[2]), "=r"(r[3]) : "r"(addr));
}
__device__ __forceinline__ void ldmx4t(uint32_t* r, uint32_t addr) {
    asm volatile("ldmatrix.sync.aligned.m8n8.x4.trans.shared.b16 {%0,%1,%2,%3}, [%4];"
        : "=r"(r[0]), "=r"(r[1]), "=r"(r[2]), "=r"(r[3]) : "r"(addr));
}
__device__ __forceinline__ void mma16816h(float* d, const uint32_t* a, uint32_t b0, uint32_t b1) {
    asm volatile("mma.sync.aligned.m16n8k16.row.col.f32.f16.f16.f32 "
        "{%0,%1,%2,%3}, {%4,%5,%6,%7}, {%8,%9}, {%0,%1,%2,%3};"
        : "+f"(d[0]), "+f"(d[1]), "+f"(d[2]), "+f"(d[3])
        : "r"(a[0]), "r"(a[1]), "r"(a[2]), "r"(a[3]), "r"(b0), "r"(b1));
}
__device__ __forceinline__ uint32_t pack_h2(float lo, float hi) {
    union { __half2 h; uint32_t u; } t;
    t.h = __floats2half2_rn(lo, hi);
    return t.u;
}
#define SWZ8(c, r)  ((c) ^ ((r) & 7))

// ---------------- per-batch valid lengths ----------------
__global__ void lengths_kernel(const int* __restrict__ mask) {
    __shared__ int sd[256];
    int b = blockIdx.x;
    int s = 0;
    for (int i = threadIdx.x; i < TT; i += 256) s += mask[b * TT + i];
    sd[threadIdx.x] = s;
    __syncthreads();
    for (int st = 128; st > 0; st >>= 1) {
        if (threadIdx.x < st) sd[threadIdx.x] += sd[threadIdx.x + st];
        __syncthreads();
    }
    if (threadIdx.x == 0) g_len[b] = sd[0];
}

// ---------------- RoPE sin/cos table ----------------
__global__ void sctab_kernel() {
    int idx = blockIdx.x * 256 + threadIdx.x;      // TT*64
    int d = idx & 63, t = idx >> 6;
    float inv = (float)exp(-(double)(2 * d) / 128.0 * 9.210340371976184);
    float ang = (float)t * inv;
    float s, c;
    sincosf(ang, &s, &c);
    g_sin[idx] = s;
    g_cos[idx] = c;
}

// ---------------- fp32 -> fp16 (hi plane only, rows stride K2) ----------------
template <int DSTW>
__global__ __launch_bounds__(256) void conv1_kernel(const float* __restrict__ in) {
    __half* out = DSTW ? g_W2 : g_A2;
    int g = blockIdx.x * 256 + threadIdx.x;        // rows * 512
    int r = g >> 9, c4 = g & 511;
    float4 v = *(const float4*)(in + (size_t)r * DD + c4 * 4);
    union { __half b[4]; uint2 u; } hi;
    hi.b[0] = __float2half_rn(v.x); hi.b[1] = __float2half_rn(v.y);
    hi.b[2] = __float2half_rn(v.z); hi.b[3] = __float2half_rn(v.w);
    *(uint2*)(out + (size_t)r * K2 + c4 * 4) = hi.u;
}

// ---------------- HMMA fp16 GEMM (single plane, K=2048) ----------------
#define GSTAGE 32768
#define SMEM_GEMM_TOTAL (3*GSTAGE)      /* 98304 B */
#define GITERS (DD/64)                  /* 32 */

template <int MODE>
__global__ __launch_bounds__(128, 2) void gemm_mma(float* __restrict__ Cout, int N) {
    extern __shared__ __align__(16) char smraw[];
    const uint32_t sb = smem_u32(smraw);
    const int tid = threadIdx.x;
    const int bm = blockIdx.y * 128, bn = blockIdx.x * 128;
    const int warp = tid >> 5, lane = tid & 31;
    const int wm = warp >> 1, wn = warp & 1;

    float acc[32][4];
#pragma unroll
    for (int i = 0; i < 32; i++)
#pragma unroll
        for (int j = 0; j < 4; j++) acc[i][j] = 0.f;

    const int r0 = tid >> 3;                       // 0..15
    const int c0 = tid & 7;
    const uint32_t soA0 = r0 * 128 + SWZ8(c0, r0) * 16;
    const uint32_t soB0 = 16384 + soA0;
    const __half* pA = g_A2 + (size_t)(bm + r0) * K2 + c0 * 8;
    const __half* pB = g_W2 + (size_t)(bn + r0) * K2 + c0 * 8;

    auto load_stage = [&](uint32_t sbase) {
#pragma unroll
        for (int l = 0; l < 8; l++) {
            cp16(sbase + soA0 + l * 2048, pA + (size_t)l * 16 * K2);
            cp16(sbase + soB0 + l * 2048, pB + (size_t)l * 16 * K2);
        }
        asm volatile("cp.async.commit_group;" ::: "memory");
        pA += 64; pB += 64;
    };

    load_stage(sb);
    load_stage(sb + GSTAGE);

    const int lrow = (lane & 7) + 8 * ((lane >> 3) & 1);
    const int lch  = lane >> 4;
    uint32_t aro[4], bro[4];
#pragma unroll
    for (int mi = 0; mi < 4; mi++) {
        int row = wm * 64 + mi * 16 + lrow;
        aro[mi] = row * 128 + ((row & 7) << 4);
    }
#pragma unroll
    for (int n16 = 0; n16 < 4; n16++) {
        int nr = wn * 64 + n16 * 16 + lrow;
        bro[n16] = 16384 + nr * 128 + ((nr & 7) << 4);
    }

    for (int i = 0; i < GITERS; i += 3) {
#pragma unroll
        for (int u = 0; u < 3; u++) {
            const int idx = i + u;
            if (idx >= GITERS) break;
            if (idx >= GITERS - 2) asm volatile("cp.async.wait_group 0;" ::: "memory");
            else                   asm volatile("cp.async.wait_group 1;" ::: "memory");
            __syncthreads();
            if (idx + 2 < GITERS) load_stage(sb + ((u + 2) % 3) * GSTAGE);

            const uint32_t sa = sb + u * GSTAGE;
#pragma unroll
            for (int ks = 0; ks < 4; ks++) {
                const uint32_t chx = (uint32_t)(ks * 2 + lch) << 4;
                uint32_t a[4][4], b[4][4];
#pragma unroll
                for (int mi = 0; mi < 4; mi++)
                    ldmx4(a[mi], sa + (aro[mi] ^ chx));
#pragma unroll
                for (int n16 = 0; n16 < 4; n16++)
                    ldmx4(b[n16], sa + (bro[n16] ^ chx));
#pragma unroll
                for (int mi = 0; mi < 4; mi++)
#pragma unroll
                    for (int n16 = 0; n16 < 4; n16++) {
                        mma16816h(acc[mi * 8 + n16 * 2],     a[mi], b[n16][0], b[n16][2]);
                        mma16816h(acc[mi * 8 + n16 * 2 + 1], a[mi], b[n16][1], b[n16][3]);
                    }
            }
        }
    }

    // ---- epilogue ----
    if (MODE == 0) {
        const int which = bn >> 11;                // 0=q 1=k 2=v
        const int h = (bn >> 7) & 15;
        if (which == 2) {
#pragma unroll
            for (int mi = 0; mi < 4; mi++)
#pragma unroll
                for (int nn = 0; nn < 8; nn++) {
                    int d = wn * 64 + (nn >> 1) * 16 + (nn & 1) * 8 + (lane & 3) * 2;
#pragma unroll
                    for (int half = 0; half < 2; half++) {
                        int m = bm + wm * 64 + mi * 16 + (lane >> 2) + half * 8;
                        int b_ = m >> 11, t_ = m & (TT - 1);
                        size_t off = (((size_t)b_ * HH + h) * TT + t_) * HDIM + d;
                        *(uint32_t*)&g_vh[off] = pack_h2(acc[mi * 8 + nn][2 * half],
                                                         acc[mi * 8 + nn][2 * half + 1]);
                    }
                }
        } else {
            float* dst = (which == 0) ? g_q : g_k;
#pragma unroll
            for (int mi = 0; mi < 4; mi++)
#pragma unroll
                for (int nn = 0; nn < 8; nn++) {
                    int d = wn * 64 + (nn >> 1) * 16 + (nn & 1) * 8 + (lane & 3) * 2;
#pragma unroll
                    for (int half = 0; half < 2; half++) {
                        int m = bm + wm * 64 + mi * 16 + (lane >> 2) + half * 8;
                        int b_ = m >> 11, t_ = m & (TT - 1);
                        float2 v2 = make_float2(acc[mi * 8 + nn][2 * half],
                                                acc[mi * 8 + nn][2 * half + 1]);
                        *(float2*)&dst[(((size_t)b_ * HH + h) * TT + t_) * HDIM + d] = v2;
                    }
                }
        }
    } else {
#pragma unroll
        for (int mi = 0; mi < 4; mi++)
#pragma unroll
            for (int nn = 0; nn < 8; nn++) {
                int col = bn + wn * 64 + (nn >> 1) * 16 + (nn & 1) * 8 + (lane & 3) * 2;
#pragma unroll
                for (int half = 0; half < 2; half++) {
                    int m = bm + wm * 64 + mi * 16 + (lane >> 2) + half * 8;
                    float2 v2 = make_float2(acc[mi * 8 + nn][2 * half],
                                            acc[mi * 8 + nn][2 * half + 1]);
                    *(float2*)&Cout[(size_t)m * N + col] = v2;
                }
            }
    }
}

// ---------------- RoPE -> fp16 planes qh, kh ----------------
__global__ void rope_split_kernel() {
    int idx = blockIdx.x * blockDim.x + threadIdx.x;   // B*H*T*64
    int d  = idx & 63;
    int t  = (idx >> 6) & (TT - 1);
    int bh = idx >> 17;
    size_t base = ((size_t)bh * TT + t) * HDIM;
    int ti = (t << 6) + d;
    float s = g_sin[ti], c = g_cos[ti];

    float q1 = g_q[base + d], q2 = g_q[base + d + 64];
    float k1 = g_k[base + d], k2 = g_k[base + d + 64];
    g_qh[base + d]      = __float2half_rn(q1 * c - q2 * s);
    g_qh[base + d + 64] = __float2half_rn(q2 * c + q1 * s);
    g_kh[base + d]      = __float2half_rn(k1 * c - k2 * s);
    g_kh[base + d + 64] = __float2half_rn(k2 * c + k1 * s);
}

// ---------------- fp16 flash attention: BQ=128, BKV=64, 8 warps ----------------
// S = Qh*Kh (1 term); O = (Ph+Pl)*Vh (2 terms, exact P split)
#define AQ_OFF   0
#define AKV_OFF  32768
#define AKV_STG  32768
#define SMEM_ATTN_TOTAL (32768 + 2*32768)   /* 98304 */

__global__ __launch_bounds__(256) void attn_mma_kernel() {
    extern __shared__ __align__(16) char smraw[];
    const uint32_t sb = smem_u32(smraw);
    const int tid = threadIdx.x;
    const int warp = tid >> 5, lane = tid & 31;
    const int qt = 15 - blockIdx.x;                 // descending work order
    const int h = blockIdx.y, b = blockIdx.z;
    const int L = g_len[b];
    const size_t bhT = ((size_t)b * HH + h) * TT;

    const int lrow = (lane & 7) + 8 * ((lane >> 3) & 1);
    const int lch  = lane >> 4;

    // ---- load Q tile (qh only), own commit group ----
    {
#pragma unroll
        for (int l = 0; l < 8; l++) {
            int idx = tid + l * 256;                // 2048 chunks
            int row = idx >> 4, c = idx & 15;
            cp16(sb + AQ_OFF + row * 256 + SWZ8(c, row) * 16,
                 g_qh + (bhT + (size_t)qt * 128 + row) * HDIM + c * 8);
        }
        asm volatile("cp.async.commit_group;" ::: "memory");
    }

    const int nt = (min(qt * 128 + 128, L) + 63) / 64;

    auto load_kv = [&](int kt, int stg) {
        const __half* pp[2];
        pp[0] = g_kh; pp[1] = g_vh;
        uint32_t base = sb + AKV_OFF + stg * AKV_STG;
#pragma unroll
        for (int l = 0; l < 8; l++) {
            int idx = tid + l * 256;                // 2048 chunks
            int pl = idx >> 10, rem = idx & 1023;
            int row = rem >> 4, c = rem & 15;
            cp16(base + pl * 16384 + row * 256 + SWZ8(c, row) * 16,
                 pp[pl] + (bhT + (size_t)kt * 64 + row) * HDIM + c * 8);
        }
        asm volatile("cp.async.commit_group;" ::: "memory");
    };
    load_kv(0, 0);

    // ---- hoist Q fragments (wait only for the Q group) ----
    uint32_t qhf[8][4];
    {
        asm volatile("cp.async.wait_group 1;" ::: "memory");
        __syncthreads();
        const uint32_t qh = sb + AQ_OFF;
        const int arow = warp * 16 + lrow;
#pragma unroll
        for (int k16 = 0; k16 < 8; k16++) {
            const int ch = k16 * 2 + lch;
            ldmx4(qhf[k16], qh + arow * 256 + SWZ8(ch, arow) * 16);
        }
    }

    float oacc[16][4];
#pragma unroll
    for (int i = 0; i < 16; i++)
#pragma unroll
        for (int j = 0; j < 4; j++) oacc[i][j] = 0.f;
    float m0 = -1e30f, m1 = -1e30f, l0 = 0.f, l1 = 0.f;

    const int wr = qt * 128 + warp * 16;
    const float scl = 0.08838834764831843f;

    for (int kt = 0; kt < nt; kt++) {
        asm volatile("cp.async.wait_group 0;" ::: "memory");
        __syncthreads();
        if (kt + 1 < nt) load_kv(kt + 1, (kt + 1) & 1);

        const uint32_t kh = sb + AKV_OFF + (kt & 1) * AKV_STG;
        const uint32_t vh = kh + 16384;

        // ---- S = Qh*Kh ----
        float sacc[8][4];
#pragma unroll
        for (int i = 0; i < 8; i++)
#pragma unroll
            for (int j = 0; j < 4; j++) sacc[i][j] = 0.f;

#pragma unroll
        for (int k16 = 0; k16 < 8; k16++) {
            const int ch = k16 * 2 + lch;
#pragma unroll
            for (int n16 = 0; n16 < 4; n16++) {
                const int nr = n16 * 16 + lrow;
                uint32_t bh[4];
                ldmx4(bh, kh + nr * 256 + SWZ8(ch, nr) * 16);
                mma16816h(sacc[2*n16],   qhf[k16], bh[0], bh[2]);
                mma16816h(sacc[2*n16+1], qhf[k16], bh[1], bh[3]);
            }
        }

        // ---- mask + online softmax ----
        const bool needmask = ((kt + 1) * 64 > qt * 128) || ((kt + 1) * 64 > L);
        const int r0g = wr + (lane >> 2);
#pragma unroll
        for (int f = 0; f < 8; f++)
#pragma unroll
            for (int c = 0; c < 4; c++) {
                float x = sacc[f][c] * scl;
                if (needmask) {
                    int col = kt * 64 + f * 8 + ((lane & 3) << 1) + (c & 1);
                    int rg = r0g + ((c >> 1) << 3);
                    if (col > rg || col >= L) x = -1e30f;
                }
                sacc[f][c] = x;
            }
        float mx0 = -1e30f, mx1 = -1e30f;
#pragma unroll
        for (int f = 0; f < 8; f++) {
            mx0 = fmaxf(mx0, fmaxf(sacc[f][0], sacc[f][1]));
            mx1 = fmaxf(mx1, fmaxf(sacc[f][2], sacc[f][3]));
        }
        mx0 = fmaxf(mx0, __shfl_xor_sync(0xffffffffu, mx0, 1));
        mx0 = fmaxf(mx0, __shfl_xor_sync(0xffffffffu, mx0, 2));
        mx1 = fmaxf(mx1, __shfl_xor_sync(0xffffffffu, mx1, 1));
        mx1 = fmaxf(mx1, __shfl_xor_sync(0xffffffffu, mx1, 2));
        float mn0 = fmaxf(m0, mx0), mn1 = fmaxf(m1, mx1);
        float corr0 = __expf(m0 - mn0), corr1 = __expf(m1 - mn1);
        float sum0 = 0.f, sum1 = 0.f;
#pragma unroll
        for (int f = 0; f < 8; f++) {
            float p;
            p = __expf(sacc[f][0] - mn0); sacc[f][0] = p; sum0 += p;
            p = __expf(sacc[f][1] - mn0); sacc[f][1] = p; sum0 += p;
            p = __expf(sacc[f][2] - mn1); sacc[f][2] = p; sum1 += p;
            p = __expf(sacc[f][3] - mn1); sacc[f][3] = p; sum1 += p;
        }
        sum0 += __shfl_xor_sync(0xffffffffu, sum0, 1);
        sum0 += __shfl_xor_sync(0xffffffffu, sum0, 2);
        sum1 += __shfl_xor_sync(0xffffffffu, sum1, 1);
        sum1 += __shfl_xor_sync(0xffffffffu, sum1, 2);
        l0 = l0 * corr0 + sum0; m0 = mn0;
        l1 = l1 * corr1 + sum1; m1 = mn1;
#pragma unroll
        for (int nf = 0; nf < 16; nf++) {
            oacc[nf][0] *= corr0; oacc[nf][1] *= corr0;
            oacc[nf][2] *= corr1; oacc[nf][3] *= corr1;
        }

        // ---- O += Ph*Vh + Pl*Vh (exact P split) ----
#pragma unroll
        for (int j16 = 0; j16 < 4; j16++) {
            const int f0 = 2 * j16, f1 = 2 * j16 + 1;
            uint32_t aPh[4], aPl[4];
            {
                float p00 = sacc[f0][0], p01 = sacc[f0][1];
                float p02 = sacc[f0][2], p03 = sacc[f0][3];
                float p10 = sacc[f1][0], p11 = sacc[f1][1];
                float p12 = sacc[f1][2], p13 = sacc[f1][3];
                aPh[0] = pack_h2(p00, p01);
                aPh[1] = pack_h2(p02, p03);
                aPh[2] = pack_h2(p10, p11);
                aPh[3] = pack_h2(p12, p13);
                union { uint32_t u; __half2 h2; } t;
                float r00, r01, r02, r03, r10, r11, r12, r13;
                t.u = aPh[0]; r00 = p00 - __half2float(t.h2.x); r01 = p01 - __half2float(t.h2.y);
                t.u = aPh[1]; r02 = p02 - __half2float(t.h2.x); r03 = p03 - __half2float(t.h2.y);
                t.u = aPh[2]; r10 = p10 - __half2float(t.h2.x); r11 = p11 - __half2float(t.h2.y);
                t.u = aPh[3]; r12 = p12 - __half2float(t.h2.x); r13 = p13 - __half2float(t.h2.y);
                aPl[0] = pack_h2(r00, r01);
                aPl[1] = pack_h2(r02, r03);
                aPl[2] = pack_h2(r10, r11);
                aPl[3] = pack_h2(r12, r13);
            }
#pragma unroll
            for (int d16 = 0; d16 < 8; d16++) {
                const int ch = d16 * 2 + lch;
                const int vr = j16 * 16 + lrow;
                uint32_t bvh[4];
                ldmx4t(bvh, vh + vr * 256 + SWZ8(ch, vr) * 16);
                mma16816h(oacc[2*d16],   aPh, bvh[0], bvh[1]);
                mma16816h(oacc[2*d16+1], aPh, bvh[2], bvh[3]);
                mma16816h(oacc[2*d16],   aPl, bvh[0], bvh[1]);
                mma16816h(oacc[2*d16+1], aPl, bvh[2], bvh[3]);
            }
        }
        __syncthreads();
    }

    // ---- epilogue: write hi plane into g_A2 ----
    const float il0 = 1.f / l0, il1 = 1.f / l1;
    const int trow = qt * 128 + warp * 16 + (lane >> 2);
#pragma unroll
    for (int nf = 0; nf < 16; nf++) {
        int col = h * 128 + nf * 8 + (lane & 3) * 2;
#pragma unroll
        for (int half = 0; half < 2; half++) {
            float v0 = oacc[nf][2 * half]     * (half ? il1 : il0);
            float v1 = oacc[nf][2 * half + 1] * (half ? il1 : il0);
            __half* row = g_A2 + ((size_t)b * TT + trow + half * 8) * K2;
            *(uint32_t*)&row[col] = pack_h2(v0, v1);
        }
    }
}

// ---------------- launcher ----------------
extern "C" void kernel_launch(void* const* d_in, const int* in_sizes, int n_in,
                              void* d_out, int out_size) {
    const float* x     = (const float*)d_in[0];
    const float* Wqkv  = (const float*)d_in[1];
    const float* Wproj = (const float*)d_in[2];
    const int*   mask  = (const int*)d_in[3];
    float* out = (float*)d_out;

    cudaFuncSetAttribute(gemm_mma<0>, cudaFuncAttributeMaxDynamicSharedMemorySize, SMEM_GEMM_TOTAL);
    cudaFuncSetAttribute(gemm_mma<1>, cudaFuncAttributeMaxDynamicSharedMemorySize, SMEM_GEMM_TOTAL);
    cudaFuncSetAttribute(attn_mma_kernel, cudaFuncAttributeMaxDynamicSharedMemorySize, SMEM_ATTN_TOTAL);

    sctab_kernel<<<(TT * 64) / 256, 256>>>();
    lengths_kernel<<<BB, 256>>>(mask);
    conv1_kernel<0><<<MROWS * 2, 256>>>(x);            // x     -> g_A2 hi
    conv1_kernel<1><<<(3 * DD) * 2, 256>>>(Wqkv);      // Wqkv  -> g_W2 hi
    gemm_mma<0><<<dim3(48, 64), 128, SMEM_GEMM_TOTAL>>>(nullptr, 0);
    rope_split_kernel<<<(BB * HH * TT * 64) / 256, 256>>>();
    attn_mma_kernel<<<dim3(16, HH, BB), 256, SMEM_ATTN_TOTAL>>>();
    conv1_kernel<1><<<DD * 2, 256>>>(Wproj);           // Wproj -> g_W2 hi
    gemm_mma<1><<<dim3(16, 64), 128, SMEM_GEMM_TOTAL>>>(out, DD);
}

// round 13
// speedup vs baseline: 9.4160x; 1.0176x over previous
#include <cuda_runtime.h>
#include <cuda_fp16.h>
#include <cstdint>
#include <math.h>

#define BB 4
#define TT 2048
#define DD 2048
#define HH 16
#define HDIM 128
#define MROWS (BB*TT)       /* 8192 */
#define K2 (2*DD)           /* 4096 row stride (hi plane only) */
#define PLANE_ELEMS ((size_t)BB*HH*TT*HDIM)   /* 16.8M */

// ---------------- scratch (device globals; uint4-backed => 16B align) ----------
__device__ uint4 g_A2_raw [(size_t)MROWS*K2/8];          // fp16, rows stride K2
__device__ uint4 g_W2_raw [(size_t)(3*DD)*K2/8];         // fp16, rows stride K2
__device__ uint4 g_qh_raw [PLANE_ELEMS/8];               // fp16 planes (attention)
__device__ uint4 g_kh_raw [PLANE_ELEMS/8];
__device__ uint4 g_vh_raw [PLANE_ELEMS/8];
__device__ float g_sin[TT*64];
__device__ float g_cos[TT*64];
__device__ int   g_len[BB];

// device-code-only views (never use in host code / kernel args)
#define g_A2  ((__half*)g_A2_raw)
#define g_W2  ((__half*)g_W2_raw)
#define g_qh  ((__half*)g_qh_raw)
#define g_kh  ((__half*)g_kh_raw)
#define g_vh  ((__half*)g_vh_raw)

// ============================ helpers ============================
__device__ __forceinline__ uint32_t smem_u32(const void* p) {
    uint32_t a;
    asm("{ .reg .u64 t; cvta.to.shared.u64 t, %1; cvt.u32.u64 %0, t; }" : "=r"(a) : "l"(p));
    return a;
}
__device__ __forceinline__ void cp16(uint32_t s, const void* g) {
    asm volatile("cp.async.cg.shared.global [%0], [%1], 16;" :: "r"(s), "l"(g));
}
__device__ __forceinline__ void ldmx4(uint32_t* r, uint32_t addr) {
    asm volatile("ldmatrix.sync.aligned.m8n8.x4.shared.b16 {%0,%1,%2,%3}, [%4];"
        : "=r"(r[0]), "=r"(r[1]), "=r"(r[2]), "=r"(r[3]) : "r"(addr));
}
__device__ __forceinline__ void ldmx4t(uint32_t* r, uint32_t addr) {
    asm volatile("ldmatrix.sync.aligned.m8n8.x4.trans.shared.b16 {%0,%1,%2,%3}, [%4];"
        : "=r"(r[0]), "=r"(r[1]), "=r"(r[2]), "=r"(r[3]) : "r"(addr));
}
__device__ __forceinline__ void mma16816h(float* d, const uint32_t* a, uint32_t b0, uint32_t b1) {
    asm volatile("mma.sync.aligned.m16n8k16.row.col.f32.f16.f16.f32 "
        "{%0,%1,%2,%3}, {%4,%5,%6,%7}, {%8,%9}, {%0,%1,%2,%3};"
        : "+f"(d[0]), "+f"(d[1]), "+f"(d[2]), "+f"(d[3])
        : "r"(a[0]), "r"(a[1]), "r"(a[2]), "r"(a[3]), "r"(b0), "r"(b1));
}
__device__ __forceinline__ uint32_t pack_h2(float lo, float hi) {
    union { __half2 h; uint32_t u; } t;
    t.h = __floats2half2_rn(lo, hi);
    return t.u;
}
#define SWZ8(c, r)  ((c) ^ ((r) & 7))

// ---------------- per-batch valid lengths ----------------
__global__ void lengths_kernel(const int* __restrict__ mask) {
    __shared__ int sd[256];
    int b = blockIdx.x;
    int s = 0;
    for (int i = threadIdx.x; i < TT; i += 256) s += mask[b * TT + i];
    sd[threadIdx.x] = s;
    __syncthreads();
    for (int st = 128; st > 0; st >>= 1) {
        if (threadIdx.x < st) sd[threadIdx.x] += sd[threadIdx.x + st];
        __syncthreads();
    }
    if (threadIdx.x == 0) g_len[b] = sd[0];
}

// ---------------- RoPE sin/cos table ----------------
__global__ void sctab_kernel() {
    int idx = blockIdx.x * 256 + threadIdx.x;      // TT*64
    int d = idx & 63, t = idx >> 6;
    float inv = (float)exp(-(double)(2 * d) / 128.0 * 9.210340371976184);
    float ang = (float)t * inv;
    float s, c;
    sincosf(ang, &s, &c);
    g_sin[idx] = s;
    g_cos[idx] = c;
}

// ---------------- fp32 -> fp16 (hi plane, rows stride K2) ----------------
template <int DSTW>
__global__ __launch_bounds__(256) void conv1_kernel(const float* __restrict__ in) {
    __half* out = DSTW ? g_W2 : g_A2;
    int g = blockIdx.x * 256 + threadIdx.x;        // rows * 512
    int r = g >> 9, c4 = g & 511;
    float4 v = *(const float4*)(in + (size_t)r * DD + c4 * 4);
    union { __half b[4]; uint2 u; } hi;
    hi.b[0] = __float2half_rn(v.x); hi.b[1] = __float2half_rn(v.y);
    hi.b[2] = __float2half_rn(v.z); hi.b[3] = __float2half_rn(v.w);
    *(uint2*)(out + (size_t)r * K2 + c4 * 4) = hi.u;
}

// ---------------- HMMA fp16 GEMM (single plane, K=2048) ----------------
// MODE 0: QKV. q/k epilogue fuses RoPE (smem stage + rotate + fp16 planes);
//          v epilogue writes fp16 plane; k/v tiles beyond valid length skipped.
// MODE 1: proj, fp32 out.
#define GSTAGE 32768
#define SMEM_GEMM_TOTAL (3*GSTAGE)      /* 98304 B */
#define GITERS (DD/64)                  /* 32 */

template <int MODE>
__global__ __launch_bounds__(128, 2) void gemm_mma(float* __restrict__ Cout, int N) {
    extern __shared__ __align__(16) char smraw[];
    const uint32_t sb = smem_u32(smraw);
    const int tid = threadIdx.x;
    const int bm = blockIdx.y * 128, bn = blockIdx.x * 128;
    const int warp = tid >> 5, lane = tid & 31;
    const int wm = warp >> 1, wn = warp & 1;

    if (MODE == 0) {
        // dead k/v tiles: rows beyond valid length are never read by attention
        const int which = bn >> 11;
        if (which >= 1 && (bm & (TT - 1)) >= g_len[bm >> 11]) return;
    }

    float acc[32][4];
#pragma unroll
    for (int i = 0; i < 32; i++)
#pragma unroll
        for (int j = 0; j < 4; j++) acc[i][j] = 0.f;

    const int r0 = tid >> 3;                       // 0..15
    const int c0 = tid & 7;
    const uint32_t soA0 = r0 * 128 + SWZ8(c0, r0) * 16;
    const uint32_t soB0 = 16384 + soA0;
    const __half* pA = g_A2 + (size_t)(bm + r0) * K2 + c0 * 8;
    const __half* pB = g_W2 + (size_t)(bn + r0) * K2 + c0 * 8;

    auto load_stage = [&](uint32_t sbase) {
#pragma unroll
        for (int l = 0; l < 8; l++) {
            cp16(sbase + soA0 + l * 2048, pA + (size_t)l * 16 * K2);
            cp16(sbase + soB0 + l * 2048, pB + (size_t)l * 16 * K2);
        }
        asm volatile("cp.async.commit_group;" ::: "memory");
        pA += 64; pB += 64;
    };

    load_stage(sb);
    load_stage(sb + GSTAGE);

    const int lrow = (lane & 7) + 8 * ((lane >> 3) & 1);
    const int lch  = lane >> 4;
    uint32_t aro[4], bro[4];
#pragma unroll
    for (int mi = 0; mi < 4; mi++) {
        int row = wm * 64 + mi * 16 + lrow;
        aro[mi] = row * 128 + ((row & 7) << 4);
    }
#pragma unroll
    for (int n16 = 0; n16 < 4; n16++) {
        int nr = wn * 64 + n16 * 16 + lrow;
        bro[n16] = 16384 + nr * 128 + ((nr & 7) << 4);
    }

    for (int i = 0; i < GITERS; i += 3) {
#pragma unroll
        for (int u = 0; u < 3; u++) {
            const int idx = i + u;
            if (idx >= GITERS) break;
            if (idx >= GITERS - 2) asm volatile("cp.async.wait_group 0;" ::: "memory");
            else                   asm volatile("cp.async.wait_group 1;" ::: "memory");
            __syncthreads();
            if (idx + 2 < GITERS) load_stage(sb + ((u + 2) % 3) * GSTAGE);

            const uint32_t sa = sb + u * GSTAGE;
#pragma unroll
            for (int ks = 0; ks < 4; ks++) {
                const uint32_t chx = (uint32_t)(ks * 2 + lch) << 4;
                uint32_t a[4][4], b[4][4];
#pragma unroll
                for (int mi = 0; mi < 4; mi++)
                    ldmx4(a[mi], sa + (aro[mi] ^ chx));
#pragma unroll
                for (int n16 = 0; n16 < 4; n16++)
                    ldmx4(b[n16], sa + (bro[n16] ^ chx));
#pragma unroll
                for (int mi = 0; mi < 4; mi++)
#pragma unroll
                    for (int n16 = 0; n16 < 4; n16++) {
                        mma16816h(acc[mi * 8 + n16 * 2],     a[mi], b[n16][0], b[n16][2]);
                        mma16816h(acc[mi * 8 + n16 * 2 + 1], a[mi], b[n16][1], b[n16][3]);
                    }
            }
        }
    }

    // ---- epilogue ----
    if (MODE == 0) {
        const int which = bn >> 11;                // 0=q 1=k 2=v
        const int h = (bn >> 7) & 15;
        if (which == 2) {
#pragma unroll
            for (int mi = 0; mi < 4; mi++)
#pragma unroll
                for (int nn = 0; nn < 8; nn++) {
                    int d = wn * 64 + (nn >> 1) * 16 + (nn & 1) * 8 + (lane & 3) * 2;
#pragma unroll
                    for (int half = 0; half < 2; half++) {
                        int m = bm + wm * 64 + mi * 16 + (lane >> 2) + half * 8;
                        int b_ = m >> 11, t_ = m & (TT - 1);
                        size_t off = (((size_t)b_ * HH + h) * TT + t_) * HDIM + d;
                        *(uint32_t*)&g_vh[off] = pack_h2(acc[mi * 8 + nn][2 * half],
                                                         acc[mi * 8 + nn][2 * half + 1]);
                    }
                }
        } else {
            // fused RoPE: stage fp32 tile in smem (pitch 130), rotate, write fp16
            __syncthreads();                       // mainloop smem reads done
            float* smf = (float*)smraw;
#pragma unroll
            for (int mi = 0; mi < 4; mi++)
#pragma unroll
                for (int nn = 0; nn < 8; nn++) {
                    int c = wn * 64 + (nn >> 1) * 16 + (nn & 1) * 8 + (lane & 3) * 2;
#pragma unroll
                    for (int half = 0; half < 2; half++) {
                        int r = wm * 64 + mi * 16 + (lane >> 2) + half * 8;
                        smf[r * 130 + c]     = acc[mi * 8 + nn][2 * half];
                        smf[r * 130 + c + 1] = acc[mi * 8 + nn][2 * half + 1];
                    }
                }
            __syncthreads();
            __half* dst = (which == 0) ? g_qh : g_kh;
            const int d = tid & 63;
            const int rh = tid >> 6;               // 0..1
            const int b_ = bm >> 11;
#pragma unroll 4
            for (int rr = 0; rr < 64; rr++) {
                int r = rh * 64 + rr;
                int t_ = (bm + r) & (TT - 1);
                int ti = (t_ << 6) + d;
                float s = g_sin[ti], c = g_cos[ti];
                float v1 = smf[r * 130 + d];
                float v2 = smf[r * 130 + d + 64];
                size_t off = (((size_t)b_ * HH + h) * TT + t_) * HDIM;
                dst[off + d]      = __float2half_rn(v1 * c - v2 * s);
                dst[off + d + 64] = __float2half_rn(v2 * c + v1 * s);
            }
        }
    } else {
#pragma unroll
        for (int mi = 0; mi < 4; mi++)
#pragma unroll
            for (int nn = 0; nn < 8; nn++) {
                int col = bn + wn * 64 + (nn >> 1) * 16 + (nn & 1) * 8 + (lane & 3) * 2;
#pragma unroll
                for (int half = 0; half < 2; half++) {
                    int m = bm + wm * 64 + mi * 16 + (lane >> 2) + half * 8;
                    float2 v2 = make_float2(acc[mi * 8 + nn][2 * half],
                                            acc[mi * 8 + nn][2 * half + 1]);
                    *(float2*)&Cout[(size_t)m * N + col] = v2;
                }
            }
    }
}

// ---------------- fp16 flash attention: BQ=128, BKV=64, 8 warps ----------------
// S = Qh*Kh (1 term); O = (Ph+Pl)*Vh (2 terms, exact P split)
#define AQ_OFF   0
#define AKV_OFF  32768
#define AKV_STG  32768
#define SMEM_ATTN_TOTAL (32768 + 2*32768)   /* 98304 */

__global__ __launch_bounds__(256) void attn_mma_kernel() {
    extern __shared__ __align__(16) char smraw[];
    const uint32_t sb = smem_u32(smraw);
    const int tid = threadIdx.x;
    const int warp = tid >> 5, lane = tid & 31;
    const int qt = 15 - blockIdx.x;                 // descending work order
    const int h = blockIdx.y, b = blockIdx.z;
    const int L = g_len[b];
    const size_t bhT = ((size_t)b * HH + h) * TT;

    const int lrow = (lane & 7) + 8 * ((lane >> 3) & 1);
    const int lch  = lane >> 4;

    // ---- load Q tile (qh only), own commit group ----
    {
#pragma unroll
        for (int l = 0; l < 8; l++) {
            int idx = tid + l * 256;                // 2048 chunks
            int row = idx >> 4, c = idx & 15;
            cp16(sb + AQ_OFF + row * 256 + SWZ8(c, row) * 16,
                 g_qh + (bhT + (size_t)qt * 128 + row) * HDIM + c * 8);
        }
        asm volatile("cp.async.commit_group;" ::: "memory");
    }

    const int nt = (min(qt * 128 + 128, L) + 63) / 64;

    auto load_kv = [&](int kt, int stg) {
        const __half* pp[2];
        pp[0] = g_kh; pp[1] = g_vh;
        uint32_t base = sb + AKV_OFF + stg * AKV_STG;
#pragma unroll
        for (int l = 0; l < 8; l++) {
            int idx = tid + l * 256;                // 2048 chunks
            int pl = idx >> 10, rem = idx & 1023;
            int row = rem >> 4, c = rem & 15;
            cp16(base + pl * 16384 + row * 256 + SWZ8(c, row) * 16,
                 pp[pl] + (bhT + (size_t)kt * 64 + row) * HDIM + c * 8);
        }
        asm volatile("cp.async.commit_group;" ::: "memory");
    };
    load_kv(0, 0);

    // ---- hoist Q fragments (wait only for the Q group) ----
    uint32_t qhf[8][4];
    {
        asm volatile("cp.async.wait_group 1;" ::: "memory");
        __syncthreads();
        const uint32_t qh = sb + AQ_OFF;
        const int arow = warp * 16 + lrow;
#pragma unroll
        for (int k16 = 0; k16 < 8; k16++) {
            const int ch = k16 * 2 + lch;
            ldmx4(qhf[k16], qh + arow * 256 + SWZ8(ch, arow) * 16);
        }
    }

    float oacc[16][4];
#pragma unroll
    for (int i = 0; i < 16; i++)
#pragma unroll
        for (int j = 0; j < 4; j++) oacc[i][j] = 0.f;
    float m0 = -1e30f, m1 = -1e30f, l0 = 0.f, l1 = 0.f;

    const int wr = qt * 128 + warp * 16;
    const float scl = 0.08838834764831843f;

    for (int kt = 0; kt < nt; kt++) {
        asm volatile("cp.async.wait_group 0;" ::: "memory");
        __syncthreads();
        if (kt + 1 < nt) load_kv(kt + 1, (kt + 1) & 1);

        const uint32_t kh = sb + AKV_OFF + (kt & 1) * AKV_STG;
        const uint32_t vh = kh + 16384;

        // ---- S = Qh*Kh ----
        float sacc[8][4];
#pragma unroll
        for (int i = 0; i < 8; i++)
#pragma unroll
            for (int j = 0; j < 4; j++) sacc[i][j] = 0.f;

#pragma unroll
        for (int k16 = 0; k16 < 8; k16++) {
            const int ch = k16 * 2 + lch;
#pragma unroll
            for (int n16 = 0; n16 < 4; n16++) {
                const int nr = n16 * 16 + lrow;
                uint32_t bh[4];
                ldmx4(bh, kh + nr * 256 + SWZ8(ch, nr) * 16);
                mma16816h(sacc[2*n16],   qhf[k16], bh[0], bh[2]);
                mma16816h(sacc[2*n16+1], qhf[k16], bh[1], bh[3]);
            }
        }

        // ---- mask + online softmax ----
        const bool needmask = ((kt + 1) * 64 > qt * 128) || ((kt + 1) * 64 > L);
        const int r0g = wr + (lane >> 2);
#pragma unroll
        for (int f = 0; f < 8; f++)
#pragma unroll
            for (int c = 0; c < 4; c++) {
                float x = sacc[f][c] * scl;
                if (needmask) {
                    int col = kt * 64 + f * 8 + ((lane & 3) << 1) + (c & 1);
                    int rg = r0g + ((c >> 1) << 3);
                    if (col > rg || col >= L) x = -1e30f;
                }
                sacc[f][c] = x;
            }
        float mx0 = -1e30f, mx1 = -1e30f;
#pragma unroll
        for (int f = 0; f < 8; f++) {
            mx0 = fmaxf(mx0, fmaxf(sacc[f][0], sacc[f][1]));
            mx1 = fmaxf(mx1, fmaxf(sacc[f][2], sacc[f][3]));
        }
        mx0 = fmaxf(mx0, __shfl_xor_sync(0xffffffffu, mx0, 1));
        mx0 = fmaxf(mx0, __shfl_xor_sync(0xffffffffu, mx0, 2));
        mx1 = fmaxf(mx1, __shfl_xor_sync(0xffffffffu, mx1, 1));
        mx1 = fmaxf(mx1, __shfl_xor_sync(0xffffffffu, mx1, 2));
        float mn0 = fmaxf(m0, mx0), mn1 = fmaxf(m1, mx1);
        float corr0 = __expf(m0 - mn0), corr1 = __expf(m1 - mn1);
        float sum0 = 0.f, sum1 = 0.f;
#pragma unroll
        for (int f = 0; f < 8; f++) {
            float p;
            p = __expf(sacc[f][0] - mn0); sacc[f][0] = p; sum0 += p;
            p = __expf(sacc[f][1] - mn0); sacc[f][1] = p; sum0 += p;
            p = __expf(sacc[f][2] - mn1); sacc[f][2] = p; sum1 += p;
            p = __expf(sacc[f][3] - mn1); sacc[f][3] = p; sum1 += p;
        }
        sum0 += __shfl_xor_sync(0xffffffffu, sum0, 1);
        sum0 += __shfl_xor_sync(0xffffffffu, sum0, 2);
        sum1 += __shfl_xor_sync(0xffffffffu, sum1, 1);
        sum1 += __shfl_xor_sync(0xffffffffu, sum1, 2);
        l0 = l0 * corr0 + sum0; m0 = mn0;
        l1 = l1 * corr1 + sum1; m1 = mn1;
#pragma unroll
        for (int nf = 0; nf < 16; nf++) {
            oacc[nf][0] *= corr0; oacc[nf][1] *= corr0;
            oacc[nf][2] *= corr1; oacc[nf][3] *= corr1;
        }

        // ---- O += Ph*Vh + Pl*Vh (exact P split) ----
#pragma unroll
        for (int j16 = 0; j16 < 4; j16++) {
            const int f0 = 2 * j16, f1 = 2 * j16 + 1;
            uint32_t aPh[4], aPl[4];
            {
                float p00 = sacc[f0][0], p01 = sacc[f0][1];
                float p02 = sacc[f0][2], p03 = sacc[f0][3];
                float p10 = sacc[f1][0], p11 = sacc[f1][1];
                float p12 = sacc[f1][2], p13 = sacc[f1][3];
                aPh[0] = pack_h2(p00, p01);
                aPh[1] = pack_h2(p02, p03);
                aPh[2] = pack_h2(p10, p11);
                aPh[3] = pack_h2(p12, p13);
                union { uint32_t u; __half2 h2; } t;
                float r00, r01, r02, r03, r10, r11, r12, r13;
                t.u = aPh[0]; r00 = p00 - __half2float(t.h2.x); r01 = p01 - __half2float(t.h2.y);
                t.u = aPh[1]; r02 = p02 - __half2float(t.h2.x); r03 = p03 - __half2float(t.h2.y);
                t.u = aPh[2]; r10 = p10 - __half2float(t.h2.x); r11 = p11 - __half2float(t.h2.y);
                t.u = aPh[3]; r12 = p12 - __half2float(t.h2.x); r13 = p13 - __half2float(t.h2.y);
                aPl[0] = pack_h2(r00, r01);
                aPl[1] = pack_h2(r02, r03);
                aPl[2] = pack_h2(r10, r11);
                aPl[3] = pack_h2(r12, r13);
            }
#pragma unroll
            for (int d16 = 0; d16 < 8; d16++) {
                const int ch = d16 * 2 + lch;
                const int vr = j16 * 16 + lrow;
                uint32_t bvh[4];
                ldmx4t(bvh, vh + vr * 256 + SWZ8(ch, vr) * 16);
                mma16816h(oacc[2*d16],   aPh, bvh[0], bvh[1]);
                mma16816h(oacc[2*d16+1], aPh, bvh[2], bvh[3]);
                mma16816h(oacc[2*d16],   aPl, bvh[0], bvh[1]);
                mma16816h(oacc[2*d16+1], aPl, bvh[2], bvh[3]);
            }
        }
        __syncthreads();
    }

    // ---- epilogue: write hi plane into g_A2 ----
    const float il0 = 1.f / l0, il1 = 1.f / l1;
    const int trow = qt * 128 + warp * 16 + (lane >> 2);
#pragma unroll
    for (int nf = 0; nf < 16; nf++) {
        int col = h * 128 + nf * 8 + (lane & 3) * 2;
#pragma unroll
        for (int half = 0; half < 2; half++) {
            float v0 = oacc[nf][2 * half]     * (half ? il1 : il0);
            float v1 = oacc[nf][2 * half + 1] * (half ? il1 : il0);
            __half* row = g_A2 + ((size_t)b * TT + trow + half * 8) * K2;
            *(uint32_t*)&row[col] = pack_h2(v0, v1);
        }
    }
}

// ---------------- launcher ----------------
extern "C" void kernel_launch(void* const* d_in, const int* in_sizes, int n_in,
                              void* d_out, int out_size) {
    const float* x     = (const float*)d_in[0];
    const float* Wqkv  = (const float*)d_in[1];
    const float* Wproj = (const float*)d_in[2];
    const int*   mask  = (const int*)d_in[3];
    float* out = (float*)d_out;

    cudaFuncSetAttribute(gemm_mma<0>, cudaFuncAttributeMaxDynamicSharedMemorySize, SMEM_GEMM_TOTAL);
    cudaFuncSetAttribute(gemm_mma<1>, cudaFuncAttributeMaxDynamicSharedMemorySize, SMEM_GEMM_TOTAL);
    cudaFuncSetAttribute(attn_mma_kernel, cudaFuncAttributeMaxDynamicSharedMemorySize, SMEM_ATTN_TOTAL);

    sctab_kernel<<<(TT * 64) / 256, 256>>>();
    lengths_kernel<<<BB, 256>>>(mask);
    conv1_kernel<0><<<MROWS * 2, 256>>>(x);            // x     -> g_A2 hi
    conv1_kernel<1><<<(3 * DD) * 2, 256>>>(Wqkv);      // Wqkv  -> g_W2 hi
    gemm_mma<0><<<dim3(48, 64), 128, SMEM_GEMM_TOTAL>>>(nullptr, 0);
    attn_mma_kernel<<<dim3(16, HH, BB), 256, SMEM_ATTN_TOTAL>>>();
    conv1_kernel<1><<<DD * 2, 256>>>(Wproj);           // Wproj -> g_W2 hi
    gemm_mma<1><<<dim3(16, 64), 128, SMEM_GEMM_TOTAL>>>(out, DD);
}

// round 14
// speedup vs baseline: 10.0170x; 1.0638x over previous
#include <cuda_runtime.h>
#include <cuda_fp16.h>
#include <cstdint>
#include <math.h>

#define BB 4
#define TT 2048
#define DD 2048
#define HH 16
#define HDIM 128
#define MROWS (BB*TT)       /* 8192 */
#define K2 (2*DD)           /* 4096 row stride (hi plane only) */
#define PLANE_ELEMS ((size_t)BB*HH*TT*HDIM)   /* 16.8M */

// ---------------- scratch (device globals; uint4-backed => 16B align) ----------
__device__ uint4 g_A2_raw [(size_t)MROWS*K2/8];          // fp16, rows stride K2
__device__ uint4 g_W2_raw [(size_t)(3*DD)*K2/8];         // fp16, rows stride K2
__device__ uint4 g_qh_raw [PLANE_ELEMS/8];               // fp16 planes (attention)
__device__ uint4 g_kh_raw [PLANE_ELEMS/8];
__device__ uint4 g_vh_raw [PLANE_ELEMS/8];
__device__ float g_sin[TT*64];
__device__ float g_cos[TT*64];
__device__ int   g_len[BB];

// device-code-only views (never use in host code / kernel args)
#define g_A2  ((__half*)g_A2_raw)
#define g_W2  ((__half*)g_W2_raw)
#define g_qh  ((__half*)g_qh_raw)
#define g_kh  ((__half*)g_kh_raw)
#define g_vh  ((__half*)g_vh_raw)

// ============================ helpers ============================
__device__ __forceinline__ uint32_t smem_u32(const void* p) {
    uint32_t a;
    asm("{ .reg .u64 t; cvta.to.shared.u64 t, %1; cvt.u32.u64 %0, t; }" : "=r"(a) : "l"(p));
    return a;
}
__device__ __forceinline__ void cp16(uint32_t s, const void* g) {
    asm volatile("cp.async.cg.shared.global [%0], [%1], 16;" :: "r"(s), "l"(g));
}
__device__ __forceinline__ void ldmx4(uint32_t* r, uint32_t addr) {
    asm volatile("ldmatrix.sync.aligned.m8n8.x4.shared.b16 {%0,%1,%2,%3}, [%4];"
        : "=r"(r[0]), "=r"(r[1]), "=r"(r[2]), "=r"(r[3]) : "r"(addr));
}
__device__ __forceinline__ void ldmx4t(uint32_t* r, uint32_t addr) {
    asm volatile("ldmatrix.sync.aligned.m8n8.x4.trans.shared.b16 {%0,%1,%2,%3}, [%4];"
        : "=r"(r[0]), "=r"(r[1]), "=r"(r[2]), "=r"(r[3]) : "r"(addr));
}
__device__ __forceinline__ void mma16816h(float* d, const uint32_t* a, uint32_t b0, uint32_t b1) {
    asm volatile("mma.sync.aligned.m16n8k16.row.col.f32.f16.f16.f32 "
        "{%0,%1,%2,%3}, {%4,%5,%6,%7}, {%8,%9}, {%0,%1,%2,%3};"
        : "+f"(d[0]), "+f"(d[1]), "+f"(d[2]), "+f"(d[3])
        : "r"(a[0]), "r"(a[1]), "r"(a[2]), "r"(a[3]), "r"(b0), "r"(b1));
}
__device__ __forceinline__ uint32_t pack_h2(float lo, float hi) {
    union { __half2 h; uint32_t u; } t;
    t.h = __floats2half2_rn(lo, hi);
    return t.u;
}
#define SWZ8(c, r)  ((c) ^ ((r) & 7))

// ---------------- per-batch valid lengths ----------------
__global__ void lengths_kernel(const int* __restrict__ mask) {
    __shared__ int sd[256];
    int b = blockIdx.x;
    int s = 0;
    for (int i = threadIdx.x; i < TT; i += 256) s += mask[b * TT + i];
    sd[threadIdx.x] = s;
    __syncthreads();
    for (int st = 128; st > 0; st >>= 1) {
        if (threadIdx.x < st) sd[threadIdx.x] += sd[threadIdx.x + st];
        __syncthreads();
    }
    if (threadIdx.x == 0) g_len[b] = sd[0];
}

// ---------------- RoPE sin/cos table ----------------
__global__ void sctab_kernel() {
    int idx = blockIdx.x * 256 + threadIdx.x;      // TT*64
    int d = idx & 63, t = idx >> 6;
    float inv = (float)exp(-(double)(2 * d) / 128.0 * 9.210340371976184);
    float ang = (float)t * inv;
    float s, c;
    sincosf(ang, &s, &c);
    g_sin[idx] = s;
    g_cos[idx] = c;
}

// ---------------- fp32 -> fp16 (hi plane, rows stride K2) ----------------
template <int DSTW>
__global__ __launch_bounds__(256) void conv1_kernel(const float* __restrict__ in) {
    __half* out = DSTW ? g_W2 : g_A2;
    int g = blockIdx.x * 256 + threadIdx.x;        // rows * 512
    int r = g >> 9, c4 = g & 511;
    float4 v = *(const float4*)(in + (size_t)r * DD + c4 * 4);
    union { __half b[4]; uint2 u; } hi;
    hi.b[0] = __float2half_rn(v.x); hi.b[1] = __float2half_rn(v.y);
    hi.b[2] = __float2half_rn(v.z); hi.b[3] = __float2half_rn(v.w);
    *(uint2*)(out + (size_t)r * K2 + c4 * 4) = hi.u;
}

// ---------------- HMMA fp16 GEMM (single plane, K=2048) ----------------
// MODE 0: QKV. q/k epilogue fuses RoPE; v epilogue writes fp16 plane;
//          k/v tiles beyond valid length skipped.
// MODE 1: proj, fp32 out.
#define GSTAGE 32768
#define SMEM_GEMM_TOTAL (3*GSTAGE)      /* 98304 B */
#define GITERS (DD/64)                  /* 32 */

template <int MODE>
__global__ __launch_bounds__(128, 2) void gemm_mma(float* __restrict__ Cout, int N) {
    extern __shared__ __align__(16) char smraw[];
    const uint32_t sb = smem_u32(smraw);
    const int tid = threadIdx.x;
    const int bm = blockIdx.y * 128, bn = blockIdx.x * 128;
    const int warp = tid >> 5, lane = tid & 31;
    const int wm = warp >> 1, wn = warp & 1;

    if (MODE == 0) {
        const int which = bn >> 11;
        if (which >= 1 && (bm & (TT - 1)) >= g_len[bm >> 11]) return;
    }

    float acc[32][4];
#pragma unroll
    for (int i = 0; i < 32; i++)
#pragma unroll
        for (int j = 0; j < 4; j++) acc[i][j] = 0.f;

    const int r0 = tid >> 3;                       // 0..15
    const int c0 = tid & 7;
    const uint32_t soA0 = r0 * 128 + SWZ8(c0, r0) * 16;
    const uint32_t soB0 = 16384 + soA0;
    const __half* pA = g_A2 + (size_t)(bm + r0) * K2 + c0 * 8;
    const __half* pB = g_W2 + (size_t)(bn + r0) * K2 + c0 * 8;

    auto load_stage = [&](uint32_t sbase) {
#pragma unroll
        for (int l = 0; l < 8; l++) {
            cp16(sbase + soA0 + l * 2048, pA + (size_t)l * 16 * K2);
            cp16(sbase + soB0 + l * 2048, pB + (size_t)l * 16 * K2);
        }
        asm volatile("cp.async.commit_group;" ::: "memory");
        pA += 64; pB += 64;
    };

    load_stage(sb);
    load_stage(sb + GSTAGE);

    const int lrow = (lane & 7) + 8 * ((lane >> 3) & 1);
    const int lch  = lane >> 4;
    uint32_t aro[4], bro[4];
#pragma unroll
    for (int mi = 0; mi < 4; mi++) {
        int row = wm * 64 + mi * 16 + lrow;
        aro[mi] = row * 128 + ((row & 7) << 4);
    }
#pragma unroll
    for (int n16 = 0; n16 < 4; n16++) {
        int nr = wn * 64 + n16 * 16 + lrow;
        bro[n16] = 16384 + nr * 128 + ((nr & 7) << 4);
    }

    for (int i = 0; i < GITERS; i += 3) {
#pragma unroll
        for (int u = 0; u < 3; u++) {
            const int idx = i + u;
            if (idx >= GITERS) break;
            if (idx >= GITERS - 2) asm volatile("cp.async.wait_group 0;" ::: "memory");
            else                   asm volatile("cp.async.wait_group 1;" ::: "memory");
            __syncthreads();
            if (idx + 2 < GITERS) load_stage(sb + ((u + 2) % 3) * GSTAGE);

            const uint32_t sa = sb + u * GSTAGE;
#pragma unroll
            for (int ks = 0; ks < 4; ks++) {
                const uint32_t chx = (uint32_t)(ks * 2 + lch) << 4;
                uint32_t a[4][4], b[4][4];
#pragma unroll
                for (int mi = 0; mi < 4; mi++)
                    ldmx4(a[mi], sa + (aro[mi] ^ chx));
#pragma unroll
                for (int n16 = 0; n16 < 4; n16++)
                    ldmx4(b[n16], sa + (bro[n16] ^ chx));
#pragma unroll
                for (int mi = 0; mi < 4; mi++)
#pragma unroll
                    for (int n16 = 0; n16 < 4; n16++) {
                        mma16816h(acc[mi * 8 + n16 * 2],     a[mi], b[n16][0], b[n16][2]);
                        mma16816h(acc[mi * 8 + n16 * 2 + 1], a[mi], b[n16][1], b[n16][3]);
                    }
            }
        }
    }

    // ---- epilogue ----
    if (MODE == 0) {
        const int which = bn >> 11;                // 0=q 1=k 2=v
        const int h = (bn >> 7) & 15;
        if (which == 2) {
#pragma unroll
            for (int mi = 0; mi < 4; mi++)
#pragma unroll
                for (int nn = 0; nn < 8; nn++) {
                    int d = wn * 64 + (nn >> 1) * 16 + (nn & 1) * 8 + (lane & 3) * 2;
#pragma unroll
                    for (int half = 0; half < 2; half++) {
                        int m = bm + wm * 64 + mi * 16 + (lane >> 2) + half * 8;
                        int b_ = m >> 11, t_ = m & (TT - 1);
                        size_t off = (((size_t)b_ * HH + h) * TT + t_) * HDIM + d;
                        *(uint32_t*)&g_vh[off] = pack_h2(acc[mi * 8 + nn][2 * half],
                                                         acc[mi * 8 + nn][2 * half + 1]);
                    }
                }
        } else {
            // fused RoPE: stage fp32 tile in smem (pitch 130), rotate, write fp16
            __syncthreads();
            float* smf = (float*)smraw;
#pragma unroll
            for (int mi = 0; mi < 4; mi++)
#pragma unroll
                for (int nn = 0; nn < 8; nn++) {
                    int c = wn * 64 + (nn >> 1) * 16 + (nn & 1) * 8 + (lane & 3) * 2;
#pragma unroll
                    for (int half = 0; half < 2; half++) {
                        int r = wm * 64 + mi * 16 + (lane >> 2) + half * 8;
                        smf[r * 130 + c]     = acc[mi * 8 + nn][2 * half];
                        smf[r * 130 + c + 1] = acc[mi * 8 + nn][2 * half + 1];
                    }
                }
            __syncthreads();
            __half* dst = (which == 0) ? g_qh : g_kh;
            const int d = tid & 63;
            const int rh = tid >> 6;               // 0..1
            const int b_ = bm >> 11;
#pragma unroll 4
            for (int rr = 0; rr < 64; rr++) {
                int r = rh * 64 + rr;
                int t_ = (bm + r) & (TT - 1);
                int ti = (t_ << 6) + d;
                float s = g_sin[ti], c = g_cos[ti];
                float v1 = smf[r * 130 + d];
                float v2 = smf[r * 130 + d + 64];
                size_t off = (((size_t)b_ * HH + h) * TT + t_) * HDIM;
                dst[off + d]      = __float2half_rn(v1 * c - v2 * s);
                dst[off + d + 64] = __float2half_rn(v2 * c + v1 * s);
            }
        }
    } else {
#pragma unroll
        for (int mi = 0; mi < 4; mi++)
#pragma unroll
            for (int nn = 0; nn < 8; nn++) {
                int col = bn + wn * 64 + (nn >> 1) * 16 + (nn & 1) * 8 + (lane & 3) * 2;
#pragma unroll
                for (int half = 0; half < 2; half++) {
                    int m = bm + wm * 64 + mi * 16 + (lane >> 2) + half * 8;
                    float2 v2 = make_float2(acc[mi * 8 + nn][2 * half],
                                            acc[mi * 8 + nn][2 * half + 1]);
                    *(float2*)&Cout[(size_t)m * N + col] = v2;
                }
            }
    }
}

// ---------------- fp16 flash attention: BQ=128, BKV=64, 8 warps ----------------
// S = Qh*Kh (1 term); O = Ph*Vh (1 term, fp16 P)
#define AQ_OFF   0
#define AKV_OFF  32768
#define AKV_STG  32768
#define SMEM_ATTN_TOTAL (32768 + 2*32768)   /* 98304 */

__global__ __launch_bounds__(256) void attn_mma_kernel() {
    extern __shared__ __align__(16) char smraw[];
    const uint32_t sb = smem_u32(smraw);
    const int tid = threadIdx.x;
    const int warp = tid >> 5, lane = tid & 31;
    const int qt = 15 - blockIdx.x;                 // descending work order
    const int h = blockIdx.y, b = blockIdx.z;
    const int L = g_len[b];
    const size_t bhT = ((size_t)b * HH + h) * TT;

    const int lrow = (lane & 7) + 8 * ((lane >> 3) & 1);
    const int lch  = lane >> 4;

    // ---- load Q tile (qh only), own commit group ----
    {
#pragma unroll
        for (int l = 0; l < 8; l++) {
            int idx = tid + l * 256;                // 2048 chunks
            int row = idx >> 4, c = idx & 15;
            cp16(sb + AQ_OFF + row * 256 + SWZ8(c, row) * 16,
                 g_qh + (bhT + (size_t)qt * 128 + row) * HDIM + c * 8);
        }
        asm volatile("cp.async.commit_group;" ::: "memory");
    }

    const int nt = (min(qt * 128 + 128, L) + 63) / 64;

    auto load_kv = [&](int kt, int stg) {
        const __half* pp[2];
        pp[0] = g_kh; pp[1] = g_vh;
        uint32_t base = sb + AKV_OFF + stg * AKV_STG;
#pragma unroll
        for (int l = 0; l < 8; l++) {
            int idx = tid + l * 256;                // 2048 chunks
            int pl = idx >> 10, rem = idx & 1023;
            int row = rem >> 4, c = rem & 15;
            cp16(base + pl * 16384 + row * 256 + SWZ8(c, row) * 16,
                 pp[pl] + (bhT + (size_t)kt * 64 + row) * HDIM + c * 8);
        }
        asm volatile("cp.async.commit_group;" ::: "memory");
    };
    load_kv(0, 0);

    // ---- hoist Q fragments (wait only for the Q group) ----
    uint32_t qhf[8][4];
    {
        asm volatile("cp.async.wait_group 1;" ::: "memory");
        __syncthreads();
        const uint32_t qh = sb + AQ_OFF;
        const int arow = warp * 16 + lrow;
#pragma unroll
        for (int k16 = 0; k16 < 8; k16++) {
            const int ch = k16 * 2 + lch;
            ldmx4(qhf[k16], qh + arow * 256 + SWZ8(ch, arow) * 16);
        }
    }

    float oacc[16][4];
#pragma unroll
    for (int i = 0; i < 16; i++)
#pragma unroll
        for (int j = 0; j < 4; j++) oacc[i][j] = 0.f;
    float m0 = -1e30f, m1 = -1e30f, l0 = 0.f, l1 = 0.f;

    const int wr = qt * 128 + warp * 16;
    const float scl = 0.08838834764831843f;

    for (int kt = 0; kt < nt; kt++) {
        asm volatile("cp.async.wait_group 0;" ::: "memory");
        __syncthreads();
        if (kt + 1 < nt) load_kv(kt + 1, (kt + 1) & 1);

        const uint32_t kh = sb + AKV_OFF + (kt & 1) * AKV_STG;
        const uint32_t vh = kh + 16384;

        // ---- S = Qh*Kh ----
        float sacc[8][4];
#pragma unroll
        for (int i = 0; i < 8; i++)
#pragma unroll
            for (int j = 0; j < 4; j++) sacc[i][j] = 0.f;

#pragma unroll
        for (int k16 = 0; k16 < 8; k16++) {
            const int ch = k16 * 2 + lch;
#pragma unroll
            for (int n16 = 0; n16 < 4; n16++) {
                const int nr = n16 * 16 + lrow;
                uint32_t bh[4];
                ldmx4(bh, kh + nr * 256 + SWZ8(ch, nr) * 16);
                mma16816h(sacc[2*n16],   qhf[k16], bh[0], bh[2]);
                mma16816h(sacc[2*n16+1], qhf[k16], bh[1], bh[3]);
            }
        }

        // ---- mask + online softmax ----
        const bool needmask = ((kt + 1) * 64 > qt * 128) || ((kt + 1) * 64 > L);
        const int r0g = wr + (lane >> 2);
#pragma unroll
        for (int f = 0; f < 8; f++)
#pragma unroll
            for (int c = 0; c < 4; c++) {
                float x = sacc[f][c] * scl;
                if (needmask) {
                    int col = kt * 64 + f * 8 + ((lane & 3) << 1) + (c & 1);
                    int rg = r0g + ((c >> 1) << 3);
                    if (col > rg || col >= L) x = -1e30f;
                }
                sacc[f][c] = x;
            }
        float mx0 = -1e30f, mx1 = -1e30f;
#pragma unroll
        for (int f = 0; f < 8; f++) {
            mx0 = fmaxf(mx0, fmaxf(sacc[f][0], sacc[f][1]));
            mx1 = fmaxf(mx1, fmaxf(sacc[f][2], sacc[f][3]));
        }
        mx0 = fmaxf(mx0, __shfl_xor_sync(0xffffffffu, mx0, 1));
        mx0 = fmaxf(mx0, __shfl_xor_sync(0xffffffffu, mx0, 2));
        mx1 = fmaxf(mx1, __shfl_xor_sync(0xffffffffu, mx1, 1));
        mx1 = fmaxf(mx1, __shfl_xor_sync(0xffffffffu, mx1, 2));
        float mn0 = fmaxf(m0, mx0), mn1 = fmaxf(m1, mx1);
        float corr0 = __expf(m0 - mn0), corr1 = __expf(m1 - mn1);
        float sum0 = 0.f, sum1 = 0.f;
#pragma unroll
        for (int f = 0; f < 8; f++) {
            float p;
            p = __expf(sacc[f][0] - mn0); sacc[f][0] = p; sum0 += p;
            p = __expf(sacc[f][1] - mn0); sacc[f][1] = p; sum0 += p;
            p = __expf(sacc[f][2] - mn1); sacc[f][2] = p; sum1 += p;
            p = __expf(sacc[f][3] - mn1); sacc[f][3] = p; sum1 += p;
        }
        sum0 += __shfl_xor_sync(0xffffffffu, sum0, 1);
        sum0 += __shfl_xor_sync(0xffffffffu, sum0, 2);
        sum1 += __shfl_xor_sync(0xffffffffu, sum1, 1);
        sum1 += __shfl_xor_sync(0xffffffffu, sum1, 2);
        l0 = l0 * corr0 + sum0; m0 = mn0;
        l1 = l1 * corr1 + sum1; m1 = mn1;
#pragma unroll
        for (int nf = 0; nf < 16; nf++) {
            oacc[nf][0] *= corr0; oacc[nf][1] *= corr0;
            oacc[nf][2] *= corr1; oacc[nf][3] *= corr1;
        }

        // ---- O += Ph*Vh (single fp16 P plane) ----
#pragma unroll
        for (int j16 = 0; j16 < 4; j16++) {
            const int f0 = 2 * j16, f1 = 2 * j16 + 1;
            uint32_t aPh[4];
            aPh[0] = pack_h2(sacc[f0][0], sacc[f0][1]);
            aPh[1] = pack_h2(sacc[f0][2], sacc[f0][3]);
            aPh[2] = pack_h2(sacc[f1][0], sacc[f1][1]);
            aPh[3] = pack_h2(sacc[f1][2], sacc[f1][3]);
#pragma unroll
            for (int d16 = 0; d16 < 8; d16++) {
                const int ch = d16 * 2 + lch;
                const int vr = j16 * 16 + lrow;
                uint32_t bvh[4];
                ldmx4t(bvh, vh + vr * 256 + SWZ8(ch, vr) * 16);
                mma16816h(oacc[2*d16],   aPh, bvh[0], bvh[1]);
                mma16816h(oacc[2*d16+1], aPh, bvh[2], bvh[3]);
            }
        }
        __syncthreads();
    }

    // ---- epilogue: write hi plane into g_A2 ----
    const float il0 = 1.f / l0, il1 = 1.f / l1;
    const int trow = qt * 128 + warp * 16 + (lane >> 2);
#pragma unroll
    for (int nf = 0; nf < 16; nf++) {
        int col = h * 128 + nf * 8 + (lane & 3) * 2;
#pragma unroll
        for (int half = 0; half < 2; half++) {
            float v0 = oacc[nf][2 * half]     * (half ? il1 : il0);
            float v1 = oacc[nf][2 * half + 1] * (half ? il1 : il0);
            __half* row = g_A2 + ((size_t)b * TT + trow + half * 8) * K2;
            *(uint32_t*)&row[col] = pack_h2(v0, v1);
        }
    }
}

// ---------------- launcher ----------------
extern "C" void kernel_launch(void* const* d_in, const int* in_sizes, int n_in,
                              void* d_out, int out_size) {
    const float* x     = (const float*)d_in[0];
    const float* Wqkv  = (const float*)d_in[1];
    const float* Wproj = (const float*)d_in[2];
    const int*   mask  = (const int*)d_in[3];
    float* out = (float*)d_out;

    cudaFuncSetAttribute(gemm_mma<0>, cudaFuncAttributeMaxDynamicSharedMemorySize, SMEM_GEMM_TOTAL);
    cudaFuncSetAttribute(gemm_mma<1>, cudaFuncAttributeMaxDynamicSharedMemorySize, SMEM_GEMM_TOTAL);
    cudaFuncSetAttribute(attn_mma_kernel, cudaFuncAttributeMaxDynamicSharedMemorySize, SMEM_ATTN_TOTAL);

    sctab_kernel<<<(TT * 64) / 256, 256>>>();
    lengths_kernel<<<BB, 256>>>(mask);
    conv1_kernel<0><<<MROWS * 2, 256>>>(x);            // x     -> g_A2 hi
    conv1_kernel<1><<<(3 * DD) * 2, 256>>>(Wqkv);      // Wqkv  -> g_W2 hi
    gemm_mma<0><<<dim3(48, 64), 128, SMEM_GEMM_TOTAL>>>(nullptr, 0);
    attn_mma_kernel<<<dim3(16, HH, BB), 256, SMEM_ATTN_TOTAL>>>();
    conv1_kernel<1><<<DD * 2, 256>>>(Wproj);           // Wproj -> g_W2 hi
    gemm_mma<1><<<dim3(16, 64), 128, SMEM_GEMM_TOTAL>>>(out, DD);
}